// round 1
// baseline (speedup 1.0000x reference)
#include <cuda_runtime.h>

#define ALPHA 0.9f
constexpr int T_LEN = 809;
constexpr int TPAD  = 810;   // T+1 (padded scans Fp/Rp)
constexpr int DD    = 304;
constexpr int EE    = 300;
constexpr int LQ    = 30;
constexpr int BB    = 4;
constexpr int MSPAN = 16;
constexpr int H1    = 1024;
constexpr int H2    = 512;
constexpr int CIN   = 1212;
constexpr int NCAND = 12824;           // sum over s of min(16, T-s)
constexpr int ROWS  = BB * NCAND;      // 51296
constexpr int MROWS = BB * TPAD;       // 3240
constexpr float EPS = 1e-5f;

// ---------------- scratch (static device globals; no allocs) ----------------
__device__ float g_Fp[MROWS * DD];     // Fp[b,t,d], Fp[0]=0, Fp[t]=F[t-1]
__device__ float g_Rp[MROWS * DD];     // Rp[b,t,d], Rp[T]=0
__device__ float g_PA[MROWS * H1];     // Fp @ (W1a*sc1)^T
__device__ float g_PB[MROWS * H1];     // Fp @ (W1b*sc1)^T
__device__ float g_PC[MROWS * H1];     // Rp @ (W1c*sc1)^T
__device__ float g_Pq[BB * H1];        // sh1 + qf @ (W1q*sc1)^T
__device__ float g_W1s[H1 * CIN];      // W1 * sc1 (rowwise)
__device__ float g_W2t[H1 * H2];       // transposed & scaled: [k][n] = W2[n][k]*sc2[n]
__device__ float g_sh2[H2];
__device__ float g_qf[BB * EE];
__device__ float g_coef[MSPAN];
__device__ int   g_sidx[NCAND];
__device__ int   g_eidx[NCAND];
__device__ float g_h2[(size_t)ROWS * H2];   // post-ReLU layer-2 activations (105 MB)

// ---------------- f32x2 helpers (double-rate fp32 FMA) ----------------
__device__ __forceinline__ unsigned long long pack2(float x) {
    unsigned long long r;
    asm("mov.b64 %0, {%1, %1};" : "=l"(r) : "f"(x));
    return r;
}
__device__ __forceinline__ void fma2(unsigned long long& d,
                                     unsigned long long a,
                                     unsigned long long b) {
    asm("fma.rn.f32x2 %0, %1, %2, %0;" : "+l"(d) : "l"(a), "l"(b));
}
__device__ __forceinline__ float2 unpack2(unsigned long long v) {
    float2 r;
    asm("mov.b64 {%0, %1}, %2;" : "=f"(r.x), "=f"(r.y) : "l"(v));
    return r;
}

// ---------------- setup: scaled weights, qf, candidate tables ----------------
__global__ void k_setup1(const float* __restrict__ Qe,
                         const float* __restrict__ W1,
                         const float* __restrict__ g1, const float* __restrict__ b1,
                         const float* __restrict__ m1, const float* __restrict__ v1,
                         const float* __restrict__ W2,
                         const float* __restrict__ g2, const float* __restrict__ b2,
                         const float* __restrict__ m2, const float* __restrict__ v2) {
    const long NW1 = (long)H1 * CIN;
    const long NW2 = (long)H1 * H2;
    const long total = NW1 + NW2 + H2 + BB * EE + T_LEN + MSPAN;
    for (long idx = (long)blockIdx.x * blockDim.x + threadIdx.x; idx < total;
         idx += (long)gridDim.x * blockDim.x) {
        long i = idx;
        if (i < NW1) {  // W1 * sc1
            int j = (int)(i / CIN);
            float sc = g1[j] * rsqrtf(v1[j] + EPS);
            g_W1s[i] = W1[i] * sc;
            continue;
        }
        i -= NW1;
        if (i < NW2) {  // W2^T * sc2
            int n = (int)(i % H2);
            int k = (int)(i / H2);
            float sc = g2[n] * rsqrtf(v2[n] + EPS);
            g_W2t[i] = W2[n * H1 + k] * sc;
            continue;
        }
        i -= NW2;
        if (i < H2) {   // sh2
            float sc = g2[i] * rsqrtf(v2[i] + EPS);
            g_sh2[i] = b2[i] - m2[i] * sc;
            continue;
        }
        i -= H2;
        if (i < BB * EE) {  // qf
            int b = (int)(i / EE), d = (int)(i % EE);
            float acc = 0.f, p = 1.f;
            for (int t = LQ - 1; t >= 0; t--) {
                acc = fmaf(p, Qe[(b * LQ + t) * EE + d], acc);
                p *= ALPHA;
            }
            g_qf[i] = acc;
            continue;
        }
        i -= BB * EE;
        if (i < T_LEN) {  // candidate (s, e) tables (same enumeration order as ref)
            int s = (int)i;
            int cnt = min(MSPAN, T_LEN - s);
            int ex = (s > 794) ? ((s - 794) * (s - 793)) / 2 : 0;
            int base = 16 * s - ex;
            for (int sp = 0; sp < cnt; sp++) {
                g_sidx[base + sp] = s;
                g_eidx[base + sp] = s + sp;
            }
            continue;
        }
        i -= T_LEN;
        if (i < MSPAN) {  // coef[span] = alpha^(span+1), double precision like ref
            double c = 1.0;
            for (int k = 0; k <= (int)i; k++) c *= 0.9;
            g_coef[i] = (float)c;
        }
    }
}

// Pq[b,j] = sh1[j] + sum_d qf[b,d] * W1s[j, 912+d]
__global__ void k_pq(const float* __restrict__ b1, const float* __restrict__ m1,
                     const float* __restrict__ g1, const float* __restrict__ v1) {
    int j = blockIdx.x * blockDim.x + threadIdx.x;
    int b = blockIdx.y;
    if (j >= H1) return;
    float sc = g1[j] * rsqrtf(v1[j] + EPS);
    float acc = b1[j] - m1[j] * sc;
    const float* w = &g_W1s[j * CIN + 3 * DD];
    const float* q = &g_qf[b * EE];
    for (int d = 0; d < EE; d++) acc = fmaf(q[d], w[d], acc);
    g_Pq[b * H1 + j] = acc;
}

// ---------------- exponential prefix/suffix scans ----------------
__global__ void k_scan(const float* __restrict__ doc) {
    int d = threadIdx.x;   // 0..303
    int b = blockIdx.x;
    const float* dp = doc + (size_t)b * T_LEN * DD + d;
    if (blockIdx.y == 0) {
        float acc = 0.f;
        float* fp = g_Fp + (size_t)(b * TPAD) * DD + d;
        fp[0] = 0.f;
        for (int t = 0; t < T_LEN; t++) {
            acc = fmaf(ALPHA, acc, dp[(size_t)t * DD]);
            fp[(size_t)(t + 1) * DD] = acc;
        }
    } else {
        float acc = 0.f;
        float* rp = g_Rp + (size_t)(b * TPAD) * DD + d;
        rp[(size_t)T_LEN * DD] = 0.f;
        for (int t = T_LEN - 1; t >= 0; t--) {
            acc = fmaf(ALPHA, acc, dp[(size_t)t * DD]);
            rp[(size_t)t * DD] = acc;
        }
    }
}

// ---------------- projections: P = {Fp,Fp,Rp} @ W1{a,b,c}s^T ----------------
__global__ void k_proj() {
    const int z = blockIdx.z;
    const float* A = (z == 2) ? g_Rp : g_Fp;
    float* P = (z == 0) ? g_PA : (z == 1 ? g_PB : g_PC);
    const int colofs = z * DD;
    const int m0 = blockIdx.x * 64;
    const int n0 = blockIdx.y * 64;
    __shared__ float sA[16][68];
    __shared__ float sB[16][68];
    const int tid = threadIdx.x;
    const int ty = tid >> 4, tx = tid & 15;
    float acc[4][4] = {};
    for (int k0 = 0; k0 < DD; k0 += 16) {
#pragma unroll
        for (int q = 0; q < 4; q++) {
            int e = tid + 256 * q;
            int kk = e & 15, r = e >> 4;
            int m = m0 + r;
            sA[kk][r] = (m < MROWS) ? A[(size_t)m * DD + k0 + kk] : 0.f;
            int n = n0 + r;
            sB[kk][r] = g_W1s[(size_t)n * CIN + colofs + k0 + kk];
        }
        __syncthreads();
#pragma unroll
        for (int kk = 0; kk < 16; kk++) {
            float4 av = *(const float4*)&sA[kk][ty * 4];
            float4 bv = *(const float4*)&sB[kk][tx * 4];
            float a[4] = {av.x, av.y, av.z, av.w};
            float b[4] = {bv.x, bv.y, bv.z, bv.w};
#pragma unroll
            for (int i = 0; i < 4; i++)
#pragma unroll
                for (int j = 0; j < 4; j++) acc[i][j] = fmaf(a[i], b[j], acc[i][j]);
        }
        __syncthreads();
    }
#pragma unroll
    for (int i = 0; i < 4; i++) {
        int m = m0 + ty * 4 + i;
        if (m < MROWS)
            *(float4*)&P[(size_t)m * H1 + n0 + tx * 4] =
                make_float4(acc[i][0], acc[i][1], acc[i][2], acc[i][3]);
    }
}

// ------- main fused kernel: A-gen(relu combine) + GEMM2 + BN2 + ReLU -> h2 -------
__global__ void __launch_bounds__(512, 1) k_main() {
    __shared__ float sAt[16][68];       // A tile, transposed [k][r]
    __shared__ float sBt[16][512];      // W2t tile [k][n]
    __shared__ int   sOffS[64], sOffE[64], sBo[64];
    __shared__ float sCf[64];
    const int tid = threadIdx.x;
    const int m0 = blockIdx.x * 64;

    if (tid < 64) {
        int m = m0 + tid;
        int offS = 0, offE = 0, bo = 0;
        float cf = 0.f;
        if (m < ROWS) {
            int b = m / NCAND;
            int i = m - b * NCAND;
            int s = g_sidx[i], e = g_eidx[i];
            offS = (b * TPAD + s) * H1;
            offE = (b * TPAD + e + 1) * H1;
            bo = b * H1;
            cf = g_coef[e - s];
        }
        sOffS[tid] = offS; sOffE[tid] = offE; sBo[tid] = bo; sCf[tid] = cf;
    }

    unsigned long long acc[8][4];
#pragma unroll
    for (int i = 0; i < 8; i++)
#pragma unroll
        for (int j = 0; j < 4; j++) acc[i][j] = 0ULL;

    const int ty = tid >> 6;   // 0..7  -> 8 rows each
    const int tx = tid & 63;   // 0..63 -> 8 cols each

    for (int k0 = 0; k0 < H1; k0 += 16) {
        __syncthreads();
        // load W2t tile (coalesced, pre-transposed in setup)
#pragma unroll
        for (int q = 0; q < 4; q++) {
            int f = tid + 512 * q;
            int kk = f >> 7;
            int n4 = (f & 127) << 2;
            float4 w = *(const float4*)&g_W2t[(size_t)(k0 + kk) * H2 + n4];
            *(float4*)&sBt[kk][n4] = w;
        }
        // generate A tile: relu(PA[s] + PB[e+1] - coef*PB[s] + PC[e+1] + Pq)
#pragma unroll
        for (int q = 0; q < 2; q++) {
            int e = tid + 512 * q;
            int kk = e & 15;
            int r = e >> 4;
            int k = k0 + kk;
            float v = g_PA[sOffS[r] + k]
                    + g_PB[sOffE[r] + k]
                    - sCf[r] * g_PB[sOffS[r] + k]
                    + g_PC[sOffE[r] + k]
                    + g_Pq[sBo[r] + k];
            sAt[kk][r] = fmaxf(v, 0.f);
        }
        __syncthreads();
#pragma unroll
        for (int kk = 0; kk < 16; kk++) {
            float4 a0 = *(const float4*)&sAt[kk][ty * 8];
            float4 a1 = *(const float4*)&sAt[kk][ty * 8 + 4];
            ulonglong2 b0 = *(const ulonglong2*)&sBt[kk][tx * 8];
            ulonglong2 b1 = *(const ulonglong2*)&sBt[kk][tx * 8 + 4];
            unsigned long long pa[8] = {pack2(a0.x), pack2(a0.y), pack2(a0.z), pack2(a0.w),
                                        pack2(a1.x), pack2(a1.y), pack2(a1.z), pack2(a1.w)};
#pragma unroll
            for (int i = 0; i < 8; i++) {
                fma2(acc[i][0], pa[i], b0.x);
                fma2(acc[i][1], pa[i], b0.y);
                fma2(acc[i][2], pa[i], b1.x);
                fma2(acc[i][3], pa[i], b1.y);
            }
        }
    }

    // epilogue: + sh2, ReLU, store h2
    const int c0 = tx * 8;
    float4 s0 = *(const float4*)&g_sh2[c0];
    float4 s1 = *(const float4*)&g_sh2[c0 + 4];
#pragma unroll
    for (int i = 0; i < 8; i++) {
        int m = m0 + ty * 8 + i;
        if (m >= ROWS) continue;
        float2 v0 = unpack2(acc[i][0]);
        float2 v1 = unpack2(acc[i][1]);
        float2 v2 = unpack2(acc[i][2]);
        float2 v3 = unpack2(acc[i][3]);
        float4 o0 = make_float4(fmaxf(v0.x + s0.x, 0.f), fmaxf(v0.y + s0.y, 0.f),
                                fmaxf(v1.x + s0.z, 0.f), fmaxf(v1.y + s0.w, 0.f));
        float4 o1 = make_float4(fmaxf(v2.x + s1.x, 0.f), fmaxf(v2.y + s1.y, 0.f),
                                fmaxf(v3.x + s1.z, 0.f), fmaxf(v3.y + s1.w, 0.f));
        *(float4*)&g_h2[(size_t)m * H2 + c0] = o0;
        *(float4*)&g_h2[(size_t)m * H2 + c0 + 4] = o1;
    }
}

// ---------------- final: out[n, 0/1] = h2[n,:] . W3[0/1,:] ----------------
__global__ void k_out(const float* __restrict__ W3, float* __restrict__ out) {
    int gw = (blockIdx.x * blockDim.x + threadIdx.x) >> 5;
    int lane = threadIdx.x & 31;
    if (gw >= ROWS) return;
    const float* h = &g_h2[(size_t)gw * H2];
    float a0 = 0.f, a1 = 0.f;
#pragma unroll
    for (int q = 0; q < 16; q++) {
        int c = lane + q * 32;
        float v = h[c];
        a0 = fmaf(v, W3[c], a0);
        a1 = fmaf(v, W3[H2 + c], a1);
    }
#pragma unroll
    for (int o = 16; o > 0; o >>= 1) {
        a0 += __shfl_down_sync(0xffffffffu, a0, o);
        a1 += __shfl_down_sync(0xffffffffu, a1, o);
    }
    if (lane == 0) {
        out[2 * gw]     = a0;
        out[2 * gw + 1] = a1;
    }
}

// ---------------- launch ----------------
extern "C" void kernel_launch(void* const* d_in, const int* in_sizes, int n_in,
                              void* d_out, int out_size) {
    (void)in_sizes; (void)n_in; (void)out_size;
    const float* doc = (const float*)d_in[0];
    const float* qe  = (const float*)d_in[1];
    const float* W1  = (const float*)d_in[2];
    const float* g1  = (const float*)d_in[3];
    const float* b1  = (const float*)d_in[4];
    const float* m1  = (const float*)d_in[5];
    const float* v1  = (const float*)d_in[6];
    const float* W2  = (const float*)d_in[7];
    const float* g2  = (const float*)d_in[8];
    const float* b2  = (const float*)d_in[9];
    const float* m2  = (const float*)d_in[10];
    const float* v2  = (const float*)d_in[11];
    const float* W3  = (const float*)d_in[12];
    float* out = (float*)d_out;

    k_setup1<<<512, 256>>>(qe, W1, g1, b1, m1, v1, W2, g2, b2, m2, v2);
    k_scan<<<dim3(BB, 2), DD>>>(doc);
    k_pq<<<dim3(H1 / 256, BB), 256>>>(b1, m1, g1, v1);
    k_proj<<<dim3((MROWS + 63) / 64, H1 / 64, 3), 256>>>();
    k_main<<<(ROWS + 63) / 64, 512>>>();
    k_out<<<(ROWS + 7) / 8, 256>>>(W3, out);
}

// round 3
// speedup vs baseline: 1.7962x; 1.7962x over previous
#include <cuda_runtime.h>
#include <cstdint>

#define ALPHA 0.9f
constexpr int T_LEN = 809;
constexpr int TPAD  = 810;
constexpr int DD    = 304;
constexpr int EE    = 300;
constexpr int LQ    = 30;
constexpr int BB    = 4;
constexpr int MSPAN = 16;
constexpr int H1    = 1024;
constexpr int H2    = 512;
constexpr int CIN   = 1212;
constexpr int NCAND = 12824;
constexpr int ROWS  = BB * NCAND;      // 51296
constexpr int MROWS = BB * TPAD;       // 3240
constexpr float EPS = 1e-5f;

// ---------------- scratch ----------------
__device__ float g_Fp[MROWS * DD];
__device__ float g_Rp[MROWS * DD];
__device__ float g_PA[MROWS * H1];
__device__ float g_PB[MROWS * H1];
__device__ float g_PC[MROWS * H1];
__device__ float g_Pq[BB * H1];
__device__ float g_W1s[H1 * CIN];
__device__ __align__(16) uint16_t g_W2bh[H1 * H2];  // bf16 hi of W2*sc2, layout [k][n]
__device__ __align__(16) uint16_t g_W2bl[H1 * H2];  // bf16 lo, layout [k][n]
__device__ float g_sh2[H2];
__device__ float g_qf[BB * EE];
__device__ float g_coef[MSPAN];
__device__ int   g_sidx[NCAND];
__device__ int   g_eidx[NCAND];
__device__ float g_outp[2 * ROWS * 2];  // per-N-tile partial outputs

// ---------------- helpers ----------------
__device__ __forceinline__ uint32_t smem_u32(const void* p) {
    uint32_t a;
    asm("{ .reg .u64 t; cvta.to.shared.u64 t, %1; cvt.u32.u64 %0, t; }" : "=r"(a) : "l"(p));
    return a;
}
// returns word with lo in bits[0:16], hi in bits[16:32]
__device__ __forceinline__ uint32_t pack_bf16x2(float lo, float hi) {
    uint32_t r;
    asm("cvt.rn.bf16x2.f32 %0, %1, %2;" : "=r"(r) : "f"(hi), "f"(lo));
    return r;
}
__device__ __forceinline__ float bf_lo_f(uint32_t u) { return __uint_as_float(u << 16); }
__device__ __forceinline__ float bf_hi_f(uint32_t u) { return __uint_as_float(u & 0xFFFF0000u); }

__device__ __forceinline__ void ldsm_x4(uint32_t* r, uint32_t a) {
    asm volatile("ldmatrix.sync.aligned.m8n8.x4.shared.b16 {%0,%1,%2,%3}, [%4];"
                 : "=r"(r[0]), "=r"(r[1]), "=r"(r[2]), "=r"(r[3]) : "r"(a));
}
__device__ __forceinline__ void ldsm_x2_t(uint32_t* r, uint32_t a) {
    asm volatile("ldmatrix.sync.aligned.m8n8.x2.trans.shared.b16 {%0,%1}, [%2];"
                 : "=r"(r[0]), "=r"(r[1]) : "r"(a));
}
__device__ __forceinline__ void mma16816(float* d, const uint32_t* a, const uint32_t* b) {
    asm volatile(
        "mma.sync.aligned.m16n8k16.row.col.f32.bf16.bf16.f32 "
        "{%0,%1,%2,%3}, {%4,%5,%6,%7}, {%8,%9}, {%0,%1,%2,%3};"
        : "+f"(d[0]), "+f"(d[1]), "+f"(d[2]), "+f"(d[3])
        : "r"(a[0]), "r"(a[1]), "r"(a[2]), "r"(a[3]), "r"(b[0]), "r"(b[1]));
}

// ---------------- setup ----------------
__global__ void k_setup1(const float* __restrict__ Qe,
                         const float* __restrict__ W1,
                         const float* __restrict__ g1, const float* __restrict__ b1,
                         const float* __restrict__ m1, const float* __restrict__ v1,
                         const float* __restrict__ W2,
                         const float* __restrict__ g2, const float* __restrict__ b2,
                         const float* __restrict__ m2, const float* __restrict__ v2) {
    const long NW1 = (long)H1 * CIN;
    const long NW2 = (long)H1 * H2;
    const long total = NW1 + NW2 + H2 + BB * EE + T_LEN + MSPAN;
    for (long idx = (long)blockIdx.x * blockDim.x + threadIdx.x; idx < total;
         idx += (long)gridDim.x * blockDim.x) {
        long i = idx;
        if (i < NW1) {
            int j = (int)(i / CIN);
            float sc = g1[j] * rsqrtf(v1[j] + EPS);
            g_W1s[i] = W1[i] * sc;
            continue;
        }
        i -= NW1;
        if (i < NW2) {  // layout [k][n]: i = k*H2 + n
            int n = (int)(i % H2);
            int k = (int)(i / H2);
            float sc = g2[n] * rsqrtf(v2[n] + EPS);
            float b = W2[(size_t)n * H1 + k] * sc;
            uint32_t u = pack_bf16x2(b, 0.f);
            float hi = bf_lo_f(u);
            uint32_t ul = pack_bf16x2(b - hi, 0.f);
            g_W2bh[i] = (uint16_t)(u & 0xFFFFu);
            g_W2bl[i] = (uint16_t)(ul & 0xFFFFu);
            continue;
        }
        i -= NW2;
        if (i < H2) {
            float sc = g2[i] * rsqrtf(v2[i] + EPS);
            g_sh2[i] = b2[i] - m2[i] * sc;
            continue;
        }
        i -= H2;
        if (i < BB * EE) {
            int b = (int)(i / EE), d = (int)(i % EE);
            float acc = 0.f, p = 1.f;
            for (int t = LQ - 1; t >= 0; t--) {
                acc = fmaf(p, Qe[(b * LQ + t) * EE + d], acc);
                p *= ALPHA;
            }
            g_qf[i] = acc;
            continue;
        }
        i -= BB * EE;
        if (i < T_LEN) {
            int s = (int)i;
            int cnt = min(MSPAN, T_LEN - s);
            int ex = (s > 794) ? ((s - 794) * (s - 793)) / 2 : 0;
            int base = 16 * s - ex;
            for (int sp = 0; sp < cnt; sp++) {
                g_sidx[base + sp] = s;
                g_eidx[base + sp] = s + sp;
            }
            continue;
        }
        i -= T_LEN;
        if (i < MSPAN) {
            double c = 1.0;
            for (int k = 0; k <= (int)i; k++) c *= 0.9;
            g_coef[i] = (float)c;
        }
    }
}

__global__ void k_pq(const float* __restrict__ b1, const float* __restrict__ m1,
                     const float* __restrict__ g1, const float* __restrict__ v1) {
    int j = blockIdx.x * blockDim.x + threadIdx.x;
    int b = blockIdx.y;
    if (j >= H1) return;
    float sc = g1[j] * rsqrtf(v1[j] + EPS);
    float acc = b1[j] - m1[j] * sc;
    const float* w = &g_W1s[j * CIN + 3 * DD];
    const float* q = &g_qf[b * EE];
    for (int d = 0; d < EE; d++) acc = fmaf(q[d], w[d], acc);
    g_Pq[b * H1 + j] = acc;
}

__global__ void k_scan(const float* __restrict__ doc) {
    int d = threadIdx.x;
    int b = blockIdx.x;
    const float* dp = doc + (size_t)b * T_LEN * DD + d;
    if (blockIdx.y == 0) {
        float acc = 0.f;
        float* fp = g_Fp + (size_t)(b * TPAD) * DD + d;
        fp[0] = 0.f;
        for (int t = 0; t < T_LEN; t++) {
            acc = fmaf(ALPHA, acc, dp[(size_t)t * DD]);
            fp[(size_t)(t + 1) * DD] = acc;
        }
    } else {
        float acc = 0.f;
        float* rp = g_Rp + (size_t)(b * TPAD) * DD + d;
        rp[(size_t)T_LEN * DD] = 0.f;
        for (int t = T_LEN - 1; t >= 0; t--) {
            acc = fmaf(ALPHA, acc, dp[(size_t)t * DD]);
            rp[(size_t)t * DD] = acc;
        }
    }
}

__global__ void k_proj() {
    const int z = blockIdx.z;
    const float* A = (z == 2) ? g_Rp : g_Fp;
    float* P = (z == 0) ? g_PA : (z == 1 ? g_PB : g_PC);
    const int colofs = z * DD;
    const int m0 = blockIdx.x * 64;
    const int n0 = blockIdx.y * 64;
    __shared__ float sA[16][68];
    __shared__ float sB[16][68];
    const int tid = threadIdx.x;
    const int ty = tid >> 4, tx = tid & 15;
    float acc[4][4] = {};
    for (int k0 = 0; k0 < DD; k0 += 16) {
#pragma unroll
        for (int q = 0; q < 4; q++) {
            int e = tid + 256 * q;
            int kk = e & 15, r = e >> 4;
            int m = m0 + r;
            sA[kk][r] = (m < MROWS) ? A[(size_t)m * DD + k0 + kk] : 0.f;
            int n = n0 + r;
            sB[kk][r] = g_W1s[(size_t)n * CIN + colofs + k0 + kk];
        }
        __syncthreads();
#pragma unroll
        for (int kk = 0; kk < 16; kk++) {
            float4 av = *(const float4*)&sA[kk][ty * 4];
            float4 bv = *(const float4*)&sB[kk][tx * 4];
            float a[4] = {av.x, av.y, av.z, av.w};
            float b[4] = {bv.x, bv.y, bv.z, bv.w};
#pragma unroll
            for (int i = 0; i < 4; i++)
#pragma unroll
                for (int j = 0; j < 4; j++) acc[i][j] = fmaf(a[i], b[j], acc[i][j]);
        }
        __syncthreads();
    }
#pragma unroll
    for (int i = 0; i < 4; i++) {
        int m = m0 + ty * 4 + i;
        if (m < MROWS)
            *(float4*)&P[(size_t)m * H1 + n0 + tx * 4] =
                make_float4(acc[i][0], acc[i][1], acc[i][2], acc[i][3]);
    }
}

// ---------------- main: mma.sync bf16 3-pass GEMM2, A generated on the fly --------
// smem layout (bytes)
constexpr int SA_STRIDE = 144;                 // 64 bf16 cols padded to 72 elems
constexpr int SB_STRIDE = 528;                 // 256 bf16 cols padded to 264 elems
constexpr uint32_t OFF_AH  = 0;                // 128 * 144 = 18432
constexpr uint32_t OFF_AL  = 18432;
constexpr uint32_t OFF_BH  = 36864;            // 64 * 528 = 33792
constexpr uint32_t OFF_BL  = 70656;
constexpr uint32_t OFF_OS  = 104448;           // int[128]
constexpr uint32_t OFF_OE  = 104960;
constexpr uint32_t OFF_BO  = 105472;
constexpr uint32_t OFF_CF  = 105984;
constexpr uint32_t OFF_W3A = 106496;           // float[256]
constexpr uint32_t OFF_W3B = 107520;
constexpr uint32_t OFF_SH2 = 108544;
constexpr uint32_t OFF_RED = 109568;           // float[2][128][2]
constexpr uint32_t SMEM_MAIN = 111616;

__global__ void __launch_bounds__(256, 1) k_main(const float* __restrict__ W3) {
    extern __shared__ char sm[];
    const uint32_t sb = smem_u32(sm);
    const int tid = threadIdx.x;
    const int lane = tid & 31;
    const int w = tid >> 5;
    const int mw = w & 3;           // M warp group (32 rows each)
    const int nw = w >> 2;          // N warp group (128 cols each)
    const int m0 = blockIdx.x * 128;
    const int n0 = blockIdx.y * 256;

    int*   sOS = (int*)(sm + OFF_OS);
    int*   sOE = (int*)(sm + OFF_OE);
    int*   sBO = (int*)(sm + OFF_BO);
    float* sCF = (float*)(sm + OFF_CF);
    float* sW3a = (float*)(sm + OFF_W3A);
    float* sW3b = (float*)(sm + OFF_W3B);
    float* sSh2 = (float*)(sm + OFF_SH2);
    float* sRed = (float*)(sm + OFF_RED);

    if (tid < 128) {
        int m = m0 + tid;
        int offS = 0, offE = 0, bo = 0;
        float cf = 0.f;
        if (m < ROWS) {
            int b = m / NCAND;
            int i = m - b * NCAND;
            int s = g_sidx[i], e = g_eidx[i];
            offS = (b * TPAD + s) * H1;
            offE = (b * TPAD + e + 1) * H1;
            bo = b * H1;
            cf = g_coef[e - s];
        }
        sOS[tid] = offS; sOE[tid] = offE; sBO[tid] = bo; sCF[tid] = cf;
    }
    sW3a[tid] = W3[n0 + tid];
    sW3b[tid] = W3[H2 + n0 + tid];
    sSh2[tid] = g_sh2[n0 + tid];
    __syncthreads();

    // A-gen config: thread covers row r, k-half kb (32 cols)
    const int r = tid >> 1;
    const int kb = (tid & 1) * 32;
    const int offS = sOS[r], offE = sOE[r], bo = sBO[r];
    const float cf = sCF[r];

    // ldmatrix base addresses
    const uint32_t aAddr0 = sb + OFF_AH + (uint32_t)((mw * 32 + (lane & 15)) * SA_STRIDE
                                                     + ((lane >> 4) * 8) * 2);
    const uint32_t bAddr0 = sb + OFF_BH + (uint32_t)((lane & 15) * SB_STRIDE + (nw * 128) * 2);

    float acc[2][16][4];
#pragma unroll
    for (int t = 0; t < 2; t++)
#pragma unroll
        for (int nf = 0; nf < 16; nf++)
#pragma unroll
            for (int c = 0; c < 4; c++) acc[t][nf][c] = 0.f;

#pragma unroll 1
    for (int c = 0; c < 16; c++) {
        __syncthreads();
        const int k0c = c * 64;
        // ---- stage B chunk (hi+lo): rows k0c..k0c+63, cols n0..n0+255 ----
#pragma unroll
        for (int it = 0; it < 8; it++) {
            int idx = it * 256 + tid;
            int kr = idx >> 5;
            int nc = idx & 31;
            size_t gsrc = ((size_t)(k0c + kr) * H2 + n0 + nc * 8) / 8;
            uint4 h = ((const uint4*)g_W2bh)[gsrc];
            uint4 l = ((const uint4*)g_W2bl)[gsrc];
            uint32_t d = (uint32_t)(kr * SB_STRIDE + nc * 16);
            *(uint4*)(sm + OFF_BH + d) = h;
            *(uint4*)(sm + OFF_BL + d) = l;
        }
        // ---- generate A chunk: gather + relu + bf16 split ----
        {
            const int k0 = k0c + kb;
            const float4* pA  = (const float4*)&g_PA[offS + k0];
            const float4* pBe = (const float4*)&g_PB[offE + k0];
            const float4* pBs = (const float4*)&g_PB[offS + k0];
            const float4* pC  = (const float4*)&g_PC[offE + k0];
            const float4* pQ  = (const float4*)&g_Pq[bo + k0];
            uint32_t hw[16], lw[16];
#pragma unroll
            for (int j = 0; j < 8; j++) {
                float4 a = pA[j], b = pBe[j], s = pBs[j], cc = pC[j], q = pQ[j];
                float v0 = fmaxf(a.x + b.x - cf * s.x + cc.x + q.x, 0.f);
                float v1 = fmaxf(a.y + b.y - cf * s.y + cc.y + q.y, 0.f);
                float v2 = fmaxf(a.z + b.z - cf * s.z + cc.z + q.z, 0.f);
                float v3 = fmaxf(a.w + b.w - cf * s.w + cc.w + q.w, 0.f);
                uint32_t u0 = pack_bf16x2(v0, v1);
                uint32_t u1 = pack_bf16x2(v2, v3);
                hw[2 * j]     = u0;
                hw[2 * j + 1] = u1;
                lw[2 * j]     = pack_bf16x2(v0 - bf_lo_f(u0), v1 - bf_hi_f(u0));
                lw[2 * j + 1] = pack_bf16x2(v2 - bf_lo_f(u1), v3 - bf_hi_f(u1));
            }
            const uint32_t ad = (uint32_t)(r * SA_STRIDE + kb * 2);
#pragma unroll
            for (int u = 0; u < 4; u++) {
                *(uint4*)(sm + OFF_AH + ad + u * 16) =
                    make_uint4(hw[4 * u], hw[4 * u + 1], hw[4 * u + 2], hw[4 * u + 3]);
                *(uint4*)(sm + OFF_AL + ad + u * 16) =
                    make_uint4(lw[4 * u], lw[4 * u + 1], lw[4 * u + 2], lw[4 * u + 3]);
            }
        }
        __syncthreads();
        // ---- compute: 4 k16 steps ----
#pragma unroll
        for (int s = 0; s < 4; s++) {
            const uint32_t ka = aAddr0 + (uint32_t)(s * 32);     // 16 elems * 2B
            uint32_t ah[2][4], al[2][4];
            ldsm_x4(ah[0], ka);
            ldsm_x4(ah[1], ka + 16 * SA_STRIDE);
            ldsm_x4(al[0], ka + (OFF_AL - OFF_AH));
            ldsm_x4(al[1], ka + (OFF_AL - OFF_AH) + 16 * SA_STRIDE);
            const uint32_t kbq = bAddr0 + (uint32_t)(s * 16 * SB_STRIDE);
#pragma unroll
            for (int nf = 0; nf < 16; nf += 2) {
                uint32_t bh0[2], bl0[2], bh1[2], bl1[2];
                ldsm_x2_t(bh0, kbq + nf * 16);
                ldsm_x2_t(bh1, kbq + nf * 16 + 16);
                ldsm_x2_t(bl0, kbq + nf * 16 + (OFF_BL - OFF_BH));
                ldsm_x2_t(bl1, kbq + nf * 16 + 16 + (OFF_BL - OFF_BH));
                mma16816(acc[0][nf], ah[0], bh0);
                mma16816(acc[1][nf], ah[1], bh0);
                mma16816(acc[0][nf + 1], ah[0], bh1);
                mma16816(acc[1][nf + 1], ah[1], bh1);
                mma16816(acc[0][nf], al[0], bh0);
                mma16816(acc[1][nf], al[1], bh0);
                mma16816(acc[0][nf + 1], al[0], bh1);
                mma16816(acc[1][nf + 1], al[1], bh1);
                mma16816(acc[0][nf], ah[0], bl0);
                mma16816(acc[1][nf], ah[1], bl0);
                mma16816(acc[0][nf + 1], ah[0], bl1);
                mma16816(acc[1][nf + 1], ah[1], bl1);
            }
        }
    }

    // ---- epilogue: relu(D + sh2) dot W3 rows, reduce, store partials ----
    float sums[4][2];
#pragma unroll
    for (int q = 0; q < 4; q++) { sums[q][0] = 0.f; sums[q][1] = 0.f; }
#pragma unroll
    for (int t = 0; t < 2; t++) {
#pragma unroll
        for (int nf = 0; nf < 16; nf++) {
            int n = nw * 128 + nf * 8 + (lane & 3) * 2;
            float sh0 = sSh2[n], sh1 = sSh2[n + 1];
            float wa0 = sW3a[n], wa1 = sW3a[n + 1];
            float wb0 = sW3b[n], wb1 = sW3b[n + 1];
            float v0 = fmaxf(acc[t][nf][0] + sh0, 0.f);
            float v1 = fmaxf(acc[t][nf][1] + sh1, 0.f);
            float v2 = fmaxf(acc[t][nf][2] + sh0, 0.f);
            float v3 = fmaxf(acc[t][nf][3] + sh1, 0.f);
            sums[t * 2][0]     = fmaf(v0, wa0, fmaf(v1, wa1, sums[t * 2][0]));
            sums[t * 2][1]     = fmaf(v0, wb0, fmaf(v1, wb1, sums[t * 2][1]));
            sums[t * 2 + 1][0] = fmaf(v2, wa0, fmaf(v3, wa1, sums[t * 2 + 1][0]));
            sums[t * 2 + 1][1] = fmaf(v2, wb0, fmaf(v3, wb1, sums[t * 2 + 1][1]));
        }
    }
#pragma unroll
    for (int q = 0; q < 4; q++) {
#pragma unroll
        for (int o = 0; o < 2; o++) {
            sums[q][o] += __shfl_xor_sync(0xffffffffu, sums[q][o], 1);
            sums[q][o] += __shfl_xor_sync(0xffffffffu, sums[q][o], 2);
        }
    }
    __syncthreads();
    if ((lane & 3) == 0) {
#pragma unroll
        for (int q = 0; q < 4; q++) {
            int rloc = mw * 32 + (q >> 1) * 16 + (q & 1) * 8 + (lane >> 2);
            sRed[nw * 256 + rloc * 2 + 0] = sums[q][0];
            sRed[nw * 256 + rloc * 2 + 1] = sums[q][1];
        }
    }
    __syncthreads();
    {
        int rloc = tid >> 1, o = tid & 1;
        int m = m0 + rloc;
        if (m < ROWS) {
            float v = sRed[rloc * 2 + o] + sRed[256 + rloc * 2 + o];
            g_outp[(size_t)blockIdx.y * (ROWS * 2) + m * 2 + o] = v;
        }
    }
}

__global__ void k_sum(float* __restrict__ out) {
    int i = blockIdx.x * 256 + threadIdx.x;
    if (i < ROWS * 2) out[i] = g_outp[i] + g_outp[ROWS * 2 + i];
}

// ---------------- launch ----------------
extern "C" void kernel_launch(void* const* d_in, const int* in_sizes, int n_in,
                              void* d_out, int out_size) {
    (void)in_sizes; (void)n_in; (void)out_size;
    const float* doc = (const float*)d_in[0];
    const float* qe  = (const float*)d_in[1];
    const float* W1  = (const float*)d_in[2];
    const float* g1  = (const float*)d_in[3];
    const float* b1  = (const float*)d_in[4];
    const float* m1  = (const float*)d_in[5];
    const float* v1  = (const float*)d_in[6];
    const float* W2  = (const float*)d_in[7];
    const float* g2  = (const float*)d_in[8];
    const float* b2  = (const float*)d_in[9];
    const float* m2  = (const float*)d_in[10];
    const float* v2  = (const float*)d_in[11];
    const float* W3  = (const float*)d_in[12];
    float* out = (float*)d_out;

    cudaFuncSetAttribute(k_main, cudaFuncAttributeMaxDynamicSharedMemorySize, SMEM_MAIN);

    k_setup1<<<512, 256>>>(qe, W1, g1, b1, m1, v1, W2, g2, b2, m2, v2);
    k_scan<<<dim3(BB, 2), DD>>>(doc);
    k_pq<<<dim3(H1 / 256, BB), 256>>>(b1, m1, g1, v1);
    k_proj<<<dim3((MROWS + 63) / 64, H1 / 64, 3), 256>>>();
    k_main<<<dim3((ROWS + 127) / 128, 2), 256, SMEM_MAIN>>>(W3);
    k_sum<<<(ROWS * 2 + 255) / 256, 256>>>(out);
}

// round 4
// speedup vs baseline: 2.0020x; 1.1145x over previous
#include <cuda_runtime.h>
#include <cuda_fp16.h>
#include <cstdint>

#define ALPHA 0.9f
constexpr int T_LEN = 809;
constexpr int TPAD  = 810;
constexpr int DD    = 304;
constexpr int EE    = 300;
constexpr int LQ    = 30;
constexpr int BB    = 4;
constexpr int MSPAN = 16;
constexpr int H1    = 1024;
constexpr int H2    = 512;
constexpr int CIN   = 1212;
constexpr int NCAND = 12824;
constexpr int ROWS  = BB * NCAND;      // 51296
constexpr int MROWS = BB * TPAD;       // 3240
constexpr float EPS = 1e-5f;

// ---------------- scratch ----------------
__device__ float g_Fp[MROWS * DD];
__device__ float g_Rp[MROWS * DD];
__device__ float g_PA[MROWS * H1];
__device__ float g_PB[MROWS * H1];
__device__ float g_PC[MROWS * H1];
__device__ float g_Pq[BB * H1];
__device__ float g_W1s[H1 * CIN];
__device__ __align__(16) __half g_W2h16[H1 * H2];  // fp16(W2*sc2), layout [k][n]
__device__ float g_sh2[H2];
__device__ float g_qf[BB * EE];
__device__ float g_coef[MSPAN];
__device__ int   g_sidx[NCAND];
__device__ int   g_eidx[NCAND];
__device__ float g_outp[2 * ROWS * 2];  // per-N-tile partial outputs

// ---------------- helpers ----------------
__device__ __forceinline__ uint32_t smem_u32(const void* p) {
    uint32_t a;
    asm("{ .reg .u64 t; cvta.to.shared.u64 t, %1; cvt.u32.u64 %0, t; }" : "=r"(a) : "l"(p));
    return a;
}
__device__ __forceinline__ unsigned long long pack2(float x) {
    unsigned long long r;
    asm("mov.b64 %0, {%1, %1};" : "=l"(r) : "f"(x));
    return r;
}
__device__ __forceinline__ void fma2(unsigned long long& d, unsigned long long a,
                                     unsigned long long b) {
    asm("fma.rn.f32x2 %0, %1, %2, %0;" : "+l"(d) : "l"(a), "l"(b));
}
__device__ __forceinline__ float2 unpack2(unsigned long long v) {
    float2 r;
    asm("mov.b64 {%0, %1}, %2;" : "=f"(r.x), "=f"(r.y) : "l"(v));
    return r;
}
__device__ __forceinline__ uint32_t h2u(__half2 h) { return *(uint32_t*)&h; }

__device__ __forceinline__ void ldsm_x4(uint32_t* r, uint32_t a) {
    asm volatile("ldmatrix.sync.aligned.m8n8.x4.shared.b16 {%0,%1,%2,%3}, [%4];"
                 : "=r"(r[0]), "=r"(r[1]), "=r"(r[2]), "=r"(r[3]) : "r"(a));
}
__device__ __forceinline__ void ldsm_x4_t(uint32_t* r, uint32_t a) {
    asm volatile("ldmatrix.sync.aligned.m8n8.x4.trans.shared.b16 {%0,%1,%2,%3}, [%4];"
                 : "=r"(r[0]), "=r"(r[1]), "=r"(r[2]), "=r"(r[3]) : "r"(a));
}
__device__ __forceinline__ void mma16816(float* d, const uint32_t* a, const uint32_t* b) {
    asm volatile(
        "mma.sync.aligned.m16n8k16.row.col.f32.f16.f16.f32 "
        "{%0,%1,%2,%3}, {%4,%5,%6,%7}, {%8,%9}, {%0,%1,%2,%3};"
        : "+f"(d[0]), "+f"(d[1]), "+f"(d[2]), "+f"(d[3])
        : "r"(a[0]), "r"(a[1]), "r"(a[2]), "r"(a[3]), "r"(b[0]), "r"(b[1]));
}
__device__ __forceinline__ void cp16(uint32_t dst, const void* src) {
    asm volatile("cp.async.cg.shared.global [%0], [%1], 16;" :: "r"(dst), "l"(src));
}
__device__ __forceinline__ void cp_commit() { asm volatile("cp.async.commit_group;"); }
template <int N> __device__ __forceinline__ void cp_wait() {
    asm volatile("cp.async.wait_group %0;" :: "n"(N));
}

// ---------------- setup ----------------
__global__ void k_setup1(const float* __restrict__ Qe,
                         const float* __restrict__ W1,
                         const float* __restrict__ g1, const float* __restrict__ b1,
                         const float* __restrict__ m1, const float* __restrict__ v1,
                         const float* __restrict__ W2,
                         const float* __restrict__ g2, const float* __restrict__ b2,
                         const float* __restrict__ m2, const float* __restrict__ v2) {
    const long NW1 = (long)H1 * CIN;
    const long NW2 = (long)H1 * H2;
    const long total = NW1 + NW2 + H2 + BB * EE + T_LEN + MSPAN;
    for (long idx = (long)blockIdx.x * blockDim.x + threadIdx.x; idx < total;
         idx += (long)gridDim.x * blockDim.x) {
        long i = idx;
        if (i < NW1) {
            int j = (int)(i / CIN);
            float sc = g1[j] * rsqrtf(v1[j] + EPS);
            g_W1s[i] = W1[i] * sc;
            continue;
        }
        i -= NW1;
        if (i < NW2) {  // layout [k][n]
            int n = (int)(i % H2);
            int k = (int)(i / H2);
            float sc = g2[n] * rsqrtf(v2[n] + EPS);
            g_W2h16[i] = __float2half_rn(W2[(size_t)n * H1 + k] * sc);
            continue;
        }
        i -= NW2;
        if (i < H2) {
            float sc = g2[i] * rsqrtf(v2[i] + EPS);
            g_sh2[i] = b2[i] - m2[i] * sc;
            continue;
        }
        i -= H2;
        if (i < BB * EE) {
            int b = (int)(i / EE), d = (int)(i % EE);
            float acc = 0.f, p = 1.f;
            for (int t = LQ - 1; t >= 0; t--) {
                acc = fmaf(p, Qe[(b * LQ + t) * EE + d], acc);
                p *= ALPHA;
            }
            g_qf[i] = acc;
            continue;
        }
        i -= BB * EE;
        if (i < T_LEN) {
            int s = (int)i;
            int cnt = min(MSPAN, T_LEN - s);
            int ex = (s > 794) ? ((s - 794) * (s - 793)) / 2 : 0;
            int base = 16 * s - ex;
            for (int sp = 0; sp < cnt; sp++) {
                g_sidx[base + sp] = s;
                g_eidx[base + sp] = s + sp;
            }
            continue;
        }
        i -= T_LEN;
        if (i < MSPAN) {
            double c = 1.0;
            for (int k = 0; k <= (int)i; k++) c *= 0.9;
            g_coef[i] = (float)c;
        }
    }
}

__global__ void k_pq(const float* __restrict__ b1, const float* __restrict__ m1,
                     const float* __restrict__ g1, const float* __restrict__ v1) {
    int j = blockIdx.x * blockDim.x + threadIdx.x;
    int b = blockIdx.y;
    if (j >= H1) return;
    float sc = g1[j] * rsqrtf(v1[j] + EPS);
    float acc = b1[j] - m1[j] * sc;
    const float* w = &g_W1s[j * CIN + 3 * DD];
    const float* q = &g_qf[b * EE];
    for (int d = 0; d < EE; d++) acc = fmaf(q[d], w[d], acc);
    g_Pq[b * H1 + j] = acc;
}

// ---------------- scans: smem-tiled to avoid alias-stalled loads ----------------
__global__ void k_scan(const float* __restrict__ doc) {
    __shared__ float tile[32 * DD];
    const int d = threadIdx.x;
    const int b = blockIdx.x;
    const float* dp = doc + (size_t)b * T_LEN * DD;
    if (blockIdx.y == 0) {
        float acc = 0.f;
        float* fp = g_Fp + (size_t)(b * TPAD) * DD + d;
        fp[0] = 0.f;
        for (int t0 = 0; t0 < T_LEN; t0 += 32) {
            int n = min(32, T_LEN - t0);
            __syncthreads();
            for (int i = d; i < n * DD; i += DD) tile[i] = dp[(size_t)t0 * DD + i];
            __syncthreads();
            for (int i = 0; i < n; i++) {
                acc = fmaf(ALPHA, acc, tile[i * DD + d]);
                fp[(size_t)(t0 + i + 1) * DD] = acc;
            }
        }
    } else {
        float acc = 0.f;
        float* rp = g_Rp + (size_t)(b * TPAD) * DD + d;
        rp[(size_t)T_LEN * DD] = 0.f;
        for (int hi = T_LEN; hi > 0; hi -= 32) {
            int lo = (hi > 32) ? hi - 32 : 0;
            int n = hi - lo;
            __syncthreads();
            for (int i = d; i < n * DD; i += DD) tile[i] = dp[(size_t)lo * DD + i];
            __syncthreads();
            for (int i = n - 1; i >= 0; i--) {
                acc = fmaf(ALPHA, acc, tile[i * DD + d]);
                rp[(size_t)(lo + i) * DD] = acc;
            }
        }
    }
}

// ---------------- projections: 128x128 tile, f32x2 accumulators ----------------
__global__ void __launch_bounds__(256) k_proj() {
    const int z = blockIdx.z;
    const float* A = (z == 2) ? g_Rp : g_Fp;
    float* P = (z == 0) ? g_PA : (z == 1 ? g_PB : g_PC);
    const int colofs = z * DD;
    const int m0 = blockIdx.x * 128;
    const int n0 = blockIdx.y * 128;
    __shared__ __align__(16) float sA[16 * 132];
    __shared__ __align__(16) float sB[16 * 132];
    const int tid = threadIdx.x;
    const int ty = tid >> 4, tx = tid & 15;
    const int r = tid >> 2, kq = (tid & 3) * 4;

    unsigned long long acc2[8][4];
#pragma unroll
    for (int i = 0; i < 8; i++)
#pragma unroll
        for (int j = 0; j < 4; j++) acc2[i][j] = 0ULL;

    for (int k0 = 0; k0 < DD; k0 += 16) {
        __syncthreads();
#pragma unroll
        for (int h = 0; h < 2; h++) {
            int rr = r + h * 64;
            int m = m0 + rr;
            float4 va = make_float4(0.f, 0.f, 0.f, 0.f);
            if (m < MROWS) va = *(const float4*)&A[(size_t)m * DD + k0 + kq];
            sA[(kq + 0) * 132 + rr] = va.x;
            sA[(kq + 1) * 132 + rr] = va.y;
            sA[(kq + 2) * 132 + rr] = va.z;
            sA[(kq + 3) * 132 + rr] = va.w;
            int n = n0 + rr;
            float4 vb = *(const float4*)&g_W1s[(size_t)n * CIN + colofs + k0 + kq];
            sB[(kq + 0) * 132 + rr] = vb.x;
            sB[(kq + 1) * 132 + rr] = vb.y;
            sB[(kq + 2) * 132 + rr] = vb.z;
            sB[(kq + 3) * 132 + rr] = vb.w;
        }
        __syncthreads();
#pragma unroll
        for (int kk = 0; kk < 16; kk++) {
            float4 a0 = *(const float4*)&sA[kk * 132 + ty * 8];
            float4 a1 = *(const float4*)&sA[kk * 132 + ty * 8 + 4];
            ulonglong2 bq0 = *(const ulonglong2*)&sB[kk * 132 + tx * 8];
            ulonglong2 bq1 = *(const ulonglong2*)&sB[kk * 132 + tx * 8 + 4];
            unsigned long long pa[8] = {pack2(a0.x), pack2(a0.y), pack2(a0.z), pack2(a0.w),
                                        pack2(a1.x), pack2(a1.y), pack2(a1.z), pack2(a1.w)};
#pragma unroll
            for (int i = 0; i < 8; i++) {
                fma2(acc2[i][0], pa[i], bq0.x);
                fma2(acc2[i][1], pa[i], bq0.y);
                fma2(acc2[i][2], pa[i], bq1.x);
                fma2(acc2[i][3], pa[i], bq1.y);
            }
        }
    }
#pragma unroll
    for (int i = 0; i < 8; i++) {
        int m = m0 + ty * 8 + i;
        if (m >= MROWS) continue;
        float2 v0 = unpack2(acc2[i][0]);
        float2 v1 = unpack2(acc2[i][1]);
        float2 v2 = unpack2(acc2[i][2]);
        float2 v3 = unpack2(acc2[i][3]);
        *(float4*)&P[(size_t)m * H1 + n0 + tx * 8] = make_float4(v0.x, v0.y, v1.x, v1.y);
        *(float4*)&P[(size_t)m * H1 + n0 + tx * 8 + 4] = make_float4(v2.x, v2.y, v3.x, v3.y);
    }
}

// -------- main: fp16 2-pass mma GEMM2, cp.async double-buffered pipeline --------
constexpr int SA_STRIDE = 144;                 // 64 fp16 cols -> 128B + 16 pad
constexpr int SB_STRIDE = 528;                 // 256 fp16 cols -> 512B + 16 pad
constexpr uint32_t OFF_AH   = 0;               // 128*144 = 18432
constexpr uint32_t OFF_AL   = 18432;
constexpr uint32_t OFF_BH   = 36864;           // 64*528 = 33792
constexpr uint32_t STAGE_SZ = 70656;
constexpr uint32_t OFF_HDR  = 141312;
constexpr uint32_t OFF_OS   = OFF_HDR;
constexpr uint32_t OFF_OE   = OFF_HDR + 512;
constexpr uint32_t OFF_BO   = OFF_HDR + 1024;
constexpr uint32_t OFF_CF   = OFF_HDR + 1536;
constexpr uint32_t OFF_W3A  = OFF_HDR + 2048;
constexpr uint32_t OFF_W3B  = OFF_HDR + 3072;
constexpr uint32_t OFF_SH2  = OFF_HDR + 4096;
constexpr uint32_t OFF_RED  = OFF_HDR + 5120;  // float[2][128][2]
constexpr uint32_t SMEM_MAIN = OFF_HDR + 7168; // 148480

__global__ void __launch_bounds__(256, 1) k_main(const float* __restrict__ W3) {
    extern __shared__ char sm[];
    const uint32_t sb = smem_u32(sm);
    const int tid = threadIdx.x;
    const int lane = tid & 31;
    const int w = tid >> 5;
    const int mw = w & 3;
    const int nw = w >> 2;
    const int m0 = blockIdx.x * 128;
    const int n0 = blockIdx.y * 256;

    int*   sOS = (int*)(sm + OFF_OS);
    int*   sOE = (int*)(sm + OFF_OE);
    int*   sBO = (int*)(sm + OFF_BO);
    float* sCF = (float*)(sm + OFF_CF);
    float* sW3a = (float*)(sm + OFF_W3A);
    float* sW3b = (float*)(sm + OFF_W3B);
    float* sSh2 = (float*)(sm + OFF_SH2);
    float* sRed = (float*)(sm + OFF_RED);

    if (tid < 128) {
        int m = m0 + tid;
        int offS = 0, offE = 0, bo = 0;
        float cf = 0.f;
        if (m < ROWS) {
            int b = m / NCAND;
            int i = m - b * NCAND;
            int s = g_sidx[i], e = g_eidx[i];
            offS = (b * TPAD + s) * H1;
            offE = (b * TPAD + e + 1) * H1;
            bo = b * H1;
            cf = g_coef[e - s];
        }
        sOS[tid] = offS; sOE[tid] = offE; sBO[tid] = bo; sCF[tid] = cf;
    }
    sW3a[tid] = W3[n0 + tid];
    sW3b[tid] = W3[H2 + n0 + tid];
    sSh2[tid] = g_sh2[n0 + tid];
    __syncthreads();

    // A-gen per-thread config: row r, k-half kb
    const int r = tid >> 1;
    const int kb = (tid & 1) * 32;
    const float cf = sCF[r];
    const float4* pA  = (const float4*)&g_PA[sOS[r] + kb];
    const float4* pBs = (const float4*)&g_PB[sOS[r] + kb];
    const float4* pBe = (const float4*)&g_PB[sOE[r] + kb];
    const float4* pC  = (const float4*)&g_PC[sOE[r] + kb];
    const float4* pQ  = (const float4*)&g_Pq[sBO[r] + kb];
    const uint32_t ad = (uint32_t)(r * SA_STRIDE + kb * 2);

    // B cp.async per-thread config
    const int bkr = tid >> 5;          // +8 per it step of 8 -> covers 64 rows via 8 its
    const int bnc = tid & 31;

    // ldmatrix base (stage-relative)
    const uint32_t aRel = OFF_AH + (uint32_t)((mw * 32 + (lane & 15)) * SA_STRIDE +
                                              ((lane >> 4) * 8) * 2);
    const uint32_t bRel = OFF_BH + (uint32_t)((lane & 15) * SB_STRIDE +
                                              (nw * 128 + (lane >> 4) * 8) * 2);

    float acc[2][16][4];
#pragma unroll
    for (int t = 0; t < 2; t++)
#pragma unroll
        for (int nf = 0; nf < 16; nf++)
#pragma unroll
            for (int c = 0; c < 4; c++) acc[t][nf][c] = 0.f;

    auto stage = [&](int cc) {
        const uint32_t st = sb + (uint32_t)(cc & 1) * STAGE_SZ;
        // B: global -> smem via cp.async (bypass regs)
        const __half* bsrc = &g_W2h16[(size_t)(cc * 64) * H2 + n0];
#pragma unroll
        for (int it = 0; it < 8; it++) {
            int kr = bkr + it * 8;
            cp16(st + OFF_BH + (uint32_t)(kr * SB_STRIDE + bnc * 16),
                 bsrc + (size_t)kr * H2 + bnc * 8);
        }
        cp_commit();
        // A: gather + relu + fp16 hi/lo split
        const int base = cc * 16;
        uint32_t hw[16], lw[16];
#pragma unroll
        for (int j = 0; j < 8; j++) {
            float4 a = pA[base + j], b = pBe[base + j], s = pBs[base + j];
            float4 c2 = pC[base + j], q = pQ[base + j];
            float v0 = fmaxf(a.x + b.x - cf * s.x + c2.x + q.x, 0.f);
            float v1 = fmaxf(a.y + b.y - cf * s.y + c2.y + q.y, 0.f);
            float v2 = fmaxf(a.z + b.z - cf * s.z + c2.z + q.z, 0.f);
            float v3 = fmaxf(a.w + b.w - cf * s.w + c2.w + q.w, 0.f);
            __half2 h01 = __floats2half2_rn(v0, v1);
            __half2 h23 = __floats2half2_rn(v2, v3);
            float2 f01 = __half22float2(h01);
            float2 f23 = __half22float2(h23);
            hw[2 * j]     = h2u(h01);
            hw[2 * j + 1] = h2u(h23);
            lw[2 * j]     = h2u(__floats2half2_rn(v0 - f01.x, v1 - f01.y));
            lw[2 * j + 1] = h2u(__floats2half2_rn(v2 - f23.x, v3 - f23.y));
        }
#pragma unroll
        for (int u = 0; u < 4; u++) {
            *(uint4*)(sm + (cc & 1) * STAGE_SZ + OFF_AH + ad + u * 16) =
                make_uint4(hw[4 * u], hw[4 * u + 1], hw[4 * u + 2], hw[4 * u + 3]);
            *(uint4*)(sm + (cc & 1) * STAGE_SZ + OFF_AL + ad + u * 16) =
                make_uint4(lw[4 * u], lw[4 * u + 1], lw[4 * u + 2], lw[4 * u + 3]);
        }
    };

    stage(0);

#pragma unroll 1
    for (int c = 0; c < 16; c++) {
        if (c < 15) { stage(c + 1); cp_wait<1>(); }
        else        { cp_wait<0>(); }
        __syncthreads();
        const uint32_t st = sb + (uint32_t)(c & 1) * STAGE_SZ;
#pragma unroll
        for (int s = 0; s < 4; s++) {
            const uint32_t ka = st + aRel + (uint32_t)(s * 32);
            uint32_t ah[2][4], al[2][4];
            ldsm_x4(ah[0], ka);
            ldsm_x4(ah[1], ka + 16 * SA_STRIDE);
            ldsm_x4(al[0], ka + (OFF_AL - OFF_AH));
            ldsm_x4(al[1], ka + (OFF_AL - OFF_AH) + 16 * SA_STRIDE);
            const uint32_t kbq = st + bRel + (uint32_t)(s * 16 * SB_STRIDE);
#pragma unroll
            for (int p = 0; p < 8; p++) {
                uint32_t bq[4];
                ldsm_x4_t(bq, kbq + p * 32);
                mma16816(acc[0][2 * p],     ah[0], bq);
                mma16816(acc[1][2 * p],     ah[1], bq);
                mma16816(acc[0][2 * p + 1], ah[0], bq + 2);
                mma16816(acc[1][2 * p + 1], ah[1], bq + 2);
                mma16816(acc[0][2 * p],     al[0], bq);
                mma16816(acc[1][2 * p],     al[1], bq);
                mma16816(acc[0][2 * p + 1], al[0], bq + 2);
                mma16816(acc[1][2 * p + 1], al[1], bq + 2);
            }
        }
        __syncthreads();
    }

    // ---- epilogue: relu(D + sh2) dot W3 rows, reduce, store partials ----
    float sums[4][2];
#pragma unroll
    for (int q = 0; q < 4; q++) { sums[q][0] = 0.f; sums[q][1] = 0.f; }
#pragma unroll
    for (int t = 0; t < 2; t++) {
#pragma unroll
        for (int nf = 0; nf < 16; nf++) {
            int n = nw * 128 + nf * 8 + (lane & 3) * 2;
            float sh0 = sSh2[n], sh1 = sSh2[n + 1];
            float wa0 = sW3a[n], wa1 = sW3a[n + 1];
            float wb0 = sW3b[n], wb1 = sW3b[n + 1];
            float v0 = fmaxf(acc[t][nf][0] + sh0, 0.f);
            float v1 = fmaxf(acc[t][nf][1] + sh1, 0.f);
            float v2 = fmaxf(acc[t][nf][2] + sh0, 0.f);
            float v3 = fmaxf(acc[t][nf][3] + sh1, 0.f);
            sums[t * 2][0]     = fmaf(v0, wa0, fmaf(v1, wa1, sums[t * 2][0]));
            sums[t * 2][1]     = fmaf(v0, wb0, fmaf(v1, wb1, sums[t * 2][1]));
            sums[t * 2 + 1][0] = fmaf(v2, wa0, fmaf(v3, wa1, sums[t * 2 + 1][0]));
            sums[t * 2 + 1][1] = fmaf(v2, wb0, fmaf(v3, wb1, sums[t * 2 + 1][1]));
        }
    }
#pragma unroll
    for (int q = 0; q < 4; q++) {
#pragma unroll
        for (int o = 0; o < 2; o++) {
            sums[q][o] += __shfl_xor_sync(0xffffffffu, sums[q][o], 1);
            sums[q][o] += __shfl_xor_sync(0xffffffffu, sums[q][o], 2);
        }
    }
    __syncthreads();
    if ((lane & 3) == 0) {
#pragma unroll
        for (int q = 0; q < 4; q++) {
            int rloc = mw * 32 + (q >> 1) * 16 + (q & 1) * 8 + (lane >> 2);
            sRed[nw * 256 + rloc * 2 + 0] = sums[q][0];
            sRed[nw * 256 + rloc * 2 + 1] = sums[q][1];
        }
    }
    __syncthreads();
    {
        int rloc = tid >> 1, o = tid & 1;
        int m = m0 + rloc;
        if (m < ROWS) {
            float v = sRed[rloc * 2 + o] + sRed[256 + rloc * 2 + o];
            g_outp[(size_t)blockIdx.y * (ROWS * 2) + m * 2 + o] = v;
        }
    }
}

__global__ void k_sum(float* __restrict__ out) {
    int i = blockIdx.x * 256 + threadIdx.x;
    if (i < ROWS * 2) out[i] = g_outp[i] + g_outp[ROWS * 2 + i];
}

// ---------------- launch ----------------
extern "C" void kernel_launch(void* const* d_in, const int* in_sizes, int n_in,
                              void* d_out, int out_size) {
    (void)in_sizes; (void)n_in; (void)out_size;
    const float* doc = (const float*)d_in[0];
    const float* qe  = (const float*)d_in[1];
    const float* W1  = (const float*)d_in[2];
    const float* g1  = (const float*)d_in[3];
    const float* b1  = (const float*)d_in[4];
    const float* m1  = (const float*)d_in[5];
    const float* v1  = (const float*)d_in[6];
    const float* W2  = (const float*)d_in[7];
    const float* g2  = (const float*)d_in[8];
    const float* b2  = (const float*)d_in[9];
    const float* m2  = (const float*)d_in[10];
    const float* v2  = (const float*)d_in[11];
    const float* W3  = (const float*)d_in[12];
    float* out = (float*)d_out;

    cudaFuncSetAttribute(k_main, cudaFuncAttributeMaxDynamicSharedMemorySize, SMEM_MAIN);

    k_setup1<<<512, 256>>>(qe, W1, g1, b1, m1, v1, W2, g2, b2, m2, v2);
    k_scan<<<dim3(BB, 2), DD>>>(doc);
    k_pq<<<dim3(H1 / 256, BB), 256>>>(b1, m1, g1, v1);
    k_proj<<<dim3((MROWS + 127) / 128, H1 / 128, 3), 256>>>();
    k_main<<<dim3((ROWS + 127) / 128, 2), 256, SMEM_MAIN>>>(W3);
    k_sum<<<(ROWS * 2 + 255) / 256, 256>>>(out);
}

// round 5
// speedup vs baseline: 2.6073x; 1.3024x over previous
#include <cuda_runtime.h>
#include <cuda_fp16.h>
#include <cstdint>

#define ALPHA 0.9f
constexpr int T_LEN = 809;
constexpr int TPAD  = 810;
constexpr int DD    = 304;
constexpr int EE    = 300;
constexpr int LQ    = 30;
constexpr int BB    = 4;
constexpr int MSPAN = 16;
constexpr int H1    = 1024;
constexpr int H2    = 512;
constexpr int CIN   = 1212;
constexpr int NCAND = 12824;
constexpr int ROWS  = BB * NCAND;      // 51296
constexpr int MROWS = BB * TPAD;       // 3240
constexpr float EPS = 1e-5f;

// ---------------- scratch ----------------
__device__ float g_Fp[MROWS * DD];
__device__ float g_Rp[MROWS * DD];
__device__ float g_PA[MROWS * H1];     // includes Pq fold (added in k_proj z==0)
__device__ float g_PB[MROWS * H1];
__device__ float g_PC[MROWS * H1];
__device__ float g_Pq[BB * H1];
__device__ float g_W1s[H1 * CIN];
__device__ __align__(16) __half g_W2h16[H1 * H2];  // fp16(W2*sc2), layout [k][n]
__device__ float g_sh2[H2];
__device__ float g_qf[BB * EE];
__device__ float g_coef[MSPAN];
__device__ int   g_sidx[NCAND];
__device__ int   g_eidx[NCAND];
__device__ float g_outp[2 * ROWS * 2];  // per-N-tile partial outputs

// ---------------- helpers ----------------
__device__ __forceinline__ uint32_t smem_u32(const void* p) {
    uint32_t a;
    asm("{ .reg .u64 t; cvta.to.shared.u64 t, %1; cvt.u32.u64 %0, t; }" : "=r"(a) : "l"(p));
    return a;
}
__device__ __forceinline__ unsigned long long pack2(float x) {
    unsigned long long r;
    asm("mov.b64 %0, {%1, %1};" : "=l"(r) : "f"(x));
    return r;
}
__device__ __forceinline__ void fma2(unsigned long long& d, unsigned long long a,
                                     unsigned long long b) {
    asm("fma.rn.f32x2 %0, %1, %2, %0;" : "+l"(d) : "l"(a), "l"(b));
}
__device__ __forceinline__ float2 unpack2(unsigned long long v) {
    float2 r;
    asm("mov.b64 {%0, %1}, %2;" : "=f"(r.x), "=f"(r.y) : "l"(v));
    return r;
}
__device__ __forceinline__ uint32_t h2u(__half2 h) { return *(uint32_t*)&h; }

__device__ __forceinline__ void ldsm_x4(uint32_t* r, uint32_t a) {
    asm volatile("ldmatrix.sync.aligned.m8n8.x4.shared.b16 {%0,%1,%2,%3}, [%4];"
                 : "=r"(r[0]), "=r"(r[1]), "=r"(r[2]), "=r"(r[3]) : "r"(a));
}
__device__ __forceinline__ void ldsm_x4_t(uint32_t* r, uint32_t a) {
    asm volatile("ldmatrix.sync.aligned.m8n8.x4.trans.shared.b16 {%0,%1,%2,%3}, [%4];"
                 : "=r"(r[0]), "=r"(r[1]), "=r"(r[2]), "=r"(r[3]) : "r"(a));
}
__device__ __forceinline__ void mma16816(float* d, const uint32_t* a, const uint32_t* b) {
    asm volatile(
        "mma.sync.aligned.m16n8k16.row.col.f32.f16.f16.f32 "
        "{%0,%1,%2,%3}, {%4,%5,%6,%7}, {%8,%9}, {%0,%1,%2,%3};"
        : "+f"(d[0]), "+f"(d[1]), "+f"(d[2]), "+f"(d[3])
        : "r"(a[0]), "r"(a[1]), "r"(a[2]), "r"(a[3]), "r"(b[0]), "r"(b[1]));
}
__device__ __forceinline__ void cp16(uint32_t dst, const void* src) {
    asm volatile("cp.async.cg.shared.global [%0], [%1], 16;" :: "r"(dst), "l"(src));
}
__device__ __forceinline__ void cp_commit() { asm volatile("cp.async.commit_group;"); }
template <int N> __device__ __forceinline__ void cp_wait() {
    asm volatile("cp.async.wait_group %0;" :: "n"(N));
}

// ---------------- setup ----------------
__global__ void k_setup1(const float* __restrict__ Qe,
                         const float* __restrict__ W1,
                         const float* __restrict__ g1, const float* __restrict__ b1,
                         const float* __restrict__ m1, const float* __restrict__ v1,
                         const float* __restrict__ W2,
                         const float* __restrict__ g2, const float* __restrict__ b2,
                         const float* __restrict__ m2, const float* __restrict__ v2) {
    const long NW1 = (long)H1 * CIN;
    const long NW2 = (long)H1 * H2;
    const long total = NW1 + NW2 + H2 + BB * EE + T_LEN + MSPAN;
    for (long idx = (long)blockIdx.x * blockDim.x + threadIdx.x; idx < total;
         idx += (long)gridDim.x * blockDim.x) {
        long i = idx;
        if (i < NW1) {
            int j = (int)(i / CIN);
            float sc = g1[j] * rsqrtf(v1[j] + EPS);
            g_W1s[i] = W1[i] * sc;
            continue;
        }
        i -= NW1;
        if (i < NW2) {  // layout [k][n]
            int n = (int)(i % H2);
            int k = (int)(i / H2);
            float sc = g2[n] * rsqrtf(v2[n] + EPS);
            g_W2h16[i] = __float2half_rn(W2[(size_t)n * H1 + k] * sc);
            continue;
        }
        i -= NW2;
        if (i < H2) {
            float sc = g2[i] * rsqrtf(v2[i] + EPS);
            g_sh2[i] = b2[i] - m2[i] * sc;
            continue;
        }
        i -= H2;
        if (i < BB * EE) {
            int b = (int)(i / EE), d = (int)(i % EE);
            float acc = 0.f, p = 1.f;
            for (int t = LQ - 1; t >= 0; t--) {
                acc = fmaf(p, Qe[(b * LQ + t) * EE + d], acc);
                p *= ALPHA;
            }
            g_qf[i] = acc;
            continue;
        }
        i -= BB * EE;
        if (i < T_LEN) {
            int s = (int)i;
            int cnt = min(MSPAN, T_LEN - s);
            int ex = (s > 794) ? ((s - 794) * (s - 793)) / 2 : 0;
            int base = 16 * s - ex;
            for (int sp = 0; sp < cnt; sp++) {
                g_sidx[base + sp] = s;
                g_eidx[base + sp] = s + sp;
            }
            continue;
        }
        i -= T_LEN;
        if (i < MSPAN) {
            double c = 1.0;
            for (int k = 0; k <= (int)i; k++) c *= 0.9;
            g_coef[i] = (float)c;
        }
    }
}

__global__ void k_pq(const float* __restrict__ b1, const float* __restrict__ m1,
                     const float* __restrict__ g1, const float* __restrict__ v1) {
    int j = blockIdx.x * blockDim.x + threadIdx.x;
    int b = blockIdx.y;
    if (j >= H1) return;
    float sc = g1[j] * rsqrtf(v1[j] + EPS);
    float acc = b1[j] - m1[j] * sc;
    const float* w = &g_W1s[j * CIN + 3 * DD];
    const float* q = &g_qf[b * EE];
    for (int d = 0; d < EE; d++) acc = fmaf(q[d], w[d], acc);
    g_Pq[b * H1 + j] = acc;
}

// ---------------- scans: smem-tiled to avoid alias-stalled loads ----------------
__global__ void k_scan(const float* __restrict__ doc) {
    __shared__ float tile[32 * DD];
    const int d = threadIdx.x;
    const int b = blockIdx.x;
    const float* dp = doc + (size_t)b * T_LEN * DD;
    if (blockIdx.y == 0) {
        float acc = 0.f;
        float* fp = g_Fp + (size_t)(b * TPAD) * DD + d;
        fp[0] = 0.f;
        for (int t0 = 0; t0 < T_LEN; t0 += 32) {
            int n = min(32, T_LEN - t0);
            __syncthreads();
            for (int i = d; i < n * DD; i += DD) tile[i] = dp[(size_t)t0 * DD + i];
            __syncthreads();
            for (int i = 0; i < n; i++) {
                acc = fmaf(ALPHA, acc, tile[i * DD + d]);
                fp[(size_t)(t0 + i + 1) * DD] = acc;
            }
        }
    } else {
        float acc = 0.f;
        float* rp = g_Rp + (size_t)(b * TPAD) * DD + d;
        rp[(size_t)T_LEN * DD] = 0.f;
        for (int hi = T_LEN; hi > 0; hi -= 32) {
            int lo = (hi > 32) ? hi - 32 : 0;
            int n = hi - lo;
            __syncthreads();
            for (int i = d; i < n * DD; i += DD) tile[i] = dp[(size_t)lo * DD + i];
            __syncthreads();
            for (int i = n - 1; i >= 0; i--) {
                acc = fmaf(ALPHA, acc, tile[i * DD + d]);
                rp[(size_t)(lo + i) * DD] = acc;
            }
        }
    }
}

// -------- projections: 128x128 tile, f32x2 accumulators; z==0 folds Pq into PA -----
__global__ void __launch_bounds__(256) k_proj() {
    const int z = blockIdx.z;
    const float* A = (z == 2) ? g_Rp : g_Fp;
    float* P = (z == 0) ? g_PA : (z == 1 ? g_PB : g_PC);
    const int colofs = z * DD;
    const int m0 = blockIdx.x * 128;
    const int n0 = blockIdx.y * 128;
    __shared__ __align__(16) float sA[16 * 132];
    __shared__ __align__(16) float sB[16 * 132];
    const int tid = threadIdx.x;
    const int ty = tid >> 4, tx = tid & 15;
    const int r = tid >> 2, kq = (tid & 3) * 4;

    unsigned long long acc2[8][4];
#pragma unroll
    for (int i = 0; i < 8; i++)
#pragma unroll
        for (int j = 0; j < 4; j++) acc2[i][j] = 0ULL;

    for (int k0 = 0; k0 < DD; k0 += 16) {
        __syncthreads();
#pragma unroll
        for (int h = 0; h < 2; h++) {
            int rr = r + h * 64;
            int m = m0 + rr;
            float4 va = make_float4(0.f, 0.f, 0.f, 0.f);
            if (m < MROWS) va = *(const float4*)&A[(size_t)m * DD + k0 + kq];
            sA[(kq + 0) * 132 + rr] = va.x;
            sA[(kq + 1) * 132 + rr] = va.y;
            sA[(kq + 2) * 132 + rr] = va.z;
            sA[(kq + 3) * 132 + rr] = va.w;
            int n = n0 + rr;
            float4 vb = *(const float4*)&g_W1s[(size_t)n * CIN + colofs + k0 + kq];
            sB[(kq + 0) * 132 + rr] = vb.x;
            sB[(kq + 1) * 132 + rr] = vb.y;
            sB[(kq + 2) * 132 + rr] = vb.z;
            sB[(kq + 3) * 132 + rr] = vb.w;
        }
        __syncthreads();
#pragma unroll
        for (int kk = 0; kk < 16; kk++) {
            float4 a0 = *(const float4*)&sA[kk * 132 + ty * 8];
            float4 a1 = *(const float4*)&sA[kk * 132 + ty * 8 + 4];
            ulonglong2 bq0 = *(const ulonglong2*)&sB[kk * 132 + tx * 8];
            ulonglong2 bq1 = *(const ulonglong2*)&sB[kk * 132 + tx * 8 + 4];
            unsigned long long pa[8] = {pack2(a0.x), pack2(a0.y), pack2(a0.z), pack2(a0.w),
                                        pack2(a1.x), pack2(a1.y), pack2(a1.z), pack2(a1.w)};
#pragma unroll
            for (int i = 0; i < 8; i++) {
                fma2(acc2[i][0], pa[i], bq0.x);
                fma2(acc2[i][1], pa[i], bq0.y);
                fma2(acc2[i][2], pa[i], bq1.x);
                fma2(acc2[i][3], pa[i], bq1.y);
            }
        }
    }
#pragma unroll
    for (int i = 0; i < 8; i++) {
        int m = m0 + ty * 8 + i;
        if (m >= MROWS) continue;
        float2 v0 = unpack2(acc2[i][0]);
        float2 v1 = unpack2(acc2[i][1]);
        float2 v2 = unpack2(acc2[i][2]);
        float2 v3 = unpack2(acc2[i][3]);
        float4 o0 = make_float4(v0.x, v0.y, v1.x, v1.y);
        float4 o1 = make_float4(v2.x, v2.y, v3.x, v3.y);
        if (z == 0) {  // fold Pq into PA
            int bq = (m / TPAD) * H1 + n0 + tx * 8;
            float4 q0 = *(const float4*)&g_Pq[bq];
            float4 q1 = *(const float4*)&g_Pq[bq + 4];
            o0.x += q0.x; o0.y += q0.y; o0.z += q0.z; o0.w += q0.w;
            o1.x += q1.x; o1.y += q1.y; o1.z += q1.z; o1.w += q1.w;
        }
        *(float4*)&P[(size_t)m * H1 + n0 + tx * 8] = o0;
        *(float4*)&P[(size_t)m * H1 + n0 + tx * 8 + 4] = o1;
    }
}

// -------- main: fp16 2-pass mma GEMM2, coalesced warp-per-row A-gen --------
constexpr int SA_STRIDE = 144;                 // 64 fp16 cols -> 128B + 16 pad
constexpr int SB_STRIDE = 528;                 // 256 fp16 cols -> 512B + 16 pad
constexpr uint32_t OFF_AH   = 0;               // 128*144 = 18432
constexpr uint32_t OFF_AL   = 18432;
constexpr uint32_t OFF_BH   = 36864;           // 64*528 = 33792
constexpr uint32_t STAGE_SZ = 70656;
constexpr uint32_t OFF_HDR  = 141312;
constexpr uint32_t OFF_OS   = OFF_HDR;
constexpr uint32_t OFF_OE   = OFF_HDR + 512;
constexpr uint32_t OFF_CF   = OFF_HDR + 1024;
constexpr uint32_t OFF_W3A  = OFF_HDR + 1536;
constexpr uint32_t OFF_W3B  = OFF_HDR + 2560;
constexpr uint32_t OFF_SH2  = OFF_HDR + 3584;
constexpr uint32_t OFF_RED  = OFF_HDR + 4608;  // float[2][128][2]
constexpr uint32_t SMEM_MAIN = OFF_HDR + 6656; // 147968

__global__ void __launch_bounds__(256, 1) k_main(const float* __restrict__ W3) {
    extern __shared__ char sm[];
    const uint32_t sb = smem_u32(sm);
    const int tid = threadIdx.x;
    const int lane = tid & 31;
    const int w = tid >> 5;
    const int mw = w & 3;
    const int nw = w >> 2;
    const int m0 = blockIdx.x * 128;
    const int n0 = blockIdx.y * 256;

    int*   sOS = (int*)(sm + OFF_OS);
    int*   sOE = (int*)(sm + OFF_OE);
    float* sCF = (float*)(sm + OFF_CF);
    float* sW3a = (float*)(sm + OFF_W3A);
    float* sW3b = (float*)(sm + OFF_W3B);
    float* sSh2 = (float*)(sm + OFF_SH2);
    float* sRed = (float*)(sm + OFF_RED);

    if (tid < 128) {
        int m = m0 + tid;
        int offS = 0, offE = 0;
        float cf = 0.f;
        if (m < ROWS) {
            int b = m / NCAND;
            int i = m - b * NCAND;
            int s = g_sidx[i], e = g_eidx[i];
            offS = (b * TPAD + s) * H1;
            offE = (b * TPAD + e + 1) * H1;
            cf = g_coef[e - s];
        }
        sOS[tid] = offS; sOE[tid] = offE; sCF[tid] = cf;
    }
    sW3a[tid] = W3[n0 + tid];
    sW3b[tid] = W3[H2 + n0 + tid];
    sSh2[tid] = g_sh2[n0 + tid];
    __syncthreads();

    // A-gen: warp w owns rows [16w, 16w+16); lane L covers cols [2L, 2L+2)
    const int wrow = w * 16;
    const int myOS = sOS[wrow + (lane & 15)];
    const int myOE = sOE[wrow + (lane & 15)];
    const float myCF = sCF[wrow + (lane & 15)];

    // B cp.async per-thread config
    const int bkr = tid >> 5;
    const int bnc = tid & 31;

    // ldmatrix base (stage-relative)
    const uint32_t aRel = OFF_AH + (uint32_t)((mw * 32 + (lane & 15)) * SA_STRIDE +
                                              ((lane >> 4) * 8) * 2);
    const uint32_t bRel = OFF_BH + (uint32_t)((lane & 15) * SB_STRIDE +
                                              (nw * 128 + (lane >> 4) * 8) * 2);

    float acc[2][16][4];
#pragma unroll
    for (int t = 0; t < 2; t++)
#pragma unroll
        for (int nf = 0; nf < 16; nf++)
#pragma unroll
            for (int c = 0; c < 4; c++) acc[t][nf][c] = 0.f;

    auto stage = [&](int cc) {
        const uint32_t stoff = (uint32_t)(cc & 1) * STAGE_SZ;
        const uint32_t st = sb + stoff;
        // B: global -> smem via cp.async
        const __half* bsrc = &g_W2h16[(size_t)(cc * 64) * H2 + n0];
#pragma unroll
        for (int it = 0; it < 8; it++) {
            int kr = bkr + it * 8;
            cp16(st + OFF_BH + (uint32_t)(kr * SB_STRIDE + bnc * 16),
                 bsrc + (size_t)kr * H2 + bnc * 8);
        }
        cp_commit();
        // A: coalesced per-row gather + relu + fp16 hi/lo split
        const int kc = cc * 64 + 2 * lane;
#pragma unroll
        for (int rr = 0; rr < 16; rr++) {
            int offS = __shfl_sync(0xffffffffu, myOS, rr);
            int offE = __shfl_sync(0xffffffffu, myOE, rr);
            float cf = __shfl_sync(0xffffffffu, myCF, rr);
            float2 a  = *(const float2*)&g_PA[offS + kc];   // PA includes Pq
            float2 bs = *(const float2*)&g_PB[offS + kc];
            float2 be = *(const float2*)&g_PB[offE + kc];
            float2 pc = *(const float2*)&g_PC[offE + kc];
            float v0 = fmaxf(a.x + be.x + pc.x - cf * bs.x, 0.f);
            float v1 = fmaxf(a.y + be.y + pc.y - cf * bs.y, 0.f);
            __half2 h = __floats2half2_rn(v0, v1);
            float2 f = __half22float2(h);
            __half2 l = __floats2half2_rn(v0 - f.x, v1 - f.y);
            uint32_t ad = stoff + (uint32_t)((wrow + rr) * SA_STRIDE + lane * 4);
            *(uint32_t*)(sm + OFF_AH + ad) = h2u(h);
            *(uint32_t*)(sm + OFF_AL + ad) = h2u(l);
        }
    };

    stage(0);

#pragma unroll 1
    for (int c = 0; c < 16; c++) {
        if (c < 15) { stage(c + 1); cp_wait<1>(); }
        else        { cp_wait<0>(); }
        __syncthreads();
        const uint32_t st = sb + (uint32_t)(c & 1) * STAGE_SZ;
#pragma unroll
        for (int s = 0; s < 4; s++) {
            const uint32_t ka = st + aRel + (uint32_t)(s * 32);
            uint32_t ah[2][4], al[2][4];
            ldsm_x4(ah[0], ka);
            ldsm_x4(ah[1], ka + 16 * SA_STRIDE);
            ldsm_x4(al[0], ka + (OFF_AL - OFF_AH));
            ldsm_x4(al[1], ka + (OFF_AL - OFF_AH) + 16 * SA_STRIDE);
            const uint32_t kbq = st + bRel + (uint32_t)(s * 16 * SB_STRIDE);
#pragma unroll
            for (int p = 0; p < 8; p++) {
                uint32_t bq[4];
                ldsm_x4_t(bq, kbq + p * 32);
                mma16816(acc[0][2 * p],     ah[0], bq);
                mma16816(acc[1][2 * p],     ah[1], bq);
                mma16816(acc[0][2 * p + 1], ah[0], bq + 2);
                mma16816(acc[1][2 * p + 1], ah[1], bq + 2);
                mma16816(acc[0][2 * p],     al[0], bq);
                mma16816(acc[1][2 * p],     al[1], bq);
                mma16816(acc[0][2 * p + 1], al[0], bq + 2);
                mma16816(acc[1][2 * p + 1], al[1], bq + 2);
            }
        }
        __syncthreads();
    }

    // ---- epilogue: relu(D + sh2) dot W3 rows, reduce, store partials ----
    float sums[4][2];
#pragma unroll
    for (int q = 0; q < 4; q++) { sums[q][0] = 0.f; sums[q][1] = 0.f; }
#pragma unroll
    for (int t = 0; t < 2; t++) {
#pragma unroll
        for (int nf = 0; nf < 16; nf++) {
            int n = nw * 128 + nf * 8 + (lane & 3) * 2;
            float sh0 = sSh2[n], sh1 = sSh2[n + 1];
            float wa0 = sW3a[n], wa1 = sW3a[n + 1];
            float wb0 = sW3b[n], wb1 = sW3b[n + 1];
            float v0 = fmaxf(acc[t][nf][0] + sh0, 0.f);
            float v1 = fmaxf(acc[t][nf][1] + sh1, 0.f);
            float v2 = fmaxf(acc[t][nf][2] + sh0, 0.f);
            float v3 = fmaxf(acc[t][nf][3] + sh1, 0.f);
            sums[t * 2][0]     = fmaf(v0, wa0, fmaf(v1, wa1, sums[t * 2][0]));
            sums[t * 2][1]     = fmaf(v0, wb0, fmaf(v1, wb1, sums[t * 2][1]));
            sums[t * 2 + 1][0] = fmaf(v2, wa0, fmaf(v3, wa1, sums[t * 2 + 1][0]));
            sums[t * 2 + 1][1] = fmaf(v2, wb0, fmaf(v3, wb1, sums[t * 2 + 1][1]));
        }
    }
#pragma unroll
    for (int q = 0; q < 4; q++) {
#pragma unroll
        for (int o = 0; o < 2; o++) {
            sums[q][o] += __shfl_xor_sync(0xffffffffu, sums[q][o], 1);
            sums[q][o] += __shfl_xor_sync(0xffffffffu, sums[q][o], 2);
        }
    }
    __syncthreads();
    if ((lane & 3) == 0) {
#pragma unroll
        for (int q = 0; q < 4; q++) {
            int rloc = mw * 32 + (q >> 1) * 16 + (q & 1) * 8 + (lane >> 2);
            sRed[nw * 256 + rloc * 2 + 0] = sums[q][0];
            sRed[nw * 256 + rloc * 2 + 1] = sums[q][1];
        }
    }
    __syncthreads();
    {
        int rloc = tid >> 1, o = tid & 1;
        int m = m0 + rloc;
        if (m < ROWS) {
            float v = sRed[rloc * 2 + o] + sRed[256 + rloc * 2 + o];
            g_outp[(size_t)blockIdx.y * (ROWS * 2) + m * 2 + o] = v;
        }
    }
}

__global__ void k_sum(float* __restrict__ out) {
    int i = blockIdx.x * 256 + threadIdx.x;
    if (i < ROWS * 2) out[i] = g_outp[i] + g_outp[ROWS * 2 + i];
}

// ---------------- launch ----------------
extern "C" void kernel_launch(void* const* d_in, const int* in_sizes, int n_in,
                              void* d_out, int out_size) {
    (void)in_sizes; (void)n_in; (void)out_size;
    const float* doc = (const float*)d_in[0];
    const float* qe  = (const float*)d_in[1];
    const float* W1  = (const float*)d_in[2];
    const float* g1  = (const float*)d_in[3];
    const float* b1  = (const float*)d_in[4];
    const float* m1  = (const float*)d_in[5];
    const float* v1  = (const float*)d_in[6];
    const float* W2  = (const float*)d_in[7];
    const float* g2  = (const float*)d_in[8];
    const float* b2  = (const float*)d_in[9];
    const float* m2  = (const float*)d_in[10];
    const float* v2  = (const float*)d_in[11];
    const float* W3  = (const float*)d_in[12];
    float* out = (float*)d_out;

    cudaFuncSetAttribute(k_main, cudaFuncAttributeMaxDynamicSharedMemorySize, SMEM_MAIN);

    k_setup1<<<512, 256>>>(qe, W1, g1, b1, m1, v1, W2, g2, b2, m2, v2);
    k_scan<<<dim3(BB, 2), DD>>>(doc);
    k_pq<<<dim3(H1 / 256, BB), 256>>>(b1, m1, g1, v1);
    k_proj<<<dim3((MROWS + 127) / 128, H1 / 128, 3), 256>>>();
    k_main<<<dim3((ROWS + 127) / 128, 2), 256, SMEM_MAIN>>>(W3);
    k_sum<<<(ROWS * 2 + 255) / 256, 256>>>(out);
}

// round 6
// speedup vs baseline: 3.6160x; 1.3869x over previous
#include <cuda_runtime.h>
#include <cuda_fp16.h>
#include <cstdint>

#define ALPHA 0.9f
constexpr int T_LEN = 809;
constexpr int TPAD  = 810;
constexpr int DD    = 304;   // doc dim; also K of layer-1 projections
constexpr int EE    = 300;
constexpr int LQ    = 30;
constexpr int BB    = 4;
constexpr int MSPAN = 16;
constexpr int H1    = 1024;
constexpr int H2    = 512;
constexpr int CIN   = 1212;
constexpr int NCAND = 12824;
constexpr int ROWS  = BB * NCAND;      // 51296
constexpr int MROWS = BB * TPAD;       // 3240
constexpr float EPS = 1e-5f;

// ---------------- scratch ----------------
__device__ __align__(16) __half g_Fph[MROWS * DD];
__device__ __align__(16) __half g_Fpl[MROWS * DD];
__device__ __align__(16) __half g_Rph[MROWS * DD];
__device__ __align__(16) __half g_Rpl[MROWS * DD];
__device__ __align__(16) __half g_W1h3[3 * DD * H1];   // [z][k][n] scaled hi
__device__ __align__(16) __half g_W1l3[3 * DD * H1];   // [z][k][n] scaled lo
__device__ float g_PA[MROWS * H1];     // includes Pq fold
__device__ float g_PB[MROWS * H1];
__device__ float g_PC[MROWS * H1];
__device__ float g_Pq[BB * H1];
__device__ __align__(16) __half g_W2h16[H1 * H2];  // fp16(W2*sc2), layout [k][n]
__device__ float g_sh2[H2];
__device__ float g_qf[BB * EE];
__device__ float g_coef[MSPAN];
__device__ int   g_sidx[NCAND];
__device__ int   g_eidx[NCAND];
__device__ float g_outp[2 * ROWS * 2];

// ---------------- helpers ----------------
__device__ __forceinline__ uint32_t smem_u32(const void* p) {
    uint32_t a;
    asm("{ .reg .u64 t; cvta.to.shared.u64 t, %1; cvt.u32.u64 %0, t; }" : "=r"(a) : "l"(p));
    return a;
}
__device__ __forceinline__ uint32_t h2u(__half2 h) { return *(uint32_t*)&h; }

__device__ __forceinline__ void ldsm_x4(uint32_t* r, uint32_t a) {
    asm volatile("ldmatrix.sync.aligned.m8n8.x4.shared.b16 {%0,%1,%2,%3}, [%4];"
                 : "=r"(r[0]), "=r"(r[1]), "=r"(r[2]), "=r"(r[3]) : "r"(a));
}
__device__ __forceinline__ void ldsm_x4_t(uint32_t* r, uint32_t a) {
    asm volatile("ldmatrix.sync.aligned.m8n8.x4.trans.shared.b16 {%0,%1,%2,%3}, [%4];"
                 : "=r"(r[0]), "=r"(r[1]), "=r"(r[2]), "=r"(r[3]) : "r"(a));
}
__device__ __forceinline__ void mma16816(float* d, const uint32_t* a, const uint32_t* b) {
    asm volatile(
        "mma.sync.aligned.m16n8k16.row.col.f32.f16.f16.f32 "
        "{%0,%1,%2,%3}, {%4,%5,%6,%7}, {%8,%9}, {%0,%1,%2,%3};"
        : "+f"(d[0]), "+f"(d[1]), "+f"(d[2]), "+f"(d[3])
        : "r"(a[0]), "r"(a[1]), "r"(a[2]), "r"(a[3]), "r"(b[0]), "r"(b[1]));
}
__device__ __forceinline__ void cp16(uint32_t dst, const void* src) {
    asm volatile("cp.async.cg.shared.global [%0], [%1], 16;" :: "r"(dst), "l"(src));
}
__device__ __forceinline__ void cp_commit() { asm volatile("cp.async.commit_group;"); }
template <int N> __device__ __forceinline__ void cp_wait() {
    asm volatile("cp.async.wait_group %0;" :: "n"(N));
}

// ---------------- setup (no W1 pass) ----------------
__global__ void k_setup1(const float* __restrict__ Qe,
                         const float* __restrict__ W2,
                         const float* __restrict__ g2, const float* __restrict__ b2,
                         const float* __restrict__ m2, const float* __restrict__ v2) {
    const long NW2 = (long)H1 * H2;
    const long total = NW2 + H2 + BB * EE + T_LEN + MSPAN;
    for (long idx = (long)blockIdx.x * blockDim.x + threadIdx.x; idx < total;
         idx += (long)gridDim.x * blockDim.x) {
        long i = idx;
        if (i < NW2) {  // layout [k][n]
            int n = (int)(i % H2);
            int k = (int)(i / H2);
            float sc = g2[n] * rsqrtf(v2[n] + EPS);
            g_W2h16[i] = __float2half_rn(W2[(size_t)n * H1 + k] * sc);
            continue;
        }
        i -= NW2;
        if (i < H2) {
            float sc = g2[i] * rsqrtf(v2[i] + EPS);
            g_sh2[i] = b2[i] - m2[i] * sc;
            continue;
        }
        i -= H2;
        if (i < BB * EE) {
            int b = (int)(i / EE), d = (int)(i % EE);
            float acc = 0.f, p = 1.f;
            for (int t = LQ - 1; t >= 0; t--) {
                acc = fmaf(p, Qe[(b * LQ + t) * EE + d], acc);
                p *= ALPHA;
            }
            g_qf[i] = acc;
            continue;
        }
        i -= BB * EE;
        if (i < T_LEN) {
            int s = (int)i;
            int cnt = min(MSPAN, T_LEN - s);
            int ex = (s > 794) ? ((s - 794) * (s - 793)) / 2 : 0;
            int base = 16 * s - ex;
            for (int sp = 0; sp < cnt; sp++) {
                g_sidx[base + sp] = s;
                g_eidx[base + sp] = s + sp;
            }
            continue;
        }
        i -= T_LEN;
        if (i < MSPAN) {
            double c = 1.0;
            for (int k = 0; k <= (int)i; k++) c *= 0.9;
            g_coef[i] = (float)c;
        }
    }
}

// W1 transpose + scale + fp16 split: g_W1{h,l}3[z][k][n] = split(W1[n][z*DD+k] * sc1[n])
__global__ void k_w1t(const float* __restrict__ W1,
                      const float* __restrict__ g1, const float* __restrict__ v1) {
    __shared__ float tl[32][33];
    const int z = blockIdx.z;
    const int k0 = blockIdx.x * 32, n0 = blockIdx.y * 32;
    const int tx = threadIdx.x & 31, ty = threadIdx.x >> 5;
#pragma unroll
    for (int it = 0; it < 4; it++) {
        int n = n0 + ty + it * 8;
        int k = k0 + tx;
        float v = (k < DD) ? W1[(size_t)n * CIN + z * DD + k] : 0.f;
        tl[ty + it * 8][tx] = v;
    }
    __syncthreads();
    const int n = n0 + tx;
    const float sc = g1[n] * rsqrtf(v1[n] + EPS);
#pragma unroll
    for (int it = 0; it < 4; it++) {
        int k = k0 + ty + it * 8;
        if (k >= DD) continue;
        float val = tl[tx][ty + it * 8] * sc;
        __half h = __float2half_rn(val);
        __half l = __float2half_rn(val - __half2float(h));
        size_t o = ((size_t)(z * DD + k)) * H1 + n;
        g_W1h3[o] = h;
        g_W1l3[o] = l;
    }
}

__global__ void k_pq(const float* __restrict__ W1,
                     const float* __restrict__ b1, const float* __restrict__ m1,
                     const float* __restrict__ g1, const float* __restrict__ v1) {
    int j = blockIdx.x * blockDim.x + threadIdx.x;
    int b = blockIdx.y;
    if (j >= H1) return;
    float sc = g1[j] * rsqrtf(v1[j] + EPS);
    const float* w = &W1[(size_t)j * CIN + 3 * DD];
    const float* q = &g_qf[b * EE];
    float dot = 0.f;
    for (int d = 0; d < EE; d++) dot = fmaf(q[d], w[d], dot);
    g_Pq[b * H1 + j] = b1[j] - m1[j] * sc + sc * dot;
}

// ---------------- scans -> fp16 hi/lo directly ----------------
__global__ void k_scan(const float* __restrict__ doc) {
    __shared__ float tile[32 * DD];
    const int d = threadIdx.x;
    const int b = blockIdx.x;
    const float* dp = doc + (size_t)b * T_LEN * DD;
    if (blockIdx.y == 0) {
        float acc = 0.f;
        __half* fh = g_Fph + (size_t)(b * TPAD) * DD + d;
        __half* fl = g_Fpl + (size_t)(b * TPAD) * DD + d;
        fh[0] = __float2half_rn(0.f);
        fl[0] = __float2half_rn(0.f);
        for (int t0 = 0; t0 < T_LEN; t0 += 32) {
            int n = min(32, T_LEN - t0);
            __syncthreads();
            for (int i = d; i < n * DD; i += DD) tile[i] = dp[(size_t)t0 * DD + i];
            __syncthreads();
            for (int i = 0; i < n; i++) {
                acc = fmaf(ALPHA, acc, tile[i * DD + d]);
                __half h = __float2half_rn(acc);
                fh[(size_t)(t0 + i + 1) * DD] = h;
                fl[(size_t)(t0 + i + 1) * DD] = __float2half_rn(acc - __half2float(h));
            }
        }
    } else {
        float acc = 0.f;
        __half* rh = g_Rph + (size_t)(b * TPAD) * DD + d;
        __half* rl = g_Rpl + (size_t)(b * TPAD) * DD + d;
        rh[(size_t)T_LEN * DD] = __float2half_rn(0.f);
        rl[(size_t)T_LEN * DD] = __float2half_rn(0.f);
        for (int hi = T_LEN; hi > 0; hi -= 32) {
            int lo = (hi > 32) ? hi - 32 : 0;
            int n = hi - lo;
            __syncthreads();
            for (int i = d; i < n * DD; i += DD) tile[i] = dp[(size_t)lo * DD + i];
            __syncthreads();
            for (int i = n - 1; i >= 0; i--) {
                acc = fmaf(ALPHA, acc, tile[i * DD + d]);
                __half h = __float2half_rn(acc);
                rh[(size_t)(lo + i) * DD] = h;
                rl[(size_t)(lo + i) * DD] = __float2half_rn(acc - __half2float(h));
            }
        }
    }
}

// ------------ projections via fp16 mma, 3-pass hi/lo (near-exact) ------------
// CTA: M=128, N=128, K=304 in 19 chunks of 16. 8 warps: 4M x 2N, warp 32x64.
constexpr int PJ_SA = 48;                    // 16k*2B + 16 pad
constexpr int PJ_SB = 272;                   // 128n*2B + 16 pad
constexpr uint32_t PJ_AH = 0;                // 128*48   = 6144
constexpr uint32_t PJ_AL = 6144;
constexpr uint32_t PJ_BH = 12288;            // 16*272   = 4352
constexpr uint32_t PJ_BL = 16640;
constexpr uint32_t PJ_STAGE = 20992;
constexpr uint32_t PJ_SMEM = 2 * PJ_STAGE;   // 41984

__global__ void __launch_bounds__(256) k_proj() {
    extern __shared__ char sm[];
    const uint32_t sb = smem_u32(sm);
    const int z = blockIdx.z;
    const int m0 = blockIdx.x * 128;
    const int n0 = blockIdx.y * 128;
    const int tid = threadIdx.x;
    const int lane = tid & 31;
    const int w = tid >> 5;
    const int mw = w & 3;
    const int nw = w >> 2;

    const __half* Ah = (z == 2) ? g_Rph : g_Fph;
    const __half* Al = (z == 2) ? g_Rpl : g_Fpl;
    float* P = (z == 0) ? g_PA : (z == 1 ? g_PB : g_PC);

    // per-thread load mapping
    const int amm = tid >> 1, aseg = tid & 1;          // A: row, 16B seg
    const int am = (m0 + amm < MROWS) ? (m0 + amm) : 0;
    const int bkr = tid >> 4, bns = tid & 15;          // B: k row, 16B seg

    auto stage = [&](int cc) {
        const uint32_t st = sb + (uint32_t)(cc & 1) * PJ_STAGE;
        const int k0 = cc * 16;
        const size_t asrc = ((size_t)am * DD + k0 + aseg * 8);
        cp16(st + PJ_AH + (uint32_t)(amm * PJ_SA + aseg * 16), Ah + asrc);
        cp16(st + PJ_AL + (uint32_t)(amm * PJ_SA + aseg * 16), Al + asrc);
        const size_t bsrc = ((size_t)(z * DD + k0 + bkr)) * H1 + n0 + bns * 8;
        cp16(st + PJ_BH + (uint32_t)(bkr * PJ_SB + bns * 16), g_W1h3 + bsrc);
        cp16(st + PJ_BL + (uint32_t)(bkr * PJ_SB + bns * 16), g_W1l3 + bsrc);
        cp_commit();
    };

    float acc[2][8][4];
#pragma unroll
    for (int i = 0; i < 2; i++)
#pragma unroll
        for (int j = 0; j < 8; j++)
#pragma unroll
            for (int c = 0; c < 4; c++) acc[i][j][c] = 0.f;

    const uint32_t aRel = (uint32_t)((mw * 32 + (lane & 15)) * PJ_SA + (lane >> 4) * 16);
    const uint32_t bRel = (uint32_t)((lane & 15) * PJ_SB + (nw * 64 + (lane >> 4) * 8) * 2);

    stage(0);
#pragma unroll 1
    for (int c = 0; c < 19; c++) {
        if (c < 18) { stage(c + 1); cp_wait<1>(); }
        else        { cp_wait<0>(); }
        __syncthreads();
        const uint32_t st = sb + (uint32_t)(c & 1) * PJ_STAGE;
        uint32_t ah[2][4], al[2][4];
        ldsm_x4(ah[0], st + PJ_AH + aRel);
        ldsm_x4(ah[1], st + PJ_AH + aRel + 16 * PJ_SA);
        ldsm_x4(al[0], st + PJ_AL + aRel);
        ldsm_x4(al[1], st + PJ_AL + aRel + 16 * PJ_SA);
#pragma unroll
        for (int g = 0; g < 4; g++) {
            uint32_t bh[4], bl[4];
            ldsm_x4_t(bh, st + PJ_BH + bRel + g * 32);
            ldsm_x4_t(bl, st + PJ_BL + bRel + g * 32);
#pragma unroll
            for (int m = 0; m < 2; m++) {
                mma16816(acc[m][2 * g],     ah[m], bh);
                mma16816(acc[m][2 * g + 1], ah[m], bh + 2);
                mma16816(acc[m][2 * g],     al[m], bh);
                mma16816(acc[m][2 * g + 1], al[m], bh + 2);
                mma16816(acc[m][2 * g],     ah[m], bl);
                mma16816(acc[m][2 * g + 1], ah[m], bl + 2);
            }
        }
        __syncthreads();
    }

    // epilogue: write P (+Pq fold for z==0)
#pragma unroll
    for (int m = 0; m < 2; m++) {
        int row0 = m0 + mw * 32 + m * 16 + (lane >> 2);
#pragma unroll
        for (int h = 0; h < 2; h++) {
            int row = row0 + h * 8;
            if (row >= MROWS) continue;
            float* pr = &P[(size_t)row * H1 + n0 + nw * 64 + (lane & 3) * 2];
            const float* qr = (z == 0)
                ? &g_Pq[(row / TPAD) * H1 + n0 + nw * 64 + (lane & 3) * 2] : nullptr;
#pragma unroll
            for (int nf = 0; nf < 8; nf++) {
                float2 v = make_float2(acc[m][nf][2 * h], acc[m][nf][2 * h + 1]);
                if (z == 0) {
                    v.x += qr[nf * 8];
                    v.y += qr[nf * 8 + 1];
                }
                *(float2*)&pr[nf * 8] = v;
            }
        }
    }
}

// -------- main: fp16 1-pass mma GEMM2, coalesced warp-per-row A-gen --------
constexpr int SA_STRIDE = 144;
constexpr int SB_STRIDE = 528;
constexpr uint32_t OFF_AH   = 0;               // 128*144 = 18432
constexpr uint32_t OFF_BH   = 18432;           // 64*528  = 33792
constexpr uint32_t STAGE_SZ = 52224;
constexpr uint32_t OFF_HDR  = 104448;
constexpr uint32_t OFF_OS   = OFF_HDR;
constexpr uint32_t OFF_OE   = OFF_HDR + 512;
constexpr uint32_t OFF_CF   = OFF_HDR + 1024;
constexpr uint32_t OFF_W3A  = OFF_HDR + 1536;
constexpr uint32_t OFF_W3B  = OFF_HDR + 2560;
constexpr uint32_t OFF_SH2  = OFF_HDR + 3584;
constexpr uint32_t OFF_RED  = OFF_HDR + 4608;
constexpr uint32_t SMEM_MAIN = OFF_HDR + 6656; // 111104

__global__ void __launch_bounds__(256, 1) k_main(const float* __restrict__ W3) {
    extern __shared__ char sm[];
    const uint32_t sb = smem_u32(sm);
    const int tid = threadIdx.x;
    const int lane = tid & 31;
    const int w = tid >> 5;
    const int mw = w & 3;
    const int nw = w >> 2;
    const int m0 = blockIdx.x * 128;
    const int n0 = blockIdx.y * 256;

    int*   sOS = (int*)(sm + OFF_OS);
    int*   sOE = (int*)(sm + OFF_OE);
    float* sCF = (float*)(sm + OFF_CF);
    float* sW3a = (float*)(sm + OFF_W3A);
    float* sW3b = (float*)(sm + OFF_W3B);
    float* sSh2 = (float*)(sm + OFF_SH2);
    float* sRed = (float*)(sm + OFF_RED);

    if (tid < 128) {
        int m = m0 + tid;
        int offS = 0, offE = 0;
        float cf = 0.f;
        if (m < ROWS) {
            int b = m / NCAND;
            int i = m - b * NCAND;
            int s = g_sidx[i], e = g_eidx[i];
            offS = (b * TPAD + s) * H1;
            offE = (b * TPAD + e + 1) * H1;
            cf = g_coef[e - s];
        }
        sOS[tid] = offS; sOE[tid] = offE; sCF[tid] = cf;
    }
    sW3a[tid] = W3[n0 + tid];
    sW3b[tid] = W3[H2 + n0 + tid];
    sSh2[tid] = g_sh2[n0 + tid];
    __syncthreads();

    const int wrow = w * 16;
    const int myOS = sOS[wrow + (lane & 15)];
    const int myOE = sOE[wrow + (lane & 15)];
    const float myCF = sCF[wrow + (lane & 15)];

    const int bkr = tid >> 5;
    const int bnc = tid & 31;

    const uint32_t aRel = OFF_AH + (uint32_t)((mw * 32 + (lane & 15)) * SA_STRIDE +
                                              ((lane >> 4) * 8) * 2);
    const uint32_t bRel = OFF_BH + (uint32_t)((lane & 15) * SB_STRIDE +
                                              (nw * 128 + (lane >> 4) * 8) * 2);

    float acc[2][16][4];
#pragma unroll
    for (int t = 0; t < 2; t++)
#pragma unroll
        for (int nf = 0; nf < 16; nf++)
#pragma unroll
            for (int c = 0; c < 4; c++) acc[t][nf][c] = 0.f;

    auto stage = [&](int cc) {
        const uint32_t stoff = (uint32_t)(cc & 1) * STAGE_SZ;
        const uint32_t st = sb + stoff;
        const __half* bsrc = &g_W2h16[(size_t)(cc * 64) * H2 + n0];
#pragma unroll
        for (int it = 0; it < 8; it++) {
            int kr = bkr + it * 8;
            cp16(st + OFF_BH + (uint32_t)(kr * SB_STRIDE + bnc * 16),
                 bsrc + (size_t)kr * H2 + bnc * 8);
        }
        cp_commit();
        const int kc = cc * 64 + 2 * lane;
#pragma unroll
        for (int rr = 0; rr < 16; rr++) {
            int offS = __shfl_sync(0xffffffffu, myOS, rr);
            int offE = __shfl_sync(0xffffffffu, myOE, rr);
            float cf = __shfl_sync(0xffffffffu, myCF, rr);
            float2 a  = *(const float2*)&g_PA[offS + kc];
            float2 bs = *(const float2*)&g_PB[offS + kc];
            float2 be = *(const float2*)&g_PB[offE + kc];
            float2 pc = *(const float2*)&g_PC[offE + kc];
            float v0 = fmaxf(a.x + be.x + pc.x - cf * bs.x, 0.f);
            float v1 = fmaxf(a.y + be.y + pc.y - cf * bs.y, 0.f);
            __half2 h = __floats2half2_rn(v0, v1);
            uint32_t ad = stoff + (uint32_t)((wrow + rr) * SA_STRIDE + lane * 4);
            *(uint32_t*)(sm + OFF_AH + ad) = h2u(h);
        }
    };

    stage(0);

#pragma unroll 1
    for (int c = 0; c < 16; c++) {
        if (c < 15) { stage(c + 1); cp_wait<1>(); }
        else        { cp_wait<0>(); }
        __syncthreads();
        const uint32_t st = sb + (uint32_t)(c & 1) * STAGE_SZ;
#pragma unroll
        for (int s = 0; s < 4; s++) {
            const uint32_t ka = st + aRel + (uint32_t)(s * 32);
            uint32_t ah[2][4];
            ldsm_x4(ah[0], ka);
            ldsm_x4(ah[1], ka + 16 * SA_STRIDE);
            const uint32_t kbq = st + bRel + (uint32_t)(s * 16 * SB_STRIDE);
#pragma unroll
            for (int p = 0; p < 8; p++) {
                uint32_t bq[4];
                ldsm_x4_t(bq, kbq + p * 32);
                mma16816(acc[0][2 * p],     ah[0], bq);
                mma16816(acc[1][2 * p],     ah[1], bq);
                mma16816(acc[0][2 * p + 1], ah[0], bq + 2);
                mma16816(acc[1][2 * p + 1], ah[1], bq + 2);
            }
        }
        __syncthreads();
    }

    // ---- epilogue: relu(D + sh2) dot W3 rows, reduce, store partials ----
    float sums[4][2];
#pragma unroll
    for (int q = 0; q < 4; q++) { sums[q][0] = 0.f; sums[q][1] = 0.f; }
#pragma unroll
    for (int t = 0; t < 2; t++) {
#pragma unroll
        for (int nf = 0; nf < 16; nf++) {
            int n = nw * 128 + nf * 8 + (lane & 3) * 2;
            float sh0 = sSh2[n], sh1 = sSh2[n + 1];
            float wa0 = sW3a[n], wa1 = sW3a[n + 1];
            float wb0 = sW3b[n], wb1 = sW3b[n + 1];
            float v0 = fmaxf(acc[t][nf][0] + sh0, 0.f);
            float v1 = fmaxf(acc[t][nf][1] + sh1, 0.f);
            float v2 = fmaxf(acc[t][nf][2] + sh0, 0.f);
            float v3 = fmaxf(acc[t][nf][3] + sh1, 0.f);
            sums[t * 2][0]     = fmaf(v0, wa0, fmaf(v1, wa1, sums[t * 2][0]));
            sums[t * 2][1]     = fmaf(v0, wb0, fmaf(v1, wb1, sums[t * 2][1]));
            sums[t * 2 + 1][0] = fmaf(v2, wa0, fmaf(v3, wa1, sums[t * 2 + 1][0]));
            sums[t * 2 + 1][1] = fmaf(v2, wb0, fmaf(v3, wb1, sums[t * 2 + 1][1]));
        }
    }
#pragma unroll
    for (int q = 0; q < 4; q++) {
#pragma unroll
        for (int o = 0; o < 2; o++) {
            sums[q][o] += __shfl_xor_sync(0xffffffffu, sums[q][o], 1);
            sums[q][o] += __shfl_xor_sync(0xffffffffu, sums[q][o], 2);
        }
    }
    __syncthreads();
    if ((lane & 3) == 0) {
#pragma unroll
        for (int q = 0; q < 4; q++) {
            int rloc = mw * 32 + (q >> 1) * 16 + (q & 1) * 8 + (lane >> 2);
            sRed[nw * 256 + rloc * 2 + 0] = sums[q][0];
            sRed[nw * 256 + rloc * 2 + 1] = sums[q][1];
        }
    }
    __syncthreads();
    {
        int rloc = tid >> 1, o = tid & 1;
        int m = m0 + rloc;
        if (m < ROWS) {
            float v = sRed[rloc * 2 + o] + sRed[256 + rloc * 2 + o];
            g_outp[(size_t)blockIdx.y * (ROWS * 2) + m * 2 + o] = v;
        }
    }
}

__global__ void k_sum(float* __restrict__ out) {
    int i = blockIdx.x * 256 + threadIdx.x;
    if (i < ROWS * 2) out[i] = g_outp[i] + g_outp[ROWS * 2 + i];
}

// ---------------- launch ----------------
extern "C" void kernel_launch(void* const* d_in, const int* in_sizes, int n_in,
                              void* d_out, int out_size) {
    (void)in_sizes; (void)n_in; (void)out_size;
    const float* doc = (const float*)d_in[0];
    const float* qe  = (const float*)d_in[1];
    const float* W1  = (const float*)d_in[2];
    const float* g1  = (const float*)d_in[3];
    const float* b1  = (const float*)d_in[4];
    const float* m1  = (const float*)d_in[5];
    const float* v1  = (const float*)d_in[6];
    const float* W2  = (const float*)d_in[7];
    const float* g2  = (const float*)d_in[8];
    const float* b2  = (const float*)d_in[9];
    const float* m2  = (const float*)d_in[10];
    const float* v2  = (const float*)d_in[11];
    const float* W3  = (const float*)d_in[12];
    float* out = (float*)d_out;

    cudaFuncSetAttribute(k_main, cudaFuncAttributeMaxDynamicSharedMemorySize, SMEM_MAIN);
    cudaFuncSetAttribute(k_proj, cudaFuncAttributeMaxDynamicSharedMemorySize, PJ_SMEM);

    k_setup1<<<512, 256>>>(qe, W2, g2, b2, m2, v2);
    k_w1t<<<dim3((DD + 31) / 32, H1 / 32, 3), 256>>>(W1, g1, v1);
    k_scan<<<dim3(BB, 2), DD>>>(doc);
    k_pq<<<dim3(H1 / 256, BB), 256>>>(W1, b1, m1, g1, v1);
    k_proj<<<dim3((MROWS + 127) / 128, H1 / 128, 3), 256, PJ_SMEM>>>();
    k_main<<<dim3((ROWS + 127) / 128, 2), 256, SMEM_MAIN>>>(W3);
    k_sum<<<(ROWS * 2 + 255) / 256, 256>>>(out);
}

// round 7
// speedup vs baseline: 3.8652x; 1.0689x over previous
#include <cuda_runtime.h>
#include <cuda_fp16.h>
#include <cstdint>

#define ALPHA 0.9f
constexpr int T_LEN = 809;
constexpr int TPAD  = 810;
constexpr int DD    = 304;
constexpr int EE    = 300;
constexpr int LQ    = 30;
constexpr int BB    = 4;
constexpr int MSPAN = 16;
constexpr int H1    = 1024;
constexpr int H2    = 512;
constexpr int CIN   = 1212;
constexpr int NCAND = 12824;
constexpr int ROWS  = BB * NCAND;      // 51296
constexpr int MROWS = BB * TPAD;       // 3240
constexpr float EPS = 1e-5f;

// ---------------- scratch ----------------
__device__ __align__(16) __half g_Fph[MROWS * DD];
__device__ __align__(16) __half g_Fpl[MROWS * DD];
__device__ __align__(16) __half g_Rph[MROWS * DD];
__device__ __align__(16) __half g_Rpl[MROWS * DD];
__device__ __align__(16) __half g_W1h3[3 * DD * H1];
__device__ __align__(16) __half g_W1l3[3 * DD * H1];
__device__ float g_PA[MROWS * H1];     // includes Pq fold
__device__ float g_PB[MROWS * H1];
__device__ float g_PC[MROWS * H1];
__device__ float g_Pq[BB * H1];
__device__ __align__(16) __half g_W2h16[H1 * H2];  // fp16(W2*sc2), [k][n]
__device__ float g_sh2[H2];
__device__ float g_coef[MSPAN];
__device__ int   g_sidx[NCAND];
__device__ int   g_eidx[NCAND];
__device__ float g_outp[2 * ROWS * 2];

// ---------------- helpers ----------------
__device__ __forceinline__ uint32_t smem_u32(const void* p) {
    uint32_t a;
    asm("{ .reg .u64 t; cvta.to.shared.u64 t, %1; cvt.u32.u64 %0, t; }" : "=r"(a) : "l"(p));
    return a;
}
__device__ __forceinline__ uint32_t h2u(__half2 h) { return *(uint32_t*)&h; }

__device__ __forceinline__ void ldsm_x4(uint32_t* r, uint32_t a) {
    asm volatile("ldmatrix.sync.aligned.m8n8.x4.shared.b16 {%0,%1,%2,%3}, [%4];"
                 : "=r"(r[0]), "=r"(r[1]), "=r"(r[2]), "=r"(r[3]) : "r"(a));
}
__device__ __forceinline__ void ldsm_x4_t(uint32_t* r, uint32_t a) {
    asm volatile("ldmatrix.sync.aligned.m8n8.x4.trans.shared.b16 {%0,%1,%2,%3}, [%4];"
                 : "=r"(r[0]), "=r"(r[1]), "=r"(r[2]), "=r"(r[3]) : "r"(a));
}
__device__ __forceinline__ void mma16816(float* d, const uint32_t* a, const uint32_t* b) {
    asm volatile(
        "mma.sync.aligned.m16n8k16.row.col.f32.f16.f16.f32 "
        "{%0,%1,%2,%3}, {%4,%5,%6,%7}, {%8,%9}, {%0,%1,%2,%3};"
        : "+f"(d[0]), "+f"(d[1]), "+f"(d[2]), "+f"(d[3])
        : "r"(a[0]), "r"(a[1]), "r"(a[2]), "r"(a[3]), "r"(b[0]), "r"(b[1]));
}
__device__ __forceinline__ void cp16(uint32_t dst, const void* src) {
    asm volatile("cp.async.cg.shared.global [%0], [%1], 16;" :: "r"(dst), "l"(src));
}
__device__ __forceinline__ void cp_commit() { asm volatile("cp.async.commit_group;"); }
template <int N> __device__ __forceinline__ void cp_wait() {
    asm volatile("cp.async.wait_group %0;" :: "n"(N));
}

// =================== fat prep kernel: all input-only preprocessing ==============
constexpr int PREP_W2   = 512;   // 32 k-tiles x 16 n-tiles
constexpr int PREP_W1   = 960;   // 3 z x 10 k-tiles x 32 n-tiles
constexpr int PREP_SCAN = 8;     // 4 batches x 2 directions
constexpr int PREP_PQ   = 512;   // x 8 warps = 4096 (b,j) jobs
constexpr int PREP_MISC = 64;
constexpr int PREP_GRID = PREP_W2 + PREP_W1 + PREP_SCAN + PREP_PQ + PREP_MISC;

__global__ void __launch_bounds__(256) k_prep(
    const float* __restrict__ doc, const float* __restrict__ Qe,
    const float* __restrict__ W1,
    const float* __restrict__ g1, const float* __restrict__ b1,
    const float* __restrict__ m1, const float* __restrict__ v1,
    const float* __restrict__ W2,
    const float* __restrict__ g2, const float* __restrict__ b2,
    const float* __restrict__ m2, const float* __restrict__ v2) {
    __shared__ float sh[32 * DD];          // 38 KB, reused per role
    int bx = blockIdx.x;
    const int tid = threadIdx.x;

    if (bx < PREP_W2) {
        // W2*sc2 -> fp16 [k][n], smem 32x32 transpose
        float (*tl)[33] = (float(*)[33])sh;
        const int kt = bx & 31, nt = bx >> 5;
        const int k0 = kt * 32, n0 = nt * 32;
        const int tx = tid & 31, ty = tid >> 5;
#pragma unroll
        for (int it = 0; it < 4; it++)
            tl[ty + it * 8][tx] = W2[(size_t)(n0 + ty + it * 8) * H1 + k0 + tx];
        __syncthreads();
        const int n = n0 + tx;
        const float sc = g2[n] * rsqrtf(v2[n] + EPS);
#pragma unroll
        for (int it = 0; it < 4; it++) {
            int k = k0 + ty + it * 8;
            g_W2h16[(size_t)k * H2 + n] = __float2half_rn(tl[tx][ty + it * 8] * sc);
        }
        return;
    }
    bx -= PREP_W2;
    if (bx < PREP_W1) {
        // W1*sc1 -> fp16 hi/lo [z][k][n], smem 32x32 transpose
        float (*tl)[33] = (float(*)[33])sh;
        const int z = bx / 320;
        const int r = bx - z * 320;
        const int kt = r % 10, nt = r / 10;
        const int k0 = kt * 32, n0 = nt * 32;
        const int tx = tid & 31, ty = tid >> 5;
#pragma unroll
        for (int it = 0; it < 4; it++) {
            int n = n0 + ty + it * 8;
            int k = k0 + tx;
            tl[ty + it * 8][tx] = (k < DD) ? W1[(size_t)n * CIN + z * DD + k] : 0.f;
        }
        __syncthreads();
        const int n = n0 + tx;
        const float sc = g1[n] * rsqrtf(v1[n] + EPS);
#pragma unroll
        for (int it = 0; it < 4; it++) {
            int k = k0 + ty + it * 8;
            if (k >= DD) continue;
            float val = tl[tx][ty + it * 8] * sc;
            __half h = __float2half_rn(val);
            __half l = __float2half_rn(val - __half2float(h));
            size_t o = ((size_t)(z * DD + k)) * H1 + n;
            g_W1h3[o] = h;
            g_W1l3[o] = l;
        }
        return;
    }
    bx -= PREP_W1;
    if (bx < PREP_SCAN) {
        const int b = bx >> 1;
        const float* dp = doc + (size_t)b * T_LEN * DD;
        const int d0 = tid, d1 = tid + 256;
        const bool has1 = (d1 < DD);
        if ((bx & 1) == 0) {
            float a0 = 0.f, a1 = 0.f;
            __half* fh = g_Fph + (size_t)(b * TPAD) * DD;
            __half* fl = g_Fpl + (size_t)(b * TPAD) * DD;
            for (int d = tid; d < DD; d += 256) {
                fh[d] = __float2half_rn(0.f);
                fl[d] = __float2half_rn(0.f);
            }
            for (int t0 = 0; t0 < T_LEN; t0 += 32) {
                int n = min(32, T_LEN - t0);
                __syncthreads();
                for (int i = tid; i < n * DD; i += 256) sh[i] = dp[(size_t)t0 * DD + i];
                __syncthreads();
                for (int i = 0; i < n; i++) {
                    size_t ro = (size_t)(t0 + i + 1) * DD;
                    a0 = fmaf(ALPHA, a0, sh[i * DD + d0]);
                    __half h0 = __float2half_rn(a0);
                    fh[ro + d0] = h0;
                    fl[ro + d0] = __float2half_rn(a0 - __half2float(h0));
                    if (has1) {
                        a1 = fmaf(ALPHA, a1, sh[i * DD + d1]);
                        __half h1v = __float2half_rn(a1);
                        fh[ro + d1] = h1v;
                        fl[ro + d1] = __float2half_rn(a1 - __half2float(h1v));
                    }
                }
            }
        } else {
            float a0 = 0.f, a1 = 0.f;
            __half* rh = g_Rph + (size_t)(b * TPAD) * DD;
            __half* rl = g_Rpl + (size_t)(b * TPAD) * DD;
            for (int d = tid; d < DD; d += 256) {
                rh[(size_t)T_LEN * DD + d] = __float2half_rn(0.f);
                rl[(size_t)T_LEN * DD + d] = __float2half_rn(0.f);
            }
            for (int hi = T_LEN; hi > 0; hi -= 32) {
                int lo = (hi > 32) ? hi - 32 : 0;
                int n = hi - lo;
                __syncthreads();
                for (int i = tid; i < n * DD; i += 256) sh[i] = dp[(size_t)lo * DD + i];
                __syncthreads();
                for (int i = n - 1; i >= 0; i--) {
                    size_t ro = (size_t)(lo + i) * DD;
                    a0 = fmaf(ALPHA, a0, sh[i * DD + d0]);
                    __half h0 = __float2half_rn(a0);
                    rh[ro + d0] = h0;
                    rl[ro + d0] = __float2half_rn(a0 - __half2float(h0));
                    if (has1) {
                        a1 = fmaf(ALPHA, a1, sh[i * DD + d1]);
                        __half h1v = __float2half_rn(a1);
                        rh[ro + d1] = h1v;
                        rl[ro + d1] = __float2half_rn(a1 - __half2float(h1v));
                    }
                }
            }
        }
        return;
    }
    bx -= PREP_SCAN;
    if (bx < PREP_PQ) {
        // warp per (b, j): Pq[b,j] = sh1[j] + sc1[j] * (qf[b] . W1q[j])
        const int lane = tid & 31;
        const int gw = bx * 8 + (tid >> 5);
        const int j = gw & (H1 - 1);
        const int b = gw >> 10;
        const float sc = g1[j] * rsqrtf(v1[j] + EPS);
        const float* wrow = &W1[(size_t)j * CIN + 3 * DD];
        float dot = 0.f;
        for (int d = lane; d < EE; d += 32) {
            float qv = 0.f, p = 1.f;
#pragma unroll
            for (int t = LQ - 1; t >= 0; t--) {
                qv = fmaf(p, Qe[(b * LQ + t) * EE + d], qv);
                p *= ALPHA;
            }
            dot = fmaf(qv, wrow[d], dot);
        }
#pragma unroll
        for (int o = 16; o > 0; o >>= 1) dot += __shfl_xor_sync(0xffffffffu, dot, o);
        if (lane == 0) g_Pq[b * H1 + j] = b1[j] - m1[j] * sc + sc * dot;
        return;
    }
    bx -= PREP_PQ;
    {
        const long total = H2 + T_LEN + MSPAN;
        for (long idx = (long)bx * 256 + tid; idx < total; idx += (long)PREP_MISC * 256) {
            long i = idx;
            if (i < H2) {
                float sc = g2[i] * rsqrtf(v2[i] + EPS);
                g_sh2[i] = b2[i] - m2[i] * sc;
                continue;
            }
            i -= H2;
            if (i < T_LEN) {
                int s = (int)i;
                int cnt = min(MSPAN, T_LEN - s);
                int ex = (s > 794) ? ((s - 794) * (s - 793)) / 2 : 0;
                int base = 16 * s - ex;
                for (int sp = 0; sp < cnt; sp++) {
                    g_sidx[base + sp] = s;
                    g_eidx[base + sp] = s + sp;
                }
                continue;
            }
            i -= T_LEN;
            if (i < MSPAN) {
                double c = 1.0;
                for (int k = 0; k <= (int)i; k++) c *= 0.9;
                g_coef[i] = (float)c;
            }
        }
    }
}

// ------------ projections via fp16 mma, 3-pass hi/lo (near-exact) ------------
constexpr int PJ_SA = 48;
constexpr int PJ_SB = 272;
constexpr uint32_t PJ_AH = 0;
constexpr uint32_t PJ_AL = 6144;
constexpr uint32_t PJ_BH = 12288;
constexpr uint32_t PJ_BL = 16640;
constexpr uint32_t PJ_STAGE = 20992;
constexpr uint32_t PJ_SMEM = 2 * PJ_STAGE;

__global__ void __launch_bounds__(256) k_proj() {
    extern __shared__ char sm[];
    const uint32_t sb = smem_u32(sm);
    const int z = blockIdx.z;
    const int m0 = blockIdx.x * 128;
    const int n0 = blockIdx.y * 128;
    const int tid = threadIdx.x;
    const int lane = tid & 31;
    const int w = tid >> 5;
    const int mw = w & 3;
    const int nw = w >> 2;

    const __half* Ah = (z == 2) ? g_Rph : g_Fph;
    const __half* Al = (z == 2) ? g_Rpl : g_Fpl;
    float* P = (z == 0) ? g_PA : (z == 1 ? g_PB : g_PC);

    const int amm = tid >> 1, aseg = tid & 1;
    const int am = (m0 + amm < MROWS) ? (m0 + amm) : 0;
    const int bkr = tid >> 4, bns = tid & 15;

    auto stage = [&](int cc) {
        const uint32_t st = sb + (uint32_t)(cc & 1) * PJ_STAGE;
        const int k0 = cc * 16;
        const size_t asrc = ((size_t)am * DD + k0 + aseg * 8);
        cp16(st + PJ_AH + (uint32_t)(amm * PJ_SA + aseg * 16), Ah + asrc);
        cp16(st + PJ_AL + (uint32_t)(amm * PJ_SA + aseg * 16), Al + asrc);
        const size_t bsrc = ((size_t)(z * DD + k0 + bkr)) * H1 + n0 + bns * 8;
        cp16(st + PJ_BH + (uint32_t)(bkr * PJ_SB + bns * 16), g_W1h3 + bsrc);
        cp16(st + PJ_BL + (uint32_t)(bkr * PJ_SB + bns * 16), g_W1l3 + bsrc);
        cp_commit();
    };

    float acc[2][8][4];
#pragma unroll
    for (int i = 0; i < 2; i++)
#pragma unroll
        for (int j = 0; j < 8; j++)
#pragma unroll
            for (int c = 0; c < 4; c++) acc[i][j][c] = 0.f;

    const uint32_t aRel = (uint32_t)((mw * 32 + (lane & 15)) * PJ_SA + (lane >> 4) * 16);
    const uint32_t bRel = (uint32_t)((lane & 15) * PJ_SB + (nw * 64 + (lane >> 4) * 8) * 2);

    stage(0);
#pragma unroll 1
    for (int c = 0; c < 19; c++) {
        if (c < 18) { stage(c + 1); cp_wait<1>(); }
        else        { cp_wait<0>(); }
        __syncthreads();
        const uint32_t st = sb + (uint32_t)(c & 1) * PJ_STAGE;
        uint32_t ah[2][4], al[2][4];
        ldsm_x4(ah[0], st + PJ_AH + aRel);
        ldsm_x4(ah[1], st + PJ_AH + aRel + 16 * PJ_SA);
        ldsm_x4(al[0], st + PJ_AL + aRel);
        ldsm_x4(al[1], st + PJ_AL + aRel + 16 * PJ_SA);
#pragma unroll
        for (int g = 0; g < 4; g++) {
            uint32_t bh[4], bl[4];
            ldsm_x4_t(bh, st + PJ_BH + bRel + g * 32);
            ldsm_x4_t(bl, st + PJ_BL + bRel + g * 32);
#pragma unroll
            for (int m = 0; m < 2; m++) {
                mma16816(acc[m][2 * g],     ah[m], bh);
                mma16816(acc[m][2 * g + 1], ah[m], bh + 2);
                mma16816(acc[m][2 * g],     al[m], bh);
                mma16816(acc[m][2 * g + 1], al[m], bh + 2);
                mma16816(acc[m][2 * g],     ah[m], bl);
                mma16816(acc[m][2 * g + 1], ah[m], bl + 2);
            }
        }
        __syncthreads();
    }

#pragma unroll
    for (int m = 0; m < 2; m++) {
        int row0 = m0 + mw * 32 + m * 16 + (lane >> 2);
#pragma unroll
        for (int h = 0; h < 2; h++) {
            int row = row0 + h * 8;
            if (row >= MROWS) continue;
            float* pr = &P[(size_t)row * H1 + n0 + nw * 64 + (lane & 3) * 2];
            const float* qr = (z == 0)
                ? &g_Pq[(row / TPAD) * H1 + n0 + nw * 64 + (lane & 3) * 2] : nullptr;
#pragma unroll
            for (int nf = 0; nf < 8; nf++) {
                float2 v = make_float2(acc[m][nf][2 * h], acc[m][nf][2 * h + 1]);
                if (z == 0) {
                    v.x += qr[nf * 8];
                    v.y += qr[nf * 8 + 1];
                }
                *(float2*)&pr[nf * 8] = v;
            }
        }
    }
}

// -------- main: fp16 1-pass mma GEMM2, batch-aligned blocks, uniform-s A-gen -----
constexpr int SA_STRIDE = 144;
constexpr int SB_STRIDE = 528;
constexpr uint32_t OFF_AH   = 0;
constexpr uint32_t OFF_BH   = 18432;
constexpr uint32_t STAGE_SZ = 52224;
constexpr uint32_t OFF_HDR  = 104448;
constexpr uint32_t OFF_OS   = OFF_HDR;
constexpr uint32_t OFF_OE   = OFF_HDR + 512;
constexpr uint32_t OFF_CF   = OFF_HDR + 1024;
constexpr uint32_t OFF_W3A  = OFF_HDR + 1536;
constexpr uint32_t OFF_W3B  = OFF_HDR + 2560;
constexpr uint32_t OFF_SH2  = OFF_HDR + 3584;
constexpr uint32_t OFF_RED  = OFF_HDR + 4608;
constexpr uint32_t SMEM_MAIN = OFF_HDR + 6656;

__global__ void __launch_bounds__(256, 1) k_main(const float* __restrict__ W3) {
    extern __shared__ char sm[];
    const uint32_t sb = smem_u32(sm);
    const int tid = threadIdx.x;
    const int lane = tid & 31;
    const int w = tid >> 5;
    const int mw = w & 3;
    const int nw = w >> 2;
    const int batch = blockIdx.y;
    const int c0i = blockIdx.x * 128;          // candidate base within batch
    const int n0 = blockIdx.z * 256;

    int*   sOS = (int*)(sm + OFF_OS);
    int*   sOE = (int*)(sm + OFF_OE);
    float* sCF = (float*)(sm + OFF_CF);
    float* sW3a = (float*)(sm + OFF_W3A);
    float* sW3b = (float*)(sm + OFF_W3B);
    float* sSh2 = (float*)(sm + OFF_SH2);
    float* sRed = (float*)(sm + OFF_RED);

    if (tid < 128) {
        int ci = c0i + tid;
        int offS = 0, offE = 0;
        float cf = 0.f;
        if (ci < NCAND) {
            int s = g_sidx[ci], e = g_eidx[ci];
            offS = (batch * TPAD + s) * H1;
            offE = (batch * TPAD + e + 1) * H1;
            cf = g_coef[e - s];
        }
        sOS[tid] = offS; sOE[tid] = offE; sCF[tid] = cf;
    }
    sW3a[tid] = W3[n0 + tid];
    sW3b[tid] = W3[H2 + n0 + tid];
    sSh2[tid] = g_sh2[n0 + tid];
    __syncthreads();

    const int wrow = w * 16;
    const int myOS = sOS[wrow + (lane & 15)];
    const int myOE = sOE[wrow + (lane & 15)];
    const float myCF = sCF[wrow + (lane & 15)];
    const bool uni = (__shfl_sync(0xffffffffu, myOS, 0) ==
                      __shfl_sync(0xffffffffu, myOS, 15));

    const int bkr = tid >> 5;
    const int bnc = tid & 31;

    const uint32_t aRel = OFF_AH + (uint32_t)((mw * 32 + (lane & 15)) * SA_STRIDE +
                                              ((lane >> 4) * 8) * 2);
    const uint32_t bRel = OFF_BH + (uint32_t)((lane & 15) * SB_STRIDE +
                                              (nw * 128 + (lane >> 4) * 8) * 2);

    float acc[2][16][4];
#pragma unroll
    for (int t = 0; t < 2; t++)
#pragma unroll
        for (int nf = 0; nf < 16; nf++)
#pragma unroll
            for (int c = 0; c < 4; c++) acc[t][nf][c] = 0.f;

    auto stage = [&](int cc) {
        const uint32_t stoff = (uint32_t)(cc & 1) * STAGE_SZ;
        const uint32_t st = sb + stoff;
        const __half* bsrc = &g_W2h16[(size_t)(cc * 64) * H2 + n0];
#pragma unroll
        for (int it = 0; it < 8; it++) {
            int kr = bkr + it * 8;
            cp16(st + OFF_BH + (uint32_t)(kr * SB_STRIDE + bnc * 16),
                 bsrc + (size_t)kr * H2 + bnc * 8);
        }
        cp_commit();
        const int kc = cc * 64 + 2 * lane;
        if (uni) {
            const int offS = __shfl_sync(0xffffffffu, myOS, 0);
            const float2 a  = *(const float2*)&g_PA[offS + kc];
            const float2 bs = *(const float2*)&g_PB[offS + kc];
#pragma unroll
            for (int rr = 0; rr < 16; rr++) {
                int offE = __shfl_sync(0xffffffffu, myOE, rr);
                float cf = __shfl_sync(0xffffffffu, myCF, rr);
                float2 be = *(const float2*)&g_PB[offE + kc];
                float2 pc = *(const float2*)&g_PC[offE + kc];
                float v0 = fmaxf(a.x + be.x + pc.x - cf * bs.x, 0.f);
                float v1 = fmaxf(a.y + be.y + pc.y - cf * bs.y, 0.f);
                __half2 h = __floats2half2_rn(v0, v1);
                uint32_t ad = stoff + (uint32_t)((wrow + rr) * SA_STRIDE + lane * 4);
                *(uint32_t*)(sm + OFF_AH + ad) = h2u(h);
            }
        } else {
#pragma unroll
            for (int rr = 0; rr < 16; rr++) {
                int offS = __shfl_sync(0xffffffffu, myOS, rr);
                int offE = __shfl_sync(0xffffffffu, myOE, rr);
                float cf = __shfl_sync(0xffffffffu, myCF, rr);
                float2 a  = *(const float2*)&g_PA[offS + kc];
                float2 bs = *(const float2*)&g_PB[offS + kc];
                float2 be = *(const float2*)&g_PB[offE + kc];
                float2 pc = *(const float2*)&g_PC[offE + kc];
                float v0 = fmaxf(a.x + be.x + pc.x - cf * bs.x, 0.f);
                float v1 = fmaxf(a.y + be.y + pc.y - cf * bs.y, 0.f);
                __half2 h = __floats2half2_rn(v0, v1);
                uint32_t ad = stoff + (uint32_t)((wrow + rr) * SA_STRIDE + lane * 4);
                *(uint32_t*)(sm + OFF_AH + ad) = h2u(h);
            }
        }
    };

    stage(0);

#pragma unroll 1
    for (int c = 0; c < 16; c++) {
        if (c < 15) { stage(c + 1); cp_wait<1>(); }
        else        { cp_wait<0>(); }
        __syncthreads();
        const uint32_t st = sb + (uint32_t)(c & 1) * STAGE_SZ;
#pragma unroll
        for (int s = 0; s < 4; s++) {
            const uint32_t ka = st + aRel + (uint32_t)(s * 32);
            uint32_t ah[2][4];
            ldsm_x4(ah[0], ka);
            ldsm_x4(ah[1], ka + 16 * SA_STRIDE);
            const uint32_t kbq = st + bRel + (uint32_t)(s * 16 * SB_STRIDE);
#pragma unroll
            for (int p = 0; p < 8; p++) {
                uint32_t bq[4];
                ldsm_x4_t(bq, kbq + p * 32);
                mma16816(acc[0][2 * p],     ah[0], bq);
                mma16816(acc[1][2 * p],     ah[1], bq);
                mma16816(acc[0][2 * p + 1], ah[0], bq + 2);
                mma16816(acc[1][2 * p + 1], ah[1], bq + 2);
            }
        }
        __syncthreads();
    }

    // ---- epilogue: relu(D + sh2) dot W3 rows, reduce, store partials ----
    float sums[4][2];
#pragma unroll
    for (int q = 0; q < 4; q++) { sums[q][0] = 0.f; sums[q][1] = 0.f; }
#pragma unroll
    for (int t = 0; t < 2; t++) {
#pragma unroll
        for (int nf = 0; nf < 16; nf++) {
            int n = nw * 128 + nf * 8 + (lane & 3) * 2;
            float sh0 = sSh2[n], sh1 = sSh2[n + 1];
            float wa0 = sW3a[n], wa1 = sW3a[n + 1];
            float wb0 = sW3b[n], wb1 = sW3b[n + 1];
            float v0 = fmaxf(acc[t][nf][0] + sh0, 0.f);
            float v1 = fmaxf(acc[t][nf][1] + sh1, 0.f);
            float v2 = fmaxf(acc[t][nf][2] + sh0, 0.f);
            float v3 = fmaxf(acc[t][nf][3] + sh1, 0.f);
            sums[t * 2][0]     = fmaf(v0, wa0, fmaf(v1, wa1, sums[t * 2][0]));
            sums[t * 2][1]     = fmaf(v0, wb0, fmaf(v1, wb1, sums[t * 2][1]));
            sums[t * 2 + 1][0] = fmaf(v2, wa0, fmaf(v3, wa1, sums[t * 2 + 1][0]));
            sums[t * 2 + 1][1] = fmaf(v2, wb0, fmaf(v3, wb1, sums[t * 2 + 1][1]));
        }
    }
#pragma unroll
    for (int q = 0; q < 4; q++) {
#pragma unroll
        for (int o = 0; o < 2; o++) {
            sums[q][o] += __shfl_xor_sync(0xffffffffu, sums[q][o], 1);
            sums[q][o] += __shfl_xor_sync(0xffffffffu, sums[q][o], 2);
        }
    }
    __syncthreads();
    if ((lane & 3) == 0) {
#pragma unroll
        for (int q = 0; q < 4; q++) {
            int rloc = mw * 32 + (q >> 1) * 16 + (q & 1) * 8 + (lane >> 2);
            sRed[nw * 256 + rloc * 2 + 0] = sums[q][0];
            sRed[nw * 256 + rloc * 2 + 1] = sums[q][1];
        }
    }
    __syncthreads();
    {
        int rloc = tid >> 1, o = tid & 1;
        int ci = c0i + rloc;
        if (ci < NCAND) {
            float v = sRed[rloc * 2 + o] + sRed[256 + rloc * 2 + o];
            g_outp[(size_t)blockIdx.z * (ROWS * 2) + (size_t)(batch * NCAND + ci) * 2 + o] = v;
        }
    }
}

__global__ void k_sum(float* __restrict__ out) {
    int i = blockIdx.x * 256 + threadIdx.x;
    if (i < ROWS * 2) out[i] = g_outp[i] + g_outp[ROWS * 2 + i];
}

// ---------------- launch ----------------
extern "C" void kernel_launch(void* const* d_in, const int* in_sizes, int n_in,
                              void* d_out, int out_size) {
    (void)in_sizes; (void)n_in; (void)out_size;
    const float* doc = (const float*)d_in[0];
    const float* qe  = (const float*)d_in[1];
    const float* W1  = (const float*)d_in[2];
    const float* g1  = (const float*)d_in[3];
    const float* b1  = (const float*)d_in[4];
    const float* m1  = (const float*)d_in[5];
    const float* v1  = (const float*)d_in[6];
    const float* W2  = (const float*)d_in[7];
    const float* g2  = (const float*)d_in[8];
    const float* b2  = (const float*)d_in[9];
    const float* m2  = (const float*)d_in[10];
    const float* v2  = (const float*)d_in[11];
    const float* W3  = (const float*)d_in[12];
    float* out = (float*)d_out;

    cudaFuncSetAttribute(k_main, cudaFuncAttributeMaxDynamicSharedMemorySize, SMEM_MAIN);
    cudaFuncSetAttribute(k_proj, cudaFuncAttributeMaxDynamicSharedMemorySize, PJ_SMEM);

    k_prep<<<PREP_GRID, 256>>>(doc, qe, W1, g1, b1, m1, v1, W2, g2, b2, m2, v2);
    k_proj<<<dim3((MROWS + 127) / 128, H1 / 128, 3), 256, PJ_SMEM>>>();
    k_main<<<dim3((NCAND + 127) / 128, BB, 2), 256, SMEM_MAIN>>>(W3);
    k_sum<<<(ROWS * 2 + 255) / 256, 256>>>(out);
}

// round 8
// speedup vs baseline: 3.9664x; 1.0262x over previous
#include <cuda_runtime.h>
#include <cuda_fp16.h>
#include <cstdint>

#define ALPHA 0.9f
constexpr int T_LEN = 809;
constexpr int TPAD  = 810;
constexpr int DD    = 304;
constexpr int EE    = 300;
constexpr int LQ    = 30;
constexpr int BB    = 4;
constexpr int MSPAN = 16;
constexpr int H1    = 1024;
constexpr int H2    = 512;
constexpr int CIN   = 1212;
constexpr int NCAND = 12824;
constexpr int ROWS  = BB * NCAND;      // 51296
constexpr int MROWS = BB * TPAD;       // 3240
constexpr float EPS = 1e-5f;

// ---------------- scratch ----------------
__device__ __align__(16) __half g_Fph[MROWS * DD];
__device__ __align__(16) __half g_Fpl[MROWS * DD];
__device__ __align__(16) __half g_Rph[MROWS * DD];
__device__ __align__(16) __half g_Rpl[MROWS * DD];
__device__ __align__(16) __half g_W1h3[3 * DD * H1];
__device__ __align__(16) __half g_W1l3[3 * DD * H1];
__device__ float g_PA[MROWS * H1];     // includes Pq fold
__device__ float g_PB[MROWS * H1];
__device__ float g_PC[MROWS * H1];
__device__ float g_Pq[BB * H1];
__device__ __align__(16) __half g_W2h16[H1 * H2];  // fp16(W2*sc2), [k][n]
__device__ float g_sh2[H2];
__device__ float g_coef[MSPAN];
__device__ int   g_sidx[NCAND];
__device__ int   g_eidx[NCAND];
__device__ float g_outp[2 * ROWS * 2];

// ---------------- helpers ----------------
__device__ __forceinline__ uint32_t smem_u32(const void* p) {
    uint32_t a;
    asm("{ .reg .u64 t; cvta.to.shared.u64 t, %1; cvt.u32.u64 %0, t; }" : "=r"(a) : "l"(p));
    return a;
}
__device__ __forceinline__ uint32_t h2u(__half2 h) { return *(uint32_t*)&h; }

__device__ __forceinline__ void ldsm_x4(uint32_t* r, uint32_t a) {
    asm volatile("ldmatrix.sync.aligned.m8n8.x4.shared.b16 {%0,%1,%2,%3}, [%4];"
                 : "=r"(r[0]), "=r"(r[1]), "=r"(r[2]), "=r"(r[3]) : "r"(a));
}
__device__ __forceinline__ void ldsm_x4_t(uint32_t* r, uint32_t a) {
    asm volatile("ldmatrix.sync.aligned.m8n8.x4.trans.shared.b16 {%0,%1,%2,%3}, [%4];"
                 : "=r"(r[0]), "=r"(r[1]), "=r"(r[2]), "=r"(r[3]) : "r"(a));
}
__device__ __forceinline__ void mma16816(float* d, const uint32_t* a, const uint32_t* b) {
    asm volatile(
        "mma.sync.aligned.m16n8k16.row.col.f32.f16.f16.f32 "
        "{%0,%1,%2,%3}, {%4,%5,%6,%7}, {%8,%9}, {%0,%1,%2,%3};"
        : "+f"(d[0]), "+f"(d[1]), "+f"(d[2]), "+f"(d[3])
        : "r"(a[0]), "r"(a[1]), "r"(a[2]), "r"(a[3]), "r"(b[0]), "r"(b[1]));
}
__device__ __forceinline__ void cp16(uint32_t dst, const void* src) {
    asm volatile("cp.async.cg.shared.global [%0], [%1], 16;" :: "r"(dst), "l"(src));
}
__device__ __forceinline__ void cp_commit() { asm volatile("cp.async.commit_group;"); }
template <int N> __device__ __forceinline__ void cp_wait() {
    asm volatile("cp.async.wait_group %0;" :: "n"(N));
}

// =================== fat prep kernel: all input-only preprocessing ==============
constexpr int PREP_W2   = 512;
constexpr int PREP_W1   = 960;
constexpr int PREP_SCAN = 8;
constexpr int PREP_PQ   = 512;
constexpr int PREP_MISC = 64;
constexpr int PREP_GRID = PREP_W2 + PREP_W1 + PREP_SCAN + PREP_PQ + PREP_MISC;

__global__ void __launch_bounds__(256) k_prep(
    const float* __restrict__ doc, const float* __restrict__ Qe,
    const float* __restrict__ W1,
    const float* __restrict__ g1, const float* __restrict__ b1,
    const float* __restrict__ m1, const float* __restrict__ v1,
    const float* __restrict__ W2,
    const float* __restrict__ g2, const float* __restrict__ b2,
    const float* __restrict__ m2, const float* __restrict__ v2) {
    __shared__ float sh[32 * DD];
    int bx = blockIdx.x;
    const int tid = threadIdx.x;

    if (bx < PREP_W2) {
        float (*tl)[33] = (float(*)[33])sh;
        const int kt = bx & 31, nt = bx >> 5;
        const int k0 = kt * 32, n0 = nt * 32;
        const int tx = tid & 31, ty = tid >> 5;
#pragma unroll
        for (int it = 0; it < 4; it++)
            tl[ty + it * 8][tx] = W2[(size_t)(n0 + ty + it * 8) * H1 + k0 + tx];
        __syncthreads();
        const int n = n0 + tx;
        const float sc = g2[n] * rsqrtf(v2[n] + EPS);
#pragma unroll
        for (int it = 0; it < 4; it++) {
            int k = k0 + ty + it * 8;
            g_W2h16[(size_t)k * H2 + n] = __float2half_rn(tl[tx][ty + it * 8] * sc);
        }
        return;
    }
    bx -= PREP_W2;
    if (bx < PREP_W1) {
        float (*tl)[33] = (float(*)[33])sh;
        const int z = bx / 320;
        const int r = bx - z * 320;
        const int kt = r % 10, nt = r / 10;
        const int k0 = kt * 32, n0 = nt * 32;
        const int tx = tid & 31, ty = tid >> 5;
#pragma unroll
        for (int it = 0; it < 4; it++) {
            int n = n0 + ty + it * 8;
            int k = k0 + tx;
            tl[ty + it * 8][tx] = (k < DD) ? W1[(size_t)n * CIN + z * DD + k] : 0.f;
        }
        __syncthreads();
        const int n = n0 + tx;
        const float sc = g1[n] * rsqrtf(v1[n] + EPS);
#pragma unroll
        for (int it = 0; it < 4; it++) {
            int k = k0 + ty + it * 8;
            if (k >= DD) continue;
            float val = tl[tx][ty + it * 8] * sc;
            __half h = __float2half_rn(val);
            __half l = __float2half_rn(val - __half2float(h));
            size_t o = ((size_t)(z * DD + k)) * H1 + n;
            g_W1h3[o] = h;
            g_W1l3[o] = l;
        }
        return;
    }
    bx -= PREP_W1;
    if (bx < PREP_SCAN) {
        const int b = bx >> 1;
        const float* dp = doc + (size_t)b * T_LEN * DD;
        const int d0 = tid, d1 = tid + 256;
        const bool has1 = (d1 < DD);
        if ((bx & 1) == 0) {
            float a0 = 0.f, a1 = 0.f;
            __half* fh = g_Fph + (size_t)(b * TPAD) * DD;
            __half* fl = g_Fpl + (size_t)(b * TPAD) * DD;
            for (int d = tid; d < DD; d += 256) {
                fh[d] = __float2half_rn(0.f);
                fl[d] = __float2half_rn(0.f);
            }
            for (int t0 = 0; t0 < T_LEN; t0 += 32) {
                int n = min(32, T_LEN - t0);
                __syncthreads();
                for (int i = tid; i < n * DD; i += 256) sh[i] = dp[(size_t)t0 * DD + i];
                __syncthreads();
                for (int i = 0; i < n; i++) {
                    size_t ro = (size_t)(t0 + i + 1) * DD;
                    a0 = fmaf(ALPHA, a0, sh[i * DD + d0]);
                    __half h0 = __float2half_rn(a0);
                    fh[ro + d0] = h0;
                    fl[ro + d0] = __float2half_rn(a0 - __half2float(h0));
                    if (has1) {
                        a1 = fmaf(ALPHA, a1, sh[i * DD + d1]);
                        __half h1v = __float2half_rn(a1);
                        fh[ro + d1] = h1v;
                        fl[ro + d1] = __float2half_rn(a1 - __half2float(h1v));
                    }
                }
            }
        } else {
            float a0 = 0.f, a1 = 0.f;
            __half* rh = g_Rph + (size_t)(b * TPAD) * DD;
            __half* rl = g_Rpl + (size_t)(b * TPAD) * DD;
            for (int d = tid; d < DD; d += 256) {
                rh[(size_t)T_LEN * DD + d] = __float2half_rn(0.f);
                rl[(size_t)T_LEN * DD + d] = __float2half_rn(0.f);
            }
            for (int hi = T_LEN; hi > 0; hi -= 32) {
                int lo = (hi > 32) ? hi - 32 : 0;
                int n = hi - lo;
                __syncthreads();
                for (int i = tid; i < n * DD; i += 256) sh[i] = dp[(size_t)lo * DD + i];
                __syncthreads();
                for (int i = n - 1; i >= 0; i--) {
                    size_t ro = (size_t)(lo + i) * DD;
                    a0 = fmaf(ALPHA, a0, sh[i * DD + d0]);
                    __half h0 = __float2half_rn(a0);
                    rh[ro + d0] = h0;
                    rl[ro + d0] = __float2half_rn(a0 - __half2float(h0));
                    if (has1) {
                        a1 = fmaf(ALPHA, a1, sh[i * DD + d1]);
                        __half h1v = __float2half_rn(a1);
                        rh[ro + d1] = h1v;
                        rl[ro + d1] = __float2half_rn(a1 - __half2float(h1v));
                    }
                }
            }
        }
        return;
    }
    bx -= PREP_SCAN;
    if (bx < PREP_PQ) {
        const int lane = tid & 31;
        const int gw = bx * 8 + (tid >> 5);
        const int j = gw & (H1 - 1);
        const int b = gw >> 10;
        const float sc = g1[j] * rsqrtf(v1[j] + EPS);
        const float* wrow = &W1[(size_t)j * CIN + 3 * DD];
        float dot = 0.f;
        for (int d = lane; d < EE; d += 32) {
            float qv = 0.f, p = 1.f;
#pragma unroll
            for (int t = LQ - 1; t >= 0; t--) {
                qv = fmaf(p, Qe[(b * LQ + t) * EE + d], qv);
                p *= ALPHA;
            }
            dot = fmaf(qv, wrow[d], dot);
        }
#pragma unroll
        for (int o = 16; o > 0; o >>= 1) dot += __shfl_xor_sync(0xffffffffu, dot, o);
        if (lane == 0) g_Pq[b * H1 + j] = b1[j] - m1[j] * sc + sc * dot;
        return;
    }
    bx -= PREP_PQ;
    {
        const long total = H2 + T_LEN + MSPAN;
        for (long idx = (long)bx * 256 + tid; idx < total; idx += (long)PREP_MISC * 256) {
            long i = idx;
            if (i < H2) {
                float sc = g2[i] * rsqrtf(v2[i] + EPS);
                g_sh2[i] = b2[i] - m2[i] * sc;
                continue;
            }
            i -= H2;
            if (i < T_LEN) {
                int s = (int)i;
                int cnt = min(MSPAN, T_LEN - s);
                int ex = (s > 794) ? ((s - 794) * (s - 793)) / 2 : 0;
                int base = 16 * s - ex;
                for (int sp = 0; sp < cnt; sp++) {
                    g_sidx[base + sp] = s;
                    g_eidx[base + sp] = s + sp;
                }
                continue;
            }
            i -= T_LEN;
            if (i < MSPAN) {
                double c = 1.0;
                for (int k = 0; k <= (int)i; k++) c *= 0.9;
                g_coef[i] = (float)c;
            }
        }
    }
}

// ------------ projections via fp16 mma, 3-pass hi/lo (near-exact) ------------
constexpr int PJ_SA = 48;
constexpr int PJ_SB = 272;
constexpr uint32_t PJ_AH = 0;
constexpr uint32_t PJ_AL = 6144;
constexpr uint32_t PJ_BH = 12288;
constexpr uint32_t PJ_BL = 16640;
constexpr uint32_t PJ_STAGE = 20992;
constexpr uint32_t PJ_SMEM = 2 * PJ_STAGE;

__global__ void __launch_bounds__(256) k_proj() {
    extern __shared__ char sm[];
    const uint32_t sb = smem_u32(sm);
    const int z = blockIdx.z;
    const int m0 = blockIdx.x * 128;
    const int n0 = blockIdx.y * 128;
    const int tid = threadIdx.x;
    const int lane = tid & 31;
    const int w = tid >> 5;
    const int mw = w & 3;
    const int nw = w >> 2;

    const __half* Ah = (z == 2) ? g_Rph : g_Fph;
    const __half* Al = (z == 2) ? g_Rpl : g_Fpl;
    float* P = (z == 0) ? g_PA : (z == 1 ? g_PB : g_PC);

    const int amm = tid >> 1, aseg = tid & 1;
    const int am = (m0 + amm < MROWS) ? (m0 + amm) : 0;
    const int bkr = tid >> 4, bns = tid & 15;

    auto stage = [&](int cc) {
        const uint32_t st = sb + (uint32_t)(cc & 1) * PJ_STAGE;
        const int k0 = cc * 16;
        const size_t asrc = ((size_t)am * DD + k0 + aseg * 8);
        cp16(st + PJ_AH + (uint32_t)(amm * PJ_SA + aseg * 16), Ah + asrc);
        cp16(st + PJ_AL + (uint32_t)(amm * PJ_SA + aseg * 16), Al + asrc);
        const size_t bsrc = ((size_t)(z * DD + k0 + bkr)) * H1 + n0 + bns * 8;
        cp16(st + PJ_BH + (uint32_t)(bkr * PJ_SB + bns * 16), g_W1h3 + bsrc);
        cp16(st + PJ_BL + (uint32_t)(bkr * PJ_SB + bns * 16), g_W1l3 + bsrc);
        cp_commit();
    };

    float acc[2][8][4];
#pragma unroll
    for (int i = 0; i < 2; i++)
#pragma unroll
        for (int j = 0; j < 8; j++)
#pragma unroll
            for (int c = 0; c < 4; c++) acc[i][j][c] = 0.f;

    const uint32_t aRel = (uint32_t)((mw * 32 + (lane & 15)) * PJ_SA + (lane >> 4) * 16);
    const uint32_t bRel = (uint32_t)((lane & 15) * PJ_SB + (nw * 64 + (lane >> 4) * 8) * 2);

    stage(0);
#pragma unroll 1
    for (int c = 0; c < 19; c++) {
        if (c < 18) { stage(c + 1); cp_wait<1>(); }
        else        { cp_wait<0>(); }
        __syncthreads();
        const uint32_t st = sb + (uint32_t)(c & 1) * PJ_STAGE;
        uint32_t ah[2][4], al[2][4];
        ldsm_x4(ah[0], st + PJ_AH + aRel);
        ldsm_x4(ah[1], st + PJ_AH + aRel + 16 * PJ_SA);
        ldsm_x4(al[0], st + PJ_AL + aRel);
        ldsm_x4(al[1], st + PJ_AL + aRel + 16 * PJ_SA);
#pragma unroll
        for (int g = 0; g < 4; g++) {
            uint32_t bh[4], bl[4];
            ldsm_x4_t(bh, st + PJ_BH + bRel + g * 32);
            ldsm_x4_t(bl, st + PJ_BL + bRel + g * 32);
#pragma unroll
            for (int m = 0; m < 2; m++) {
                mma16816(acc[m][2 * g],     ah[m], bh);
                mma16816(acc[m][2 * g + 1], ah[m], bh + 2);
                mma16816(acc[m][2 * g],     al[m], bh);
                mma16816(acc[m][2 * g + 1], al[m], bh + 2);
                mma16816(acc[m][2 * g],     ah[m], bl);
                mma16816(acc[m][2 * g + 1], ah[m], bl + 2);
            }
        }
        __syncthreads();
    }

#pragma unroll
    for (int m = 0; m < 2; m++) {
        int row0 = m0 + mw * 32 + m * 16 + (lane >> 2);
#pragma unroll
        for (int h = 0; h < 2; h++) {
            int row = row0 + h * 8;
            if (row >= MROWS) continue;
            float* pr = &P[(size_t)row * H1 + n0 + nw * 64 + (lane & 3) * 2];
            const float* qr = (z == 0)
                ? &g_Pq[(row / TPAD) * H1 + n0 + nw * 64 + (lane & 3) * 2] : nullptr;
#pragma unroll
            for (int nf = 0; nf < 8; nf++) {
                float2 v = make_float2(acc[m][nf][2 * h], acc[m][nf][2 * h + 1]);
                if (z == 0) {
                    v.x += qr[nf * 8];
                    v.y += qr[nf * 8 + 1];
                }
                *(float2*)&pr[nf * 8] = v;
            }
        }
    }
}

// ---- main: fp16 mma GEMM2, 512 threads (16 warps, 4Mx4N) for 4 warps/SMSP ----
constexpr int SA_STRIDE = 144;
constexpr int SB_STRIDE = 528;
constexpr uint32_t OFF_AH   = 0;
constexpr uint32_t OFF_BH   = 18432;
constexpr uint32_t STAGE_SZ = 52224;
constexpr uint32_t OFF_HDR  = 104448;
constexpr uint32_t OFF_OS   = OFF_HDR;
constexpr uint32_t OFF_OE   = OFF_HDR + 512;
constexpr uint32_t OFF_CF   = OFF_HDR + 1024;
constexpr uint32_t OFF_W3A  = OFF_HDR + 1536;
constexpr uint32_t OFF_W3B  = OFF_HDR + 2560;
constexpr uint32_t OFF_SH2  = OFF_HDR + 3584;
constexpr uint32_t OFF_RED  = OFF_HDR + 4608;   // float[4][128][2] = 4096
constexpr uint32_t SMEM_MAIN = OFF_HDR + 8704;  // 113152

__global__ void __launch_bounds__(512, 1) k_main(const float* __restrict__ W3) {
    extern __shared__ char sm[];
    const uint32_t sb = smem_u32(sm);
    const int tid = threadIdx.x;
    const int lane = tid & 31;
    const int w = tid >> 5;          // 0..15
    const int mw = w & 3;            // 4 M groups of 32 rows
    const int nw = w >> 2;           // 4 N groups of 64 cols
    const int batch = blockIdx.y;
    const int c0i = blockIdx.x * 128;
    const int n0 = blockIdx.z * 256;

    int*   sOS = (int*)(sm + OFF_OS);
    int*   sOE = (int*)(sm + OFF_OE);
    float* sCF = (float*)(sm + OFF_CF);
    float* sW3a = (float*)(sm + OFF_W3A);
    float* sW3b = (float*)(sm + OFF_W3B);
    float* sSh2 = (float*)(sm + OFF_SH2);
    float* sRed = (float*)(sm + OFF_RED);

    if (tid < 128) {
        int ci = c0i + tid;
        int offS = 0, offE = 0;
        float cf = 0.f;
        if (ci < NCAND) {
            int s = g_sidx[ci], e = g_eidx[ci];
            offS = (batch * TPAD + s) * H1;
            offE = (batch * TPAD + e + 1) * H1;
            cf = g_coef[e - s];
        }
        sOS[tid] = offS; sOE[tid] = offE; sCF[tid] = cf;
    }
    if (tid < 256) {
        sW3a[tid] = W3[n0 + tid];
        sW3b[tid] = W3[H2 + n0 + tid];
        sSh2[tid] = g_sh2[n0 + tid];
    }
    __syncthreads();

    // A-gen: warp w owns rows [8w, 8w+8); lane covers cols [2*lane, 2*lane+2)
    const int wrow = w * 8;
    const int myOS = sOS[wrow + (lane & 7)];
    const int myOE = sOE[wrow + (lane & 7)];
    const float myCF = sCF[wrow + (lane & 7)];
    const bool uni = (__shfl_sync(0xffffffffu, myOS, 0) ==
                      __shfl_sync(0xffffffffu, myOS, 7));

    // B cp.async config: 2048 x 16B lines over 512 threads -> 4 its
    const int bkr = tid >> 5;        // 0..15
    const int bnc = tid & 31;

    const uint32_t aRel = OFF_AH + (uint32_t)((mw * 32 + (lane & 15)) * SA_STRIDE +
                                              ((lane >> 4) * 8) * 2);
    const uint32_t bRel = OFF_BH + (uint32_t)((lane & 15) * SB_STRIDE +
                                              (nw * 64 + (lane >> 4) * 8) * 2);

    float acc[2][8][4];
#pragma unroll
    for (int t = 0; t < 2; t++)
#pragma unroll
        for (int nf = 0; nf < 8; nf++)
#pragma unroll
            for (int c = 0; c < 4; c++) acc[t][nf][c] = 0.f;

    auto stage = [&](int cc) {
        const uint32_t stoff = (uint32_t)(cc & 1) * STAGE_SZ;
        const uint32_t st = sb + stoff;
        const __half* bsrc = &g_W2h16[(size_t)(cc * 64) * H2 + n0];
#pragma unroll
        for (int it = 0; it < 4; it++) {
            int kr = bkr + it * 16;
            cp16(st + OFF_BH + (uint32_t)(kr * SB_STRIDE + bnc * 16),
                 bsrc + (size_t)kr * H2 + bnc * 8);
        }
        cp_commit();
        const int kc = cc * 64 + 2 * lane;
        if (uni) {
            const int offS = __shfl_sync(0xffffffffu, myOS, 0);
            const float2 a  = *(const float2*)&g_PA[offS + kc];
            const float2 bs = *(const float2*)&g_PB[offS + kc];
#pragma unroll
            for (int rr = 0; rr < 8; rr++) {
                int offE = __shfl_sync(0xffffffffu, myOE, rr);
                float cf = __shfl_sync(0xffffffffu, myCF, rr);
                float2 be = *(const float2*)&g_PB[offE + kc];
                float2 pc = *(const float2*)&g_PC[offE + kc];
                float v0 = fmaxf(a.x + be.x + pc.x - cf * bs.x, 0.f);
                float v1 = fmaxf(a.y + be.y + pc.y - cf * bs.y, 0.f);
                __half2 h = __floats2half2_rn(v0, v1);
                uint32_t ad = stoff + (uint32_t)((wrow + rr) * SA_STRIDE + lane * 4);
                *(uint32_t*)(sm + OFF_AH + ad) = h2u(h);
            }
        } else {
#pragma unroll
            for (int rr = 0; rr < 8; rr++) {
                int offS = __shfl_sync(0xffffffffu, myOS, rr);
                int offE = __shfl_sync(0xffffffffu, myOE, rr);
                float cf = __shfl_sync(0xffffffffu, myCF, rr);
                float2 a  = *(const float2*)&g_PA[offS + kc];
                float2 bs = *(const float2*)&g_PB[offS + kc];
                float2 be = *(const float2*)&g_PB[offE + kc];
                float2 pc = *(const float2*)&g_PC[offE + kc];
                float v0 = fmaxf(a.x + be.x + pc.x - cf * bs.x, 0.f);
                float v1 = fmaxf(a.y + be.y + pc.y - cf * bs.y, 0.f);
                __half2 h = __floats2half2_rn(v0, v1);
                uint32_t ad = stoff + (uint32_t)((wrow + rr) * SA_STRIDE + lane * 4);
                *(uint32_t*)(sm + OFF_AH + ad) = h2u(h);
            }
        }
    };

    stage(0);

#pragma unroll 1
    for (int c = 0; c < 16; c++) {
        if (c < 15) { stage(c + 1); cp_wait<1>(); }
        else        { cp_wait<0>(); }
        __syncthreads();
        const uint32_t st = sb + (uint32_t)(c & 1) * STAGE_SZ;
#pragma unroll
        for (int s = 0; s < 4; s++) {
            const uint32_t ka = st + aRel + (uint32_t)(s * 32);
            uint32_t ah[2][4];
            ldsm_x4(ah[0], ka);
            ldsm_x4(ah[1], ka + 16 * SA_STRIDE);
            const uint32_t kbq = st + bRel + (uint32_t)(s * 16 * SB_STRIDE);
#pragma unroll
            for (int p = 0; p < 4; p++) {
                uint32_t bq[4];
                ldsm_x4_t(bq, kbq + p * 32);
                mma16816(acc[0][2 * p],     ah[0], bq);
                mma16816(acc[1][2 * p],     ah[1], bq);
                mma16816(acc[0][2 * p + 1], ah[0], bq + 2);
                mma16816(acc[1][2 * p + 1], ah[1], bq + 2);
            }
        }
        __syncthreads();
    }

    // ---- epilogue: relu(D + sh2) dot W3, reduce across lanes + 4 N-groups ----
    float sums[4][2];
#pragma unroll
    for (int q = 0; q < 4; q++) { sums[q][0] = 0.f; sums[q][1] = 0.f; }
#pragma unroll
    for (int t = 0; t < 2; t++) {
#pragma unroll
        for (int nf = 0; nf < 8; nf++) {
            int n = nw * 64 + nf * 8 + (lane & 3) * 2;
            float sh0 = sSh2[n], sh1 = sSh2[n + 1];
            float wa0 = sW3a[n], wa1 = sW3a[n + 1];
            float wb0 = sW3b[n], wb1 = sW3b[n + 1];
            float v0 = fmaxf(acc[t][nf][0] + sh0, 0.f);
            float v1 = fmaxf(acc[t][nf][1] + sh1, 0.f);
            float v2 = fmaxf(acc[t][nf][2] + sh0, 0.f);
            float v3 = fmaxf(acc[t][nf][3] + sh1, 0.f);
            sums[t * 2][0]     = fmaf(v0, wa0, fmaf(v1, wa1, sums[t * 2][0]));
            sums[t * 2][1]     = fmaf(v0, wb0, fmaf(v1, wb1, sums[t * 2][1]));
            sums[t * 2 + 1][0] = fmaf(v2, wa0, fmaf(v3, wa1, sums[t * 2 + 1][0]));
            sums[t * 2 + 1][1] = fmaf(v2, wb0, fmaf(v3, wb1, sums[t * 2 + 1][1]));
        }
    }
#pragma unroll
    for (int q = 0; q < 4; q++) {
#pragma unroll
        for (int o = 0; o < 2; o++) {
            sums[q][o] += __shfl_xor_sync(0xffffffffu, sums[q][o], 1);
            sums[q][o] += __shfl_xor_sync(0xffffffffu, sums[q][o], 2);
        }
    }
    __syncthreads();
    if ((lane & 3) == 0) {
#pragma unroll
        for (int q = 0; q < 4; q++) {
            int rloc = mw * 32 + (q >> 1) * 16 + (q & 1) * 8 + (lane >> 2);
            sRed[nw * 256 + rloc * 2 + 0] = sums[q][0];
            sRed[nw * 256 + rloc * 2 + 1] = sums[q][1];
        }
    }
    __syncthreads();
    if (tid < 256) {
        int rloc = tid >> 1, o = tid & 1;
        int ci = c0i + rloc;
        if (ci < NCAND) {
            float v = sRed[rloc * 2 + o] + sRed[256 + rloc * 2 + o] +
                      sRed[512 + rloc * 2 + o] + sRed[768 + rloc * 2 + o];
            g_outp[(size_t)blockIdx.z * (ROWS * 2) + (size_t)(batch * NCAND + ci) * 2 + o] = v;
        }
    }
}

__global__ void k_sum(float* __restrict__ out) {
    int i = blockIdx.x * 256 + threadIdx.x;
    if (i < ROWS * 2) out[i] = g_outp[i] + g_outp[ROWS * 2 + i];
}

// ---------------- launch ----------------
extern "C" void kernel_launch(void* const* d_in, const int* in_sizes, int n_in,
                              void* d_out, int out_size) {
    (void)in_sizes; (void)n_in; (void)out_size;
    const float* doc = (const float*)d_in[0];
    const float* qe  = (const float*)d_in[1];
    const float* W1  = (const float*)d_in[2];
    const float* g1  = (const float*)d_in[3];
    const float* b1  = (const float*)d_in[4];
    const float* m1  = (const float*)d_in[5];
    const float* v1  = (const float*)d_in[6];
    const float* W2  = (const float*)d_in[7];
    const float* g2  = (const float*)d_in[8];
    const float* b2  = (const float*)d_in[9];
    const float* m2  = (const float*)d_in[10];
    const float* v2  = (const float*)d_in[11];
    const float* W3  = (const float*)d_in[12];
    float* out = (float*)d_out;

    cudaFuncSetAttribute(k_main, cudaFuncAttributeMaxDynamicSharedMemorySize, SMEM_MAIN);
    cudaFuncSetAttribute(k_proj, cudaFuncAttributeMaxDynamicSharedMemorySize, PJ_SMEM);

    k_prep<<<PREP_GRID, 256>>>(doc, qe, W1, g1, b1, m1, v1, W2, g2, b2, m2, v2);
    k_proj<<<dim3((MROWS + 127) / 128, H1 / 128, 3), 256, PJ_SMEM>>>();
    k_main<<<dim3((NCAND + 127) / 128, BB, 2), 512, SMEM_MAIN>>>(W3);
    k_sum<<<(ROWS * 2 + 255) / 256, 256>>>(out);
}

// round 9
// speedup vs baseline: 4.6869x; 1.1816x over previous
#include <cuda_runtime.h>
#include <cuda_fp16.h>
#include <cstdint>

#define ALPHA 0.9f
constexpr int T_LEN = 809;
constexpr int TPAD  = 810;
constexpr int DD    = 304;
constexpr int EE    = 300;
constexpr int LQ    = 30;
constexpr int BB    = 4;
constexpr int MSPAN = 16;
constexpr int H1    = 1024;
constexpr int H2    = 512;
constexpr int CIN   = 1212;
constexpr int NCAND = 12824;
constexpr int ROWS  = BB * NCAND;      // 51296
constexpr int MROWS = BB * TPAD;       // 3240
constexpr float EPS = 1e-5f;

// ---------------- scratch ----------------
__device__ __align__(16) __half g_Fph[MROWS * DD];
__device__ __align__(16) __half g_Fpl[MROWS * DD];
__device__ __align__(16) __half g_Rph[MROWS * DD];
__device__ __align__(16) __half g_Rpl[MROWS * DD];
__device__ __align__(16) __half g_W1h3[3 * DD * H1];
__device__ float g_PA[MROWS * H1];     // includes Pq fold
__device__ float g_PB[MROWS * H1];
__device__ float g_PC[MROWS * H1];
__device__ float g_Pq[BB * H1];
__device__ __align__(16) __half g_W2h16[H1 * H2];  // fp16(W2*sc2), [k][n]
__device__ float g_sh2[H2];
__device__ float g_coef[MSPAN];
__device__ int   g_sidx[NCAND];
__device__ int   g_eidx[NCAND];
__device__ float g_outp[2 * ROWS * 2];

// ---------------- helpers ----------------
__device__ __forceinline__ uint32_t smem_u32(const void* p) {
    uint32_t a;
    asm("{ .reg .u64 t; cvta.to.shared.u64 t, %1; cvt.u32.u64 %0, t; }" : "=r"(a) : "l"(p));
    return a;
}
__device__ __forceinline__ uint32_t h2u(__half2 h) { return *(uint32_t*)&h; }

__device__ __forceinline__ void ldsm_x4(uint32_t* r, uint32_t a) {
    asm volatile("ldmatrix.sync.aligned.m8n8.x4.shared.b16 {%0,%1,%2,%3}, [%4];"
                 : "=r"(r[0]), "=r"(r[1]), "=r"(r[2]), "=r"(r[3]) : "r"(a));
}
__device__ __forceinline__ void ldsm_x4_t(uint32_t* r, uint32_t a) {
    asm volatile("ldmatrix.sync.aligned.m8n8.x4.trans.shared.b16 {%0,%1,%2,%3}, [%4];"
                 : "=r"(r[0]), "=r"(r[1]), "=r"(r[2]), "=r"(r[3]) : "r"(a));
}
__device__ __forceinline__ void mma16816(float* d, const uint32_t* a, const uint32_t* b) {
    asm volatile(
        "mma.sync.aligned.m16n8k16.row.col.f32.f16.f16.f32 "
        "{%0,%1,%2,%3}, {%4,%5,%6,%7}, {%8,%9}, {%0,%1,%2,%3};"
        : "+f"(d[0]), "+f"(d[1]), "+f"(d[2]), "+f"(d[3])
        : "r"(a[0]), "r"(a[1]), "r"(a[2]), "r"(a[3]), "r"(b[0]), "r"(b[1]));
}
__device__ __forceinline__ void cp16(uint32_t dst, const void* src) {
    asm volatile("cp.async.cg.shared.global [%0], [%1], 16;" :: "r"(dst), "l"(src));
}
__device__ __forceinline__ void cp_commit() { asm volatile("cp.async.commit_group;"); }
template <int N> __device__ __forceinline__ void cp_wait() {
    asm volatile("cp.async.wait_group %0;" :: "n"(N));
}

// =================== fat prep kernel ==============
constexpr int PREP_W2   = 512;
constexpr int PREP_W1   = 960;
constexpr int PREP_SCAN = 8;
constexpr int PREP_PQ   = 512;
constexpr int PREP_MISC = 64;
constexpr int PREP_GRID = PREP_W2 + PREP_W1 + PREP_SCAN + PREP_PQ + PREP_MISC;

__global__ void __launch_bounds__(256) k_prep(
    const float* __restrict__ doc, const float* __restrict__ Qe,
    const float* __restrict__ W1,
    const float* __restrict__ g1, const float* __restrict__ b1,
    const float* __restrict__ m1, const float* __restrict__ v1,
    const float* __restrict__ W2,
    const float* __restrict__ g2, const float* __restrict__ b2,
    const float* __restrict__ m2, const float* __restrict__ v2) {
    __shared__ float sh[32 * DD];
    int bx = blockIdx.x;
    const int tid = threadIdx.x;

    if (bx < PREP_W2) {
        float (*tl)[33] = (float(*)[33])sh;
        const int kt = bx & 31, nt = bx >> 5;
        const int k0 = kt * 32, n0 = nt * 32;
        const int tx = tid & 31, ty = tid >> 5;
#pragma unroll
        for (int it = 0; it < 4; it++)
            tl[ty + it * 8][tx] = W2[(size_t)(n0 + ty + it * 8) * H1 + k0 + tx];
        __syncthreads();
        const int n = n0 + tx;
        const float sc = g2[n] * rsqrtf(v2[n] + EPS);
#pragma unroll
        for (int it = 0; it < 4; it++) {
            int k = k0 + ty + it * 8;
            g_W2h16[(size_t)k * H2 + n] = __float2half_rn(tl[tx][ty + it * 8] * sc);
        }
        return;
    }
    bx -= PREP_W2;
    if (bx < PREP_W1) {
        float (*tl)[33] = (float(*)[33])sh;
        const int z = bx / 320;
        const int r = bx - z * 320;
        const int kt = r % 10, nt = r / 10;
        const int k0 = kt * 32, n0 = nt * 32;
        const int tx = tid & 31, ty = tid >> 5;
#pragma unroll
        for (int it = 0; it < 4; it++) {
            int n = n0 + ty + it * 8;
            int k = k0 + tx;
            tl[ty + it * 8][tx] = (k < DD) ? W1[(size_t)n * CIN + z * DD + k] : 0.f;
        }
        __syncthreads();
        const int n = n0 + tx;
        const float sc = g1[n] * rsqrtf(v1[n] + EPS);
#pragma unroll
        for (int it = 0; it < 4; it++) {
            int k = k0 + ty + it * 8;
            if (k >= DD) continue;
            g_W1h3[((size_t)(z * DD + k)) * H1 + n] =
                __float2half_rn(tl[tx][ty + it * 8] * sc);
        }
        return;
    }
    bx -= PREP_W1;
    if (bx < PREP_SCAN) {
        const int b = bx >> 1;
        const float* dp = doc + (size_t)b * T_LEN * DD;
        const int d0 = tid, d1 = tid + 256;
        const bool has1 = (d1 < DD);
        if ((bx & 1) == 0) {
            float a0 = 0.f, a1 = 0.f;
            __half* fh = g_Fph + (size_t)(b * TPAD) * DD;
            __half* fl = g_Fpl + (size_t)(b * TPAD) * DD;
            for (int d = tid; d < DD; d += 256) {
                fh[d] = __float2half_rn(0.f);
                fl[d] = __float2half_rn(0.f);
            }
            for (int t0 = 0; t0 < T_LEN; t0 += 32) {
                int n = min(32, T_LEN - t0);
                __syncthreads();
                for (int i = tid; i < n * DD; i += 256) sh[i] = dp[(size_t)t0 * DD + i];
                __syncthreads();
                for (int i = 0; i < n; i++) {
                    size_t ro = (size_t)(t0 + i + 1) * DD;
                    a0 = fmaf(ALPHA, a0, sh[i * DD + d0]);
                    __half h0 = __float2half_rn(a0);
                    fh[ro + d0] = h0;
                    fl[ro + d0] = __float2half_rn(a0 - __half2float(h0));
                    if (has1) {
                        a1 = fmaf(ALPHA, a1, sh[i * DD + d1]);
                        __half h1v = __float2half_rn(a1);
                        fh[ro + d1] = h1v;
                        fl[ro + d1] = __float2half_rn(a1 - __half2float(h1v));
                    }
                }
            }
        } else {
            float a0 = 0.f, a1 = 0.f;
            __half* rh = g_Rph + (size_t)(b * TPAD) * DD;
            __half* rl = g_Rpl + (size_t)(b * TPAD) * DD;
            for (int d = tid; d < DD; d += 256) {
                rh[(size_t)T_LEN * DD + d] = __float2half_rn(0.f);
                rl[(size_t)T_LEN * DD + d] = __float2half_rn(0.f);
            }
            for (int hi = T_LEN; hi > 0; hi -= 32) {
                int lo = (hi > 32) ? hi - 32 : 0;
                int n = hi - lo;
                __syncthreads();
                for (int i = tid; i < n * DD; i += 256) sh[i] = dp[(size_t)lo * DD + i];
                __syncthreads();
                for (int i = n - 1; i >= 0; i--) {
                    size_t ro = (size_t)(lo + i) * DD;
                    a0 = fmaf(ALPHA, a0, sh[i * DD + d0]);
                    __half h0 = __float2half_rn(a0);
                    rh[ro + d0] = h0;
                    rl[ro + d0] = __float2half_rn(a0 - __half2float(h0));
                    if (has1) {
                        a1 = fmaf(ALPHA, a1, sh[i * DD + d1]);
                        __half h1v = __float2half_rn(a1);
                        rh[ro + d1] = h1v;
                        rl[ro + d1] = __float2half_rn(a1 - __half2float(h1v));
                    }
                }
            }
        }
        return;
    }
    bx -= PREP_SCAN;
    if (bx < PREP_PQ) {
        const int lane = tid & 31;
        const int gw = bx * 8 + (tid >> 5);
        const int j = gw & (H1 - 1);
        const int b = gw >> 10;
        const float sc = g1[j] * rsqrtf(v1[j] + EPS);
        const float* wrow = &W1[(size_t)j * CIN + 3 * DD];
        float dot = 0.f;
        for (int d = lane; d < EE; d += 32) {
            float qv = 0.f, p = 1.f;
#pragma unroll
            for (int t = LQ - 1; t >= 0; t--) {
                qv = fmaf(p, Qe[(b * LQ + t) * EE + d], qv);
                p *= ALPHA;
            }
            dot = fmaf(qv, wrow[d], dot);
        }
#pragma unroll
        for (int o = 16; o > 0; o >>= 1) dot += __shfl_xor_sync(0xffffffffu, dot, o);
        if (lane == 0) g_Pq[b * H1 + j] = b1[j] - m1[j] * sc + sc * dot;
        return;
    }
    bx -= PREP_PQ;
    {
        const long total = H2 + T_LEN + MSPAN;
        for (long idx = (long)bx * 256 + tid; idx < total; idx += (long)PREP_MISC * 256) {
            long i = idx;
            if (i < H2) {
                float sc = g2[i] * rsqrtf(v2[i] + EPS);
                g_sh2[i] = b2[i] - m2[i] * sc;
                continue;
            }
            i -= H2;
            if (i < T_LEN) {
                int s = (int)i;
                int cnt = min(MSPAN, T_LEN - s);
                int ex = (s > 794) ? ((s - 794) * (s - 793)) / 2 : 0;
                int base = 16 * s - ex;
                for (int sp = 0; sp < cnt; sp++) {
                    g_sidx[base + sp] = s;
                    g_eidx[base + sp] = s + sp;
                }
                continue;
            }
            i -= T_LEN;
            if (i < MSPAN) {
                double c = 1.0;
                for (int k = 0; k <= (int)i; k++) c *= 0.9;
                g_coef[i] = (float)c;
            }
        }
    }
}

// ---------- projections via fp16 mma, 2-pass (AhBh + AlBh; W1 fp16) ----------
constexpr int PJ_SA = 48;
constexpr int PJ_SB = 272;
constexpr uint32_t PJ_AH = 0;
constexpr uint32_t PJ_AL = 6144;
constexpr uint32_t PJ_BH = 12288;
constexpr uint32_t PJ_STAGE = 16640;
constexpr uint32_t PJ_SMEM = 2 * PJ_STAGE;   // 33280

__global__ void __launch_bounds__(256) k_proj() {
    extern __shared__ char sm[];
    const uint32_t sb = smem_u32(sm);
    const int z = blockIdx.z;
    const int m0 = blockIdx.x * 128;
    const int n0 = blockIdx.y * 128;
    const int tid = threadIdx.x;
    const int lane = tid & 31;
    const int w = tid >> 5;
    const int mw = w & 3;
    const int nw = w >> 2;

    const __half* Ah = (z == 2) ? g_Rph : g_Fph;
    const __half* Al = (z == 2) ? g_Rpl : g_Fpl;
    float* P = (z == 0) ? g_PA : (z == 1 ? g_PB : g_PC);

    const int amm = tid >> 1, aseg = tid & 1;
    const int am = (m0 + amm < MROWS) ? (m0 + amm) : 0;
    const int bkr = tid >> 4, bns = tid & 15;

    auto stage = [&](int cc) {
        const uint32_t st = sb + (uint32_t)(cc & 1) * PJ_STAGE;
        const int k0 = cc * 16;
        const size_t asrc = ((size_t)am * DD + k0 + aseg * 8);
        cp16(st + PJ_AH + (uint32_t)(amm * PJ_SA + aseg * 16), Ah + asrc);
        cp16(st + PJ_AL + (uint32_t)(amm * PJ_SA + aseg * 16), Al + asrc);
        const size_t bsrc = ((size_t)(z * DD + k0 + bkr)) * H1 + n0 + bns * 8;
        cp16(st + PJ_BH + (uint32_t)(bkr * PJ_SB + bns * 16), g_W1h3 + bsrc);
        cp_commit();
    };

    float acc[2][8][4];
#pragma unroll
    for (int i = 0; i < 2; i++)
#pragma unroll
        for (int j = 0; j < 8; j++)
#pragma unroll
            for (int c = 0; c < 4; c++) acc[i][j][c] = 0.f;

    const uint32_t aRel = (uint32_t)((mw * 32 + (lane & 15)) * PJ_SA + (lane >> 4) * 16);
    const uint32_t bRel = (uint32_t)((lane & 15) * PJ_SB + (nw * 64 + (lane >> 4) * 8) * 2);

    stage(0);
#pragma unroll 1
    for (int c = 0; c < 19; c++) {
        if (c < 18) { stage(c + 1); cp_wait<1>(); }
        else        { cp_wait<0>(); }
        __syncthreads();
        const uint32_t st = sb + (uint32_t)(c & 1) * PJ_STAGE;
        uint32_t ah[2][4], al[2][4];
        ldsm_x4(ah[0], st + PJ_AH + aRel);
        ldsm_x4(ah[1], st + PJ_AH + aRel + 16 * PJ_SA);
        ldsm_x4(al[0], st + PJ_AL + aRel);
        ldsm_x4(al[1], st + PJ_AL + aRel + 16 * PJ_SA);
#pragma unroll
        for (int g = 0; g < 4; g++) {
            uint32_t bh[4];
            ldsm_x4_t(bh, st + PJ_BH + bRel + g * 32);
#pragma unroll
            for (int m = 0; m < 2; m++) {
                mma16816(acc[m][2 * g],     ah[m], bh);
                mma16816(acc[m][2 * g + 1], ah[m], bh + 2);
                mma16816(acc[m][2 * g],     al[m], bh);
                mma16816(acc[m][2 * g + 1], al[m], bh + 2);
            }
        }
        __syncthreads();
    }

#pragma unroll
    for (int m = 0; m < 2; m++) {
        int row0 = m0 + mw * 32 + m * 16 + (lane >> 2);
#pragma unroll
        for (int h = 0; h < 2; h++) {
            int row = row0 + h * 8;
            if (row >= MROWS) continue;
            float* pr = &P[(size_t)row * H1 + n0 + nw * 64 + (lane & 3) * 2];
            const float* qr = (z == 0)
                ? &g_Pq[(row / TPAD) * H1 + n0 + nw * 64 + (lane & 3) * 2] : nullptr;
#pragma unroll
            for (int nf = 0; nf < 8; nf++) {
                float2 v = make_float2(acc[m][nf][2 * h], acc[m][nf][2 * h + 1]);
                if (z == 0) {
                    v.x += qr[nf * 8];
                    v.y += qr[nf * 8 + 1];
                }
                *(float2*)&pr[nf * 8] = v;
            }
        }
    }
}

// ---- main: fp16 mma GEMM2, M=64 tile, 256 threads, 2 CTAs/SM for overlap ----
constexpr int SA_STRIDE = 144;
constexpr int SB_STRIDE = 528;
constexpr uint32_t OFF_AH   = 0;                // 64*144 = 9216
constexpr uint32_t OFF_BH   = 9216;             // 64*528 = 33792
constexpr uint32_t STAGE_SZ = 43008;
constexpr uint32_t OFF_HDR  = 86016;
constexpr uint32_t OFF_OS   = OFF_HDR;          // int[64]
constexpr uint32_t OFF_OE   = OFF_HDR + 256;
constexpr uint32_t OFF_CF   = OFF_HDR + 512;
constexpr uint32_t OFF_W3A  = OFF_HDR + 768;    // float[256]
constexpr uint32_t OFF_W3B  = OFF_HDR + 1792;
constexpr uint32_t OFF_SH2  = OFF_HDR + 2816;
constexpr uint32_t OFF_RED  = OFF_HDR + 3840;   // float[4][64][2] = 2048
constexpr uint32_t SMEM_MAIN = OFF_HDR + 5888;  // 91904 (x2 CTAs = 183808)

__global__ void __launch_bounds__(256, 2) k_main(const float* __restrict__ W3) {
    extern __shared__ char sm[];
    const uint32_t sb = smem_u32(sm);
    const int tid = threadIdx.x;
    const int lane = tid & 31;
    const int w = tid >> 5;          // 0..7
    const int mw = w & 1;            // 2 M groups of 32 rows
    const int nw = w >> 1;           // 4 N groups of 64 cols
    const int batch = blockIdx.y;
    const int c0i = blockIdx.x * 64;
    const int n0 = blockIdx.z * 256;

    int*   sOS = (int*)(sm + OFF_OS);
    int*   sOE = (int*)(sm + OFF_OE);
    float* sCF = (float*)(sm + OFF_CF);
    float* sW3a = (float*)(sm + OFF_W3A);
    float* sW3b = (float*)(sm + OFF_W3B);
    float* sSh2 = (float*)(sm + OFF_SH2);
    float* sRed = (float*)(sm + OFF_RED);

    if (tid < 64) {
        int ci = c0i + tid;
        int offS = 0, offE = 0;
        float cf = 0.f;
        if (ci < NCAND) {
            int s = g_sidx[ci], e = g_eidx[ci];
            offS = (batch * TPAD + s) * H1;
            offE = (batch * TPAD + e + 1) * H1;
            cf = g_coef[e - s];
        }
        sOS[tid] = offS; sOE[tid] = offE; sCF[tid] = cf;
    }
    sW3a[tid] = W3[n0 + tid];
    sW3b[tid] = W3[H2 + n0 + tid];
    sSh2[tid] = g_sh2[n0 + tid];
    __syncthreads();

    // A-gen: warp w owns rows [8w, 8w+8)
    const int wrow = w * 8;
    const int myOS = sOS[wrow + (lane & 7)];
    const int myOE = sOE[wrow + (lane & 7)];
    const float myCF = sCF[wrow + (lane & 7)];
    const bool uni = (__shfl_sync(0xffffffffu, myOS, 0) ==
                      __shfl_sync(0xffffffffu, myOS, 7));

    // B cp.async: 64 k-rows x 512B = 2048 lines / 256 threads = 8 per thread
    const int bkr = tid >> 5;
    const int bnc = tid & 31;

    const uint32_t aRel = OFF_AH + (uint32_t)((mw * 32 + (lane & 15)) * SA_STRIDE +
                                              ((lane >> 4) * 8) * 2);
    const uint32_t bRel = OFF_BH + (uint32_t)((lane & 15) * SB_STRIDE +
                                              (nw * 64 + (lane >> 4) * 8) * 2);

    float acc[2][8][4];
#pragma unroll
    for (int t = 0; t < 2; t++)
#pragma unroll
        for (int nf = 0; nf < 8; nf++)
#pragma unroll
            for (int c = 0; c < 4; c++) acc[t][nf][c] = 0.f;

    auto stage = [&](int cc) {
        const uint32_t stoff = (uint32_t)(cc & 1) * STAGE_SZ;
        const uint32_t st = sb + stoff;
        const __half* bsrc = &g_W2h16[(size_t)(cc * 64) * H2 + n0];
#pragma unroll
        for (int it = 0; it < 8; it++) {
            int kr = bkr + it * 8;
            cp16(st + OFF_BH + (uint32_t)(kr * SB_STRIDE + bnc * 16),
                 bsrc + (size_t)kr * H2 + bnc * 8);
        }
        cp_commit();
        const int kc = cc * 64 + 2 * lane;
        if (uni) {
            const int offS = __shfl_sync(0xffffffffu, myOS, 0);
            const float2 a  = *(const float2*)&g_PA[offS + kc];
            const float2 bs = *(const float2*)&g_PB[offS + kc];
#pragma unroll
            for (int rr = 0; rr < 8; rr++) {
                int offE = __shfl_sync(0xffffffffu, myOE, rr);
                float cf = __shfl_sync(0xffffffffu, myCF, rr);
                float2 be = *(const float2*)&g_PB[offE + kc];
                float2 pc = *(const float2*)&g_PC[offE + kc];
                float v0 = fmaxf(a.x + be.x + pc.x - cf * bs.x, 0.f);
                float v1 = fmaxf(a.y + be.y + pc.y - cf * bs.y, 0.f);
                __half2 h = __floats2half2_rn(v0, v1);
                uint32_t ad = stoff + (uint32_t)((wrow + rr) * SA_STRIDE + lane * 4);
                *(uint32_t*)(sm + OFF_AH + ad) = h2u(h);
            }
        } else {
#pragma unroll
            for (int rr = 0; rr < 8; rr++) {
                int offS = __shfl_sync(0xffffffffu, myOS, rr);
                int offE = __shfl_sync(0xffffffffu, myOE, rr);
                float cf = __shfl_sync(0xffffffffu, myCF, rr);
                float2 a  = *(const float2*)&g_PA[offS + kc];
                float2 bs = *(const float2*)&g_PB[offS + kc];
                float2 be = *(const float2*)&g_PB[offE + kc];
                float2 pc = *(const float2*)&g_PC[offE + kc];
                float v0 = fmaxf(a.x + be.x + pc.x - cf * bs.x, 0.f);
                float v1 = fmaxf(a.y + be.y + pc.y - cf * bs.y, 0.f);
                __half2 h = __floats2half2_rn(v0, v1);
                uint32_t ad = stoff + (uint32_t)((wrow + rr) * SA_STRIDE + lane * 4);
                *(uint32_t*)(sm + OFF_AH + ad) = h2u(h);
            }
        }
    };

    stage(0);

#pragma unroll 1
    for (int c = 0; c < 16; c++) {
        if (c < 15) { stage(c + 1); cp_wait<1>(); }
        else        { cp_wait<0>(); }
        __syncthreads();
        const uint32_t st = sb + (uint32_t)(c & 1) * STAGE_SZ;
#pragma unroll
        for (int s = 0; s < 4; s++) {
            const uint32_t ka = st + aRel + (uint32_t)(s * 32);
            uint32_t ah[2][4];
            ldsm_x4(ah[0], ka);
            ldsm_x4(ah[1], ka + 16 * SA_STRIDE);
            const uint32_t kbq = st + bRel + (uint32_t)(s * 16 * SB_STRIDE);
#pragma unroll
            for (int p = 0; p < 4; p++) {
                uint32_t bq[4];
                ldsm_x4_t(bq, kbq + p * 32);
                mma16816(acc[0][2 * p],     ah[0], bq);
                mma16816(acc[1][2 * p],     ah[1], bq);
                mma16816(acc[0][2 * p + 1], ah[0], bq + 2);
                mma16816(acc[1][2 * p + 1], ah[1], bq + 2);
            }
        }
        __syncthreads();
    }

    // ---- epilogue: relu(D + sh2) dot W3, reduce lanes + 4 N-groups ----
    float sums[4][2];
#pragma unroll
    for (int q = 0; q < 4; q++) { sums[q][0] = 0.f; sums[q][1] = 0.f; }
#pragma unroll
    for (int t = 0; t < 2; t++) {
#pragma unroll
        for (int nf = 0; nf < 8; nf++) {
            int n = nw * 64 + nf * 8 + (lane & 3) * 2;
            float sh0 = sSh2[n], sh1 = sSh2[n + 1];
            float wa0 = sW3a[n], wa1 = sW3a[n + 1];
            float wb0 = sW3b[n], wb1 = sW3b[n + 1];
            float v0 = fmaxf(acc[t][nf][0] + sh0, 0.f);
            float v1 = fmaxf(acc[t][nf][1] + sh1, 0.f);
            float v2 = fmaxf(acc[t][nf][2] + sh0, 0.f);
            float v3 = fmaxf(acc[t][nf][3] + sh1, 0.f);
            sums[t * 2][0]     = fmaf(v0, wa0, fmaf(v1, wa1, sums[t * 2][0]));
            sums[t * 2][1]     = fmaf(v0, wb0, fmaf(v1, wb1, sums[t * 2][1]));
            sums[t * 2 + 1][0] = fmaf(v2, wa0, fmaf(v3, wa1, sums[t * 2 + 1][0]));
            sums[t * 2 + 1][1] = fmaf(v2, wb0, fmaf(v3, wb1, sums[t * 2 + 1][1]));
        }
    }
#pragma unroll
    for (int q = 0; q < 4; q++) {
#pragma unroll
        for (int o = 0; o < 2; o++) {
            sums[q][o] += __shfl_xor_sync(0xffffffffu, sums[q][o], 1);
            sums[q][o] += __shfl_xor_sync(0xffffffffu, sums[q][o], 2);
        }
    }
    __syncthreads();
    if ((lane & 3) == 0) {
#pragma unroll
        for (int q = 0; q < 4; q++) {
            int rloc = mw * 32 + (q >> 1) * 16 + (q & 1) * 8 + (lane >> 2);
            sRed[nw * 128 + rloc * 2 + 0] = sums[q][0];
            sRed[nw * 128 + rloc * 2 + 1] = sums[q][1];
        }
    }
    __syncthreads();
    if (tid < 128) {
        int rloc = tid >> 1, o = tid & 1;
        int ci = c0i + rloc;
        if (ci < NCAND) {
            float v = sRed[rloc * 2 + o] + sRed[128 + rloc * 2 + o] +
                      sRed[256 + rloc * 2 + o] + sRed[384 + rloc * 2 + o];
            g_outp[(size_t)blockIdx.z * (ROWS * 2) + (size_t)(batch * NCAND + ci) * 2 + o] = v;
        }
    }
}

__global__ void k_sum(float* __restrict__ out) {
    int i = blockIdx.x * 256 + threadIdx.x;
    if (i < ROWS * 2) out[i] = g_outp[i] + g_outp[ROWS * 2 + i];
}

// ---------------- launch ----------------
extern "C" void kernel_launch(void* const* d_in, const int* in_sizes, int n_in,
                              void* d_out, int out_size) {
    (void)in_sizes; (void)n_in; (void)out_size;
    const float* doc = (const float*)d_in[0];
    const float* qe  = (const float*)d_in[1];
    const float* W1  = (const float*)d_in[2];
    const float* g1  = (const float*)d_in[3];
    const float* b1  = (const float*)d_in[4];
    const float* m1  = (const float*)d_in[5];
    const float* v1  = (const float*)d_in[6];
    const float* W2  = (const float*)d_in[7];
    const float* g2  = (const float*)d_in[8];
    const float* b2  = (const float*)d_in[9];
    const float* m2  = (const float*)d_in[10];
    const float* v2  = (const float*)d_in[11];
    const float* W3  = (const float*)d_in[12];
    float* out = (float*)d_out;

    cudaFuncSetAttribute(k_main, cudaFuncAttributeMaxDynamicSharedMemorySize, SMEM_MAIN);
    cudaFuncSetAttribute(k_proj, cudaFuncAttributeMaxDynamicSharedMemorySize, PJ_SMEM);

    k_prep<<<PREP_GRID, 256>>>(doc, qe, W1, g1, b1, m1, v1, W2, g2, b2, m2, v2);
    k_proj<<<dim3((MROWS + 127) / 128, H1 / 128, 3), 256, PJ_SMEM>>>();
    k_main<<<dim3((NCAND + 63) / 64, BB, 2), 256, SMEM_MAIN>>>(W3);
    k_sum<<<(ROWS * 2 + 255) / 256, 256>>>(out);
}

// round 10
// speedup vs baseline: 4.7633x; 1.0163x over previous
#include <cuda_runtime.h>
#include <cuda_fp16.h>
#include <cstdint>

#define ALPHA 0.9f
constexpr int T_LEN = 809;
constexpr int TPAD  = 810;
constexpr int DD    = 304;
constexpr int EE    = 300;
constexpr int LQ    = 30;
constexpr int BB    = 4;
constexpr int MSPAN = 16;
constexpr int H1    = 1024;
constexpr int H2    = 512;
constexpr int CIN   = 1212;
constexpr int NCAND = 12824;
constexpr int ROWS  = BB * NCAND;      // 51296
constexpr int MROWS = BB * TPAD;       // 3240
constexpr float EPS = 1e-5f;

// ---------------- scratch ----------------
__device__ __align__(16) __half g_Fph[MROWS * DD];
__device__ __align__(16) __half g_Fpl[MROWS * DD];
__device__ __align__(16) __half g_Rph[MROWS * DD];
__device__ __align__(16) __half g_Rpl[MROWS * DD];
__device__ __align__(16) __half g_W1h3[3 * DD * H1];
__device__ __align__(16) __half g_PX[MROWS * H1];   // fp16(PA + Pq)
__device__ __align__(16) __half g_PY[MROWS * H1];   // fp16(PB)
__device__ __align__(16) __half g_PE[MROWS * H1];   // fp16(PB + PC)
__device__ float g_Pq[BB * H1];
__device__ __align__(16) __half g_W2h16[H1 * H2];   // fp16(W2*sc2), [k][n]
__device__ float g_sh2[H2];
__device__ float g_coef[MSPAN];
__device__ int   g_sidx[NCAND];
__device__ int   g_eidx[NCAND];
__device__ float g_outp[2 * ROWS * 2];

// ---------------- helpers ----------------
__device__ __forceinline__ uint32_t smem_u32(const void* p) {
    uint32_t a;
    asm("{ .reg .u64 t; cvta.to.shared.u64 t, %1; cvt.u32.u64 %0, t; }" : "=r"(a) : "l"(p));
    return a;
}
__device__ __forceinline__ uint32_t h2u(__half2 h) { return *(uint32_t*)&h; }

__device__ __forceinline__ void ldsm_x4(uint32_t* r, uint32_t a) {
    asm volatile("ldmatrix.sync.aligned.m8n8.x4.shared.b16 {%0,%1,%2,%3}, [%4];"
                 : "=r"(r[0]), "=r"(r[1]), "=r"(r[2]), "=r"(r[3]) : "r"(a));
}
__device__ __forceinline__ void ldsm_x4_t(uint32_t* r, uint32_t a) {
    asm volatile("ldmatrix.sync.aligned.m8n8.x4.trans.shared.b16 {%0,%1,%2,%3}, [%4];"
                 : "=r"(r[0]), "=r"(r[1]), "=r"(r[2]), "=r"(r[3]) : "r"(a));
}
__device__ __forceinline__ void mma16816(float* d, const uint32_t* a, const uint32_t* b) {
    asm volatile(
        "mma.sync.aligned.m16n8k16.row.col.f32.f16.f16.f32 "
        "{%0,%1,%2,%3}, {%4,%5,%6,%7}, {%8,%9}, {%0,%1,%2,%3};"
        : "+f"(d[0]), "+f"(d[1]), "+f"(d[2]), "+f"(d[3])
        : "r"(a[0]), "r"(a[1]), "r"(a[2]), "r"(a[3]), "r"(b[0]), "r"(b[1]));
}
__device__ __forceinline__ void cp16(uint32_t dst, const void* src) {
    asm volatile("cp.async.cg.shared.global [%0], [%1], 16;" :: "r"(dst), "l"(src));
}
__device__ __forceinline__ void cp_commit() { asm volatile("cp.async.commit_group;"); }
template <int N> __device__ __forceinline__ void cp_wait() {
    asm volatile("cp.async.wait_group %0;" :: "n"(N));
}

// =================== fat prep kernel ==============
constexpr int PREP_W2   = 512;
constexpr int PREP_W1   = 960;
constexpr int PREP_SCAN = 8;
constexpr int PREP_PQ   = 512;
constexpr int PREP_MISC = 64;
constexpr int PREP_GRID = PREP_W2 + PREP_W1 + PREP_SCAN + PREP_PQ + PREP_MISC;

__global__ void __launch_bounds__(256) k_prep(
    const float* __restrict__ doc, const float* __restrict__ Qe,
    const float* __restrict__ W1,
    const float* __restrict__ g1, const float* __restrict__ b1,
    const float* __restrict__ m1, const float* __restrict__ v1,
    const float* __restrict__ W2,
    const float* __restrict__ g2, const float* __restrict__ b2,
    const float* __restrict__ m2, const float* __restrict__ v2) {
    __shared__ float sh[32 * DD];
    int bx = blockIdx.x;
    const int tid = threadIdx.x;

    if (bx < PREP_W2) {
        float (*tl)[33] = (float(*)[33])sh;
        const int kt = bx & 31, nt = bx >> 5;
        const int k0 = kt * 32, n0 = nt * 32;
        const int tx = tid & 31, ty = tid >> 5;
#pragma unroll
        for (int it = 0; it < 4; it++)
            tl[ty + it * 8][tx] = W2[(size_t)(n0 + ty + it * 8) * H1 + k0 + tx];
        __syncthreads();
        const int n = n0 + tx;
        const float sc = g2[n] * rsqrtf(v2[n] + EPS);
#pragma unroll
        for (int it = 0; it < 4; it++) {
            int k = k0 + ty + it * 8;
            g_W2h16[(size_t)k * H2 + n] = __float2half_rn(tl[tx][ty + it * 8] * sc);
        }
        return;
    }
    bx -= PREP_W2;
    if (bx < PREP_W1) {
        float (*tl)[33] = (float(*)[33])sh;
        const int z = bx / 320;
        const int r = bx - z * 320;
        const int kt = r % 10, nt = r / 10;
        const int k0 = kt * 32, n0 = nt * 32;
        const int tx = tid & 31, ty = tid >> 5;
#pragma unroll
        for (int it = 0; it < 4; it++) {
            int n = n0 + ty + it * 8;
            int k = k0 + tx;
            tl[ty + it * 8][tx] = (k < DD) ? W1[(size_t)n * CIN + z * DD + k] : 0.f;
        }
        __syncthreads();
        const int n = n0 + tx;
        const float sc = g1[n] * rsqrtf(v1[n] + EPS);
#pragma unroll
        for (int it = 0; it < 4; it++) {
            int k = k0 + ty + it * 8;
            if (k >= DD) continue;
            g_W1h3[((size_t)(z * DD + k)) * H1 + n] =
                __float2half_rn(tl[tx][ty + it * 8] * sc);
        }
        return;
    }
    bx -= PREP_W1;
    if (bx < PREP_SCAN) {
        const int b = bx >> 1;
        const float* dp = doc + (size_t)b * T_LEN * DD;
        const int d0 = tid, d1 = tid + 256;
        const bool has1 = (d1 < DD);
        if ((bx & 1) == 0) {
            float a0 = 0.f, a1 = 0.f;
            __half* fh = g_Fph + (size_t)(b * TPAD) * DD;
            __half* fl = g_Fpl + (size_t)(b * TPAD) * DD;
            for (int d = tid; d < DD; d += 256) {
                fh[d] = __float2half_rn(0.f);
                fl[d] = __float2half_rn(0.f);
            }
            for (int t0 = 0; t0 < T_LEN; t0 += 32) {
                int n = min(32, T_LEN - t0);
                __syncthreads();
                for (int i = tid; i < n * DD; i += 256) sh[i] = dp[(size_t)t0 * DD + i];
                __syncthreads();
                for (int i = 0; i < n; i++) {
                    size_t ro = (size_t)(t0 + i + 1) * DD;
                    a0 = fmaf(ALPHA, a0, sh[i * DD + d0]);
                    __half h0 = __float2half_rn(a0);
                    fh[ro + d0] = h0;
                    fl[ro + d0] = __float2half_rn(a0 - __half2float(h0));
                    if (has1) {
                        a1 = fmaf(ALPHA, a1, sh[i * DD + d1]);
                        __half h1v = __float2half_rn(a1);
                        fh[ro + d1] = h1v;
                        fl[ro + d1] = __float2half_rn(a1 - __half2float(h1v));
                    }
                }
            }
        } else {
            float a0 = 0.f, a1 = 0.f;
            __half* rh = g_Rph + (size_t)(b * TPAD) * DD;
            __half* rl = g_Rpl + (size_t)(b * TPAD) * DD;
            for (int d = tid; d < DD; d += 256) {
                rh[(size_t)T_LEN * DD + d] = __float2half_rn(0.f);
                rl[(size_t)T_LEN * DD + d] = __float2half_rn(0.f);
            }
            for (int hi = T_LEN; hi > 0; hi -= 32) {
                int lo = (hi > 32) ? hi - 32 : 0;
                int n = hi - lo;
                __syncthreads();
                for (int i = tid; i < n * DD; i += 256) sh[i] = dp[(size_t)lo * DD + i];
                __syncthreads();
                for (int i = n - 1; i >= 0; i--) {
                    size_t ro = (size_t)(lo + i) * DD;
                    a0 = fmaf(ALPHA, a0, sh[i * DD + d0]);
                    __half h0 = __float2half_rn(a0);
                    rh[ro + d0] = h0;
                    rl[ro + d0] = __float2half_rn(a0 - __half2float(h0));
                    if (has1) {
                        a1 = fmaf(ALPHA, a1, sh[i * DD + d1]);
                        __half h1v = __float2half_rn(a1);
                        rh[ro + d1] = h1v;
                        rl[ro + d1] = __float2half_rn(a1 - __half2float(h1v));
                    }
                }
            }
        }
        return;
    }
    bx -= PREP_SCAN;
    if (bx < PREP_PQ) {
        const int lane = tid & 31;
        const int gw = bx * 8 + (tid >> 5);
        const int j = gw & (H1 - 1);
        const int b = gw >> 10;
        const float sc = g1[j] * rsqrtf(v1[j] + EPS);
        const float* wrow = &W1[(size_t)j * CIN + 3 * DD];
        float dot = 0.f;
        for (int d = lane; d < EE; d += 32) {
            float qv = 0.f, p = 1.f;
#pragma unroll
            for (int t = LQ - 1; t >= 0; t--) {
                qv = fmaf(p, Qe[(b * LQ + t) * EE + d], qv);
                p *= ALPHA;
            }
            dot = fmaf(qv, wrow[d], dot);
        }
#pragma unroll
        for (int o = 16; o > 0; o >>= 1) dot += __shfl_xor_sync(0xffffffffu, dot, o);
        if (lane == 0) g_Pq[b * H1 + j] = b1[j] - m1[j] * sc + sc * dot;
        return;
    }
    bx -= PREP_PQ;
    {
        const long total = H2 + T_LEN + MSPAN;
        for (long idx = (long)bx * 256 + tid; idx < total; idx += (long)PREP_MISC * 256) {
            long i = idx;
            if (i < H2) {
                float sc = g2[i] * rsqrtf(v2[i] + EPS);
                g_sh2[i] = b2[i] - m2[i] * sc;
                continue;
            }
            i -= H2;
            if (i < T_LEN) {
                int s = (int)i;
                int cnt = min(MSPAN, T_LEN - s);
                int ex = (s > 794) ? ((s - 794) * (s - 793)) / 2 : 0;
                int base = 16 * s - ex;
                for (int sp = 0; sp < cnt; sp++) {
                    g_sidx[base + sp] = s;
                    g_eidx[base + sp] = s + sp;
                }
                continue;
            }
            i -= T_LEN;
            if (i < MSPAN) {
                double c = 1.0;
                for (int k = 0; k <= (int)i; k++) c *= 0.9;
                g_coef[i] = (float)c;
            }
        }
    }
}

// ---------- projections via fp16 mma, 2-pass (AhBh + AlBh); fp16 P outputs -----
// z = zbase + blockIdx.z: 0 -> PX (adds Pq), 1 -> PY, 2 -> PE (adds PY)
constexpr int PJ_SA = 48;
constexpr int PJ_SB = 272;
constexpr uint32_t PJ_AH = 0;
constexpr uint32_t PJ_AL = 6144;
constexpr uint32_t PJ_BH = 12288;
constexpr uint32_t PJ_STAGE = 16640;
constexpr uint32_t PJ_SMEM = 2 * PJ_STAGE;   // 33280

__global__ void __launch_bounds__(256) k_proj(int zbase) {
    extern __shared__ char sm[];
    const uint32_t sb = smem_u32(sm);
    const int z = zbase + blockIdx.z;
    const int m0 = blockIdx.x * 128;
    const int n0 = blockIdx.y * 128;
    const int tid = threadIdx.x;
    const int lane = tid & 31;
    const int w = tid >> 5;
    const int mw = w & 3;
    const int nw = w >> 2;

    const __half* Ah = (z == 2) ? g_Rph : g_Fph;
    const __half* Al = (z == 2) ? g_Rpl : g_Fpl;
    __half* P = (z == 0) ? g_PX : (z == 1 ? g_PY : g_PE);

    const int amm = tid >> 1, aseg = tid & 1;
    const int am = (m0 + amm < MROWS) ? (m0 + amm) : 0;
    const int bkr = tid >> 4, bns = tid & 15;

    auto stage = [&](int cc) {
        const uint32_t st = sb + (uint32_t)(cc & 1) * PJ_STAGE;
        const int k0 = cc * 16;
        const size_t asrc = ((size_t)am * DD + k0 + aseg * 8);
        cp16(st + PJ_AH + (uint32_t)(amm * PJ_SA + aseg * 16), Ah + asrc);
        cp16(st + PJ_AL + (uint32_t)(amm * PJ_SA + aseg * 16), Al + asrc);
        const size_t bsrc = ((size_t)(z * DD + k0 + bkr)) * H1 + n0 + bns * 8;
        cp16(st + PJ_BH + (uint32_t)(bkr * PJ_SB + bns * 16), g_W1h3 + bsrc);
        cp_commit();
    };

    float acc[2][8][4];
#pragma unroll
    for (int i = 0; i < 2; i++)
#pragma unroll
        for (int j = 0; j < 8; j++)
#pragma unroll
            for (int c = 0; c < 4; c++) acc[i][j][c] = 0.f;

    const uint32_t aRel = (uint32_t)((mw * 32 + (lane & 15)) * PJ_SA + (lane >> 4) * 16);
    const uint32_t bRel = (uint32_t)((lane & 15) * PJ_SB + (nw * 64 + (lane >> 4) * 8) * 2);

    stage(0);
#pragma unroll 1
    for (int c = 0; c < 19; c++) {
        if (c < 18) { stage(c + 1); cp_wait<1>(); }
        else        { cp_wait<0>(); }
        __syncthreads();
        const uint32_t st = sb + (uint32_t)(c & 1) * PJ_STAGE;
        uint32_t ah[2][4], al[2][4];
        ldsm_x4(ah[0], st + PJ_AH + aRel);
        ldsm_x4(ah[1], st + PJ_AH + aRel + 16 * PJ_SA);
        ldsm_x4(al[0], st + PJ_AL + aRel);
        ldsm_x4(al[1], st + PJ_AL + aRel + 16 * PJ_SA);
#pragma unroll
        for (int g = 0; g < 4; g++) {
            uint32_t bh[4];
            ldsm_x4_t(bh, st + PJ_BH + bRel + g * 32);
#pragma unroll
            for (int m = 0; m < 2; m++) {
                mma16816(acc[m][2 * g],     ah[m], bh);
                mma16816(acc[m][2 * g + 1], ah[m], bh + 2);
                mma16816(acc[m][2 * g],     al[m], bh);
                mma16816(acc[m][2 * g + 1], al[m], bh + 2);
            }
        }
        __syncthreads();
    }

#pragma unroll
    for (int m = 0; m < 2; m++) {
        int row0 = m0 + mw * 32 + m * 16 + (lane >> 2);
#pragma unroll
        for (int h = 0; h < 2; h++) {
            int row = row0 + h * 8;
            if (row >= MROWS) continue;
            const int col = n0 + nw * 64 + (lane & 3) * 2;
            __half2* pr = (__half2*)&P[(size_t)row * H1 + col];
            const float* qr = (z == 0) ? &g_Pq[(row / TPAD) * H1 + col] : nullptr;
            const __half2* yr = (z == 2) ? (const __half2*)&g_PY[(size_t)row * H1 + col]
                                         : nullptr;
#pragma unroll
            for (int nf = 0; nf < 8; nf++) {
                float vx = acc[m][nf][2 * h];
                float vy = acc[m][nf][2 * h + 1];
                if (z == 0) {
                    vx += qr[nf * 8];
                    vy += qr[nf * 8 + 1];
                } else if (z == 2) {
                    float2 yv = __half22float2(yr[nf * 4]);
                    vx += yv.x;
                    vy += yv.y;
                }
                pr[nf * 4] = __floats2half2_rn(vx, vy);
            }
        }
    }
}

// ---- main: fp16 mma GEMM2, M=64 tile, 2 CTAs/SM, 3-stream fp16 A-gen ----
constexpr int SA_STRIDE = 144;
constexpr int SB_STRIDE = 528;
constexpr uint32_t OFF_AH   = 0;                // 64*144 = 9216
constexpr uint32_t OFF_BH   = 9216;             // 64*528 = 33792
constexpr uint32_t STAGE_SZ = 43008;
constexpr uint32_t OFF_HDR  = 86016;
constexpr uint32_t OFF_OS   = OFF_HDR;
constexpr uint32_t OFF_OE   = OFF_HDR + 256;
constexpr uint32_t OFF_CF   = OFF_HDR + 512;
constexpr uint32_t OFF_W3A  = OFF_HDR + 768;
constexpr uint32_t OFF_W3B  = OFF_HDR + 1792;
constexpr uint32_t OFF_SH2  = OFF_HDR + 2816;
constexpr uint32_t OFF_RED  = OFF_HDR + 3840;
constexpr uint32_t SMEM_MAIN = OFF_HDR + 5888;  // 91904 (x2 CTAs/SM)

__global__ void __launch_bounds__(256, 2) k_main(const float* __restrict__ W3) {
    extern __shared__ char sm[];
    const uint32_t sb = smem_u32(sm);
    const int tid = threadIdx.x;
    const int lane = tid & 31;
    const int w = tid >> 5;
    const int mw = w & 1;
    const int nw = w >> 1;
    const int batch = blockIdx.y;
    const int c0i = blockIdx.x * 64;
    const int n0 = blockIdx.z * 256;

    int*   sOS = (int*)(sm + OFF_OS);
    int*   sOE = (int*)(sm + OFF_OE);
    float* sCF = (float*)(sm + OFF_CF);
    float* sW3a = (float*)(sm + OFF_W3A);
    float* sW3b = (float*)(sm + OFF_W3B);
    float* sSh2 = (float*)(sm + OFF_SH2);
    float* sRed = (float*)(sm + OFF_RED);

    if (tid < 64) {
        int ci = c0i + tid;
        int offS = 0, offE = 0;
        float cf = 0.f;
        if (ci < NCAND) {
            int s = g_sidx[ci], e = g_eidx[ci];
            offS = (batch * TPAD + s) * H1;
            offE = (batch * TPAD + e + 1) * H1;
            cf = g_coef[e - s];
        }
        sOS[tid] = offS; sOE[tid] = offE; sCF[tid] = cf;
    }
    sW3a[tid] = W3[n0 + tid];
    sW3b[tid] = W3[H2 + n0 + tid];
    sSh2[tid] = g_sh2[n0 + tid];
    __syncthreads();

    const int wrow = w * 8;
    const int myOS = sOS[wrow + (lane & 7)];
    const int myOE = sOE[wrow + (lane & 7)];
    const float myCF = sCF[wrow + (lane & 7)];
    const bool uni = (__shfl_sync(0xffffffffu, myOS, 0) ==
                      __shfl_sync(0xffffffffu, myOS, 7));

    const int bkr = tid >> 5;
    const int bnc = tid & 31;

    const uint32_t aRel = OFF_AH + (uint32_t)((mw * 32 + (lane & 15)) * SA_STRIDE +
                                              ((lane >> 4) * 8) * 2);
    const uint32_t bRel = OFF_BH + (uint32_t)((lane & 15) * SB_STRIDE +
                                              (nw * 64 + (lane >> 4) * 8) * 2);

    float acc[2][8][4];
#pragma unroll
    for (int t = 0; t < 2; t++)
#pragma unroll
        for (int nf = 0; nf < 8; nf++)
#pragma unroll
            for (int c = 0; c < 4; c++) acc[t][nf][c] = 0.f;

    auto stage = [&](int cc) {
        const uint32_t stoff = (uint32_t)(cc & 1) * STAGE_SZ;
        const uint32_t st = sb + stoff;
        const __half* bsrc = &g_W2h16[(size_t)(cc * 64) * H2 + n0];
#pragma unroll
        for (int it = 0; it < 8; it++) {
            int kr = bkr + it * 8;
            cp16(st + OFF_BH + (uint32_t)(kr * SB_STRIDE + bnc * 16),
                 bsrc + (size_t)kr * H2 + bnc * 8);
        }
        cp_commit();
        const int kc = cc * 64 + 2 * lane;
        if (uni) {
            const int offS = __shfl_sync(0xffffffffu, myOS, 0);
            const float2 x = __half22float2(*(const __half2*)&g_PX[offS + kc]);
            const float2 y = __half22float2(*(const __half2*)&g_PY[offS + kc]);
#pragma unroll
            for (int rr = 0; rr < 8; rr++) {
                int offE = __shfl_sync(0xffffffffu, myOE, rr);
                float cf = __shfl_sync(0xffffffffu, myCF, rr);
                float2 e = __half22float2(*(const __half2*)&g_PE[offE + kc]);
                float v0 = fmaxf(x.x + e.x - cf * y.x, 0.f);
                float v1 = fmaxf(x.y + e.y - cf * y.y, 0.f);
                __half2 h = __floats2half2_rn(v0, v1);
                uint32_t ad = stoff + (uint32_t)((wrow + rr) * SA_STRIDE + lane * 4);
                *(uint32_t*)(sm + OFF_AH + ad) = h2u(h);
            }
        } else {
#pragma unroll
            for (int rr = 0; rr < 8; rr++) {
                int offS = __shfl_sync(0xffffffffu, myOS, rr);
                int offE = __shfl_sync(0xffffffffu, myOE, rr);
                float cf = __shfl_sync(0xffffffffu, myCF, rr);
                float2 x = __half22float2(*(const __half2*)&g_PX[offS + kc]);
                float2 y = __half22float2(*(const __half2*)&g_PY[offS + kc]);
                float2 e = __half22float2(*(const __half2*)&g_PE[offE + kc]);
                float v0 = fmaxf(x.x + e.x - cf * y.x, 0.f);
                float v1 = fmaxf(x.y + e.y - cf * y.y, 0.f);
                __half2 h = __floats2half2_rn(v0, v1);
                uint32_t ad = stoff + (uint32_t)((wrow + rr) * SA_STRIDE + lane * 4);
                *(uint32_t*)(sm + OFF_AH + ad) = h2u(h);
            }
        }
    };

    stage(0);

#pragma unroll 1
    for (int c = 0; c < 16; c++) {
        if (c < 15) { stage(c + 1); cp_wait<1>(); }
        else        { cp_wait<0>(); }
        __syncthreads();
        const uint32_t st = sb + (uint32_t)(c & 1) * STAGE_SZ;
#pragma unroll
        for (int s = 0; s < 4; s++) {
            const uint32_t ka = st + aRel + (uint32_t)(s * 32);
            uint32_t ah[2][4];
            ldsm_x4(ah[0], ka);
            ldsm_x4(ah[1], ka + 16 * SA_STRIDE);
            const uint32_t kbq = st + bRel + (uint32_t)(s * 16 * SB_STRIDE);
#pragma unroll
            for (int p = 0; p < 4; p++) {
                uint32_t bq[4];
                ldsm_x4_t(bq, kbq + p * 32);
                mma16816(acc[0][2 * p],     ah[0], bq);
                mma16816(acc[1][2 * p],     ah[1], bq);
                mma16816(acc[0][2 * p + 1], ah[0], bq + 2);
                mma16816(acc[1][2 * p + 1], ah[1], bq + 2);
            }
        }
        __syncthreads();
    }

    // ---- epilogue: relu(D + sh2) dot W3, reduce lanes + 4 N-groups ----
    float sums[4][2];
#pragma unroll
    for (int q = 0; q < 4; q++) { sums[q][0] = 0.f; sums[q][1] = 0.f; }
#pragma unroll
    for (int t = 0; t < 2; t++) {
#pragma unroll
        for (int nf = 0; nf < 8; nf++) {
            int n = nw * 64 + nf * 8 + (lane & 3) * 2;
            float sh0 = sSh2[n], sh1 = sSh2[n + 1];
            float wa0 = sW3a[n], wa1 = sW3a[n + 1];
            float wb0 = sW3b[n], wb1 = sW3b[n + 1];
            float v0 = fmaxf(acc[t][nf][0] + sh0, 0.f);
            float v1 = fmaxf(acc[t][nf][1] + sh1, 0.f);
            float v2 = fmaxf(acc[t][nf][2] + sh0, 0.f);
            float v3 = fmaxf(acc[t][nf][3] + sh1, 0.f);
            sums[t * 2][0]     = fmaf(v0, wa0, fmaf(v1, wa1, sums[t * 2][0]));
            sums[t * 2][1]     = fmaf(v0, wb0, fmaf(v1, wb1, sums[t * 2][1]));
            sums[t * 2 + 1][0] = fmaf(v2, wa0, fmaf(v3, wa1, sums[t * 2 + 1][0]));
            sums[t * 2 + 1][1] = fmaf(v2, wb0, fmaf(v3, wb1, sums[t * 2 + 1][1]));
        }
    }
#pragma unroll
    for (int q = 0; q < 4; q++) {
#pragma unroll
        for (int o = 0; o < 2; o++) {
            sums[q][o] += __shfl_xor_sync(0xffffffffu, sums[q][o], 1);
            sums[q][o] += __shfl_xor_sync(0xffffffffu, sums[q][o], 2);
        }
    }
    __syncthreads();
    if ((lane & 3) == 0) {
#pragma unroll
        for (int q = 0; q < 4; q++) {
            int rloc = mw * 32 + (q >> 1) * 16 + (q & 1) * 8 + (lane >> 2);
            sRed[nw * 128 + rloc * 2 + 0] = sums[q][0];
            sRed[nw * 128 + rloc * 2 + 1] = sums[q][1];
        }
    }
    __syncthreads();
    if (tid < 128) {
        int rloc = tid >> 1, o = tid & 1;
        int ci = c0i + rloc;
        if (ci < NCAND) {
            float v = sRed[rloc * 2 + o] + sRed[128 + rloc * 2 + o] +
                      sRed[256 + rloc * 2 + o] + sRed[384 + rloc * 2 + o];
            g_outp[(size_t)blockIdx.z * (ROWS * 2) + (size_t)(batch * NCAND + ci) * 2 + o] = v;
        }
    }
}

__global__ void k_sum(float* __restrict__ out) {
    int i = blockIdx.x * 256 + threadIdx.x;
    if (i < ROWS * 2) out[i] = g_outp[i] + g_outp[ROWS * 2 + i];
}

// ---------------- launch ----------------
extern "C" void kernel_launch(void* const* d_in, const int* in_sizes, int n_in,
                              void* d_out, int out_size) {
    (void)in_sizes; (void)n_in; (void)out_size;
    const float* doc = (const float*)d_in[0];
    const float* qe  = (const float*)d_in[1];
    const float* W1  = (const float*)d_in[2];
    const float* g1  = (const float*)d_in[3];
    const float* b1  = (const float*)d_in[4];
    const float* m1  = (const float*)d_in[5];
    const float* v1  = (const float*)d_in[6];
    const float* W2  = (const float*)d_in[7];
    const float* g2  = (const float*)d_in[8];
    const float* b2  = (const float*)d_in[9];
    const float* m2  = (const float*)d_in[10];
    const float* v2  = (const float*)d_in[11];
    const float* W3  = (const float*)d_in[12];
    float* out = (float*)d_out;

    cudaFuncSetAttribute(k_main, cudaFuncAttributeMaxDynamicSharedMemorySize, SMEM_MAIN);
    cudaFuncSetAttribute(k_proj, cudaFuncAttributeMaxDynamicSharedMemorySize, PJ_SMEM);

    k_prep<<<PREP_GRID, 256>>>(doc, qe, W1, g1, b1, m1, v1, W2, g2, b2, m2, v2);
    // PX (z=0, +Pq) and PY (z=1) first; PE (z=2) depends on PY
    k_proj<<<dim3((MROWS + 127) / 128, H1 / 128, 2), 256, PJ_SMEM>>>(0);
    k_proj<<<dim3((MROWS + 127) / 128, H1 / 128, 1), 256, PJ_SMEM>>>(2);
    k_main<<<dim3((NCAND + 63) / 64, BB, 2), 256, SMEM_MAIN>>>(W3);
    k_sum<<<(ROWS * 2 + 255) / 256, 256>>>(out);
}